// round 8
// baseline (speedup 1.0000x reference)
#include <cuda_runtime.h>
#include <cuda_bf16.h>
#include <cstdint>

#define BB   2
#define TT   2048
#define DD   4096
#define HH   32
#define GG   8
#define DH   128
#define KVD  (GG*DH)     /* 1024 */
#define MTOT (BB*TT)     /* 4096 */

// int8 2-slice operands + per-row scales
__device__ int8_t g_X0[(size_t)MTOT * DD],  g_X1[(size_t)MTOT * DD];
__device__ int8_t g_Wq0[(size_t)DD * DD],   g_Wq1[(size_t)DD * DD];
__device__ int8_t g_Wk0[(size_t)KVD * DD],  g_Wk1[(size_t)KVD * DD];
__device__ int8_t g_Wv0[(size_t)KVD * DD],  g_Wv1[(size_t)KVD * DD];
__device__ int8_t g_Wo0[(size_t)DD * DD],   g_Wo1[(size_t)DD * DD];
__device__ int8_t g_Y0[(size_t)MTOT * DD],  g_Y1[(size_t)MTOT * DD];
__device__ float  g_sX[MTOT], g_sWq[DD], g_sWk[KVD], g_sWv[KVD], g_sWo[DD], g_sY[MTOT];

// bf16 hi/lo attention inputs; fp32 attention output
__device__ __nv_bfloat16 g_Q_hi[(size_t)MTOT * DD],  g_Q_lo[(size_t)MTOT * DD];
__device__ __nv_bfloat16 g_K_hi[(size_t)MTOT * KVD], g_K_lo[(size_t)MTOT * KVD];
__device__ __nv_bfloat16 g_V_hi[(size_t)MTOT * KVD], g_V_lo[(size_t)MTOT * KVD];
__device__ float g_Yf[(size_t)MTOT * DD];

// ---------------------------------------------------------------------------
__device__ __forceinline__ uint32_t smem_u32(const void* p) {
    uint32_t a;
    asm("{ .reg .u64 t; cvta.to.shared.u64 t, %1; cvt.u32.u64 %0, t; }"
        : "=r"(a) : "l"(p));
    return a;
}
__device__ __forceinline__ void ldsm4(uint32_t& r0, uint32_t& r1, uint32_t& r2,
                                      uint32_t& r3, uint32_t addr) {
    asm volatile("ldmatrix.sync.aligned.m8n8.x4.shared.b16 {%0,%1,%2,%3}, [%4];"
                 : "=r"(r0), "=r"(r1), "=r"(r2), "=r"(r3) : "r"(addr));
}
__device__ __forceinline__ void ldsm4t(uint32_t& r0, uint32_t& r1, uint32_t& r2,
                                       uint32_t& r3, uint32_t addr) {
    asm volatile("ldmatrix.sync.aligned.m8n8.x4.trans.shared.b16 {%0,%1,%2,%3}, [%4];"
                 : "=r"(r0), "=r"(r1), "=r"(r2), "=r"(r3) : "r"(addr));
}
__device__ __forceinline__ void mma16816(float* c, const uint32_t* a,
                                         uint32_t b0, uint32_t b1) {
    asm volatile(
        "mma.sync.aligned.m16n8k16.row.col.f32.bf16.bf16.f32 "
        "{%0,%1,%2,%3}, {%4,%5,%6,%7}, {%8,%9}, {%0,%1,%2,%3};"
        : "+f"(c[0]), "+f"(c[1]), "+f"(c[2]), "+f"(c[3])
        : "r"(a[0]), "r"(a[1]), "r"(a[2]), "r"(a[3]), "r"(b0), "r"(b1));
}
__device__ __forceinline__ void mma_s8(int* c, const uint32_t* a,
                                       uint32_t b0, uint32_t b1) {
    asm volatile(
        "mma.sync.aligned.m16n8k32.row.col.s32.s8.s8.s32 "
        "{%0,%1,%2,%3}, {%4,%5,%6,%7}, {%8,%9}, {%0,%1,%2,%3};"
        : "+r"(c[0]), "+r"(c[1]), "+r"(c[2]), "+r"(c[3])
        : "r"(a[0]), "r"(a[1]), "r"(a[2]), "r"(a[3]), "r"(b0), "r"(b1));
}
__device__ __forceinline__ void cpasync16(uint32_t dst, const void* src) {
    asm volatile("cp.async.cg.shared.global [%0], [%1], 16;"
                 :: "r"(dst), "l"(src) : "memory");
}
#define CP_COMMIT() asm volatile("cp.async.commit_group;" ::: "memory")
#define CP_WAIT1()  asm volatile("cp.async.wait_group 1;" ::: "memory")
#define CP_WAIT0()  asm volatile("cp.async.wait_group 0;" ::: "memory")

__device__ __forceinline__ float ex2f(float x) {
    float y;
    asm("ex2.approx.ftz.f32 %0, %1;" : "=f"(y) : "f"(x));
    return y;
}
__device__ __forceinline__ void split_pack(float a, float b,
                                           uint32_t& h, uint32_t& l) {
    __nv_bfloat162 hb = __floats2bfloat162_rn(a, b);
    __nv_bfloat162 lb = __floats2bfloat162_rn(a - __low2float(hb),
                                              b - __high2float(hb));
    h = *reinterpret_cast<uint32_t*>(&hb);
    l = *reinterpret_cast<uint32_t*>(&lb);
}

// ---------------------------------------------------------------------------
// fp32 -> int8 2-slice split with per-row scale.  x = s*(q0*128+q1)/16384.
// One block per row; cols multiple of 512.
// ---------------------------------------------------------------------------
__device__ __forceinline__ int q_clamp(float t) {
    int a = __float2int_rn(t);
    return max(-127, min(127, a));
}
__global__ __launch_bounds__(128) void split_i8(
    const float* __restrict__ x, int8_t* __restrict__ q0,
    int8_t* __restrict__ q1, float* __restrict__ scale, int cols)
{
    __shared__ float red[4];
    const int row = blockIdx.x, tid = threadIdx.x;
    const float* xr = x + (size_t)row * cols;
    float m = 0.f;
    for (int c = tid * 4; c < cols; c += 512) {
        float4 v = *(const float4*)&xr[c];
        m = fmaxf(m, fmaxf(fmaxf(fabsf(v.x), fabsf(v.y)),
                           fmaxf(fabsf(v.z), fabsf(v.w))));
    }
    #pragma unroll
    for (int o = 16; o; o >>= 1) m = fmaxf(m, __shfl_xor_sync(0xffffffffu, m, o));
    if ((tid & 31) == 0) red[tid >> 5] = m;
    __syncthreads();
    if (tid == 0) {
        float s = fmaxf(fmaxf(red[0], red[1]), fmaxf(red[2], red[3]));
        scale[row] = s;
        red[0] = (s > 0.f) ? 128.f / s : 0.f;
    }
    __syncthreads();
    const float r = red[0];
    for (int c = tid * 4; c < cols; c += 512) {
        float4 v = *(const float4*)&xr[c];
        uint32_t p0 = 0, p1 = 0;
        float e[4] = { v.x, v.y, v.z, v.w };
        #pragma unroll
        for (int i = 0; i < 4; i++) {
            float t = e[i] * r;
            int a = q_clamp(t);
            int b = q_clamp((t - (float)a) * 128.f);
            p0 |= ((uint32_t)(a & 255)) << (8 * i);
            p1 |= ((uint32_t)(b & 255)) << (8 * i);
        }
        size_t idx = ((size_t)row * cols + c) >> 2;
        ((uint32_t*)q0)[idx] = p0;
        ((uint32_t*)q1)[idx] = p1;
    }
}

// ---------------------------------------------------------------------------
// int8 GEMM: C = sA*sB*(q·p)/2^28 + bias.  CTA 128x128, 8 warps of 64x32,
// K-chunk 64 (2 x k32 MMAs), cp.async double buffer (80 KB).
// ---------------------------------------------------------------------------
#define RS8     80                      /* 64 B data + 16 pad */
#define SUB8    (128 * RS8)             /* 10240 B per slice-tile */
#define STAGE8  (4 * SUB8)              /* 40960 */
#define GEMM_SMEM (2 * STAGE8)          /* 81920 */

struct I8Ptrs { const int8_t *a0, *a1, *b0, *b1; };

__device__ __forceinline__ void load_stage_i8(
    uint32_t sb, int tid, const I8Ptrs& p, int K, int k0)
{
    #pragma unroll
    for (int t = 0; t < 8; t++) {
        const int id  = t * 256 + tid;        // 0..2047
        const int tl  = id >> 9;              // 0..3
        const int x   = id & 511;
        const int r   = x >> 2;
        const int c16 = (x & 3) << 4;
        const int8_t* src =
            (tl == 0 ? p.a0 : tl == 1 ? p.a1 : tl == 2 ? p.b0 : p.b1)
            + (size_t)r * K + k0 + c16;
        cpasync16(sb + tl * SUB8 + r * RS8 + c16, src);
    }
}

__global__ __launch_bounds__(256, 1) void gemm_i8(
    const int8_t* __restrict__ A0, const int8_t* __restrict__ A1,
    const float* __restrict__ sA,
    const int8_t* __restrict__ B0, const int8_t* __restrict__ B1,
    const float* __restrict__ sB,
    const float* __restrict__ bias,
    float* __restrict__ Cf,
    __nv_bfloat16* __restrict__ Ch, __nv_bfloat16* __restrict__ Cl,
    int M, int N, int K)
{
    extern __shared__ char sm_[];
    const uint32_t smem_base = smem_u32(sm_);
    const int tid  = threadIdx.x;
    const int wid  = tid >> 5;
    const int lane = tid & 31;
    const int wm   = wid >> 2;          // 0..1
    const int wn   = wid & 3;           // 0..3
    const int brow = blockIdx.y << 7;
    const int bcol = blockIdx.x << 7;

    I8Ptrs p;
    p.a0 = A0 + (size_t)brow * K;  p.a1 = A1 + (size_t)brow * K;
    p.b0 = B0 + (size_t)bcol * K;  p.b1 = B1 + (size_t)bcol * K;

    int accM[4][4][4], accX[4][4][4];
    #pragma unroll
    for (int i = 0; i < 4; i++)
        #pragma unroll
        for (int j = 0; j < 4; j++)
            #pragma unroll
            for (int k = 0; k < 4; k++) { accM[i][j][k] = 0; accX[i][j][k] = 0; }

    const int nchunks = K / 64;

    load_stage_i8(smem_base, tid, p, K, 0);             CP_COMMIT();
    load_stage_i8(smem_base + STAGE8, tid, p, K, 64);   CP_COMMIT();
    CP_WAIT1();
    __syncthreads();

    const int a_row = lane & 15;
    const int a_kb  = (lane >> 4) << 4;
    const int b_row = (lane & 7) + ((lane >> 4) << 3);
    const int b_kb  = ((lane >> 3) & 1) << 4;

    for (int chunk = 0; chunk < nchunks; chunk++) {
        const uint32_t sb = smem_base + (chunk & 1) * STAGE8;

        #pragma unroll
        for (int ks = 0; ks < 2; ks++) {
            uint32_t a0[4][4], a1[4][4], bb0[8], bb1[8];
            #pragma unroll
            for (int mt = 0; mt < 4; mt++) {
                uint32_t ra = sb + (wm * 64 + mt * 16 + a_row) * RS8
                            + ks * 32 + a_kb;
                ldsm4(a0[mt][0], a0[mt][1], a0[mt][2], a0[mt][3], ra);
                ldsm4(a1[mt][0], a1[mt][1], a1[mt][2], a1[mt][3], ra + SUB8);
            }
            #pragma unroll
            for (int pr = 0; pr < 2; pr++) {
                uint32_t rb = sb + 2 * SUB8
                            + (wn * 32 + pr * 16 + b_row) * RS8
                            + ks * 32 + b_kb;
                ldsm4(bb0[pr * 4], bb0[pr * 4 + 1], bb0[pr * 4 + 2], bb0[pr * 4 + 3], rb);
                ldsm4(bb1[pr * 4], bb1[pr * 4 + 1], bb1[pr * 4 + 2], bb1[pr * 4 + 3], rb + SUB8);
            }
            // main term q0*p0 (16 independent accumulators)
            #pragma unroll
            for (int mt = 0; mt < 4; mt++)
                #pragma unroll
                for (int nt = 0; nt < 4; nt++)
                    mma_s8(accM[mt][nt], a0[mt], bb0[nt * 2], bb0[nt * 2 + 1]);
            // cross q0*p1
            #pragma unroll
            for (int mt = 0; mt < 4; mt++)
                #pragma unroll
                for (int nt = 0; nt < 4; nt++)
                    mma_s8(accX[mt][nt], a0[mt], bb1[nt * 2], bb1[nt * 2 + 1]);
            // cross q1*p0
            #pragma unroll
            for (int mt = 0; mt < 4; mt++)
                #pragma unroll
                for (int nt = 0; nt < 4; nt++)
                    mma_s8(accX[mt][nt], a1[mt], bb0[nt * 2], bb0[nt * 2 + 1]);
        }
        __syncthreads();

        if (chunk + 2 < nchunks) {
            load_stage_i8(smem_base + (chunk & 1) * STAGE8, tid, p, K,
                          (chunk + 2) * 64);
            CP_COMMIT();
            CP_WAIT1();
            __syncthreads();
        } else if (chunk + 1 < nchunks) {
            CP_WAIT0();
            __syncthreads();
        }
    }

    // epilogue: C = sA*sB*(M*2^14 + X*2^7)*2^-28 + bias
    const float INV28 = 3.7252902984619141e-09f;   // 2^-28
    const int crow = lane >> 2;
    const int ccol = (lane & 3) << 1;
    #pragma unroll
    for (int mt = 0; mt < 4; mt++) {
        const size_t row0 = (size_t)(brow + wm * 64 + mt * 16 + crow);
        const float sa0 = __ldg(&sA[row0]) * INV28;
        const float sa1 = __ldg(&sA[row0 + 8]) * INV28;
        #pragma unroll
        for (int nt = 0; nt < 4; nt++) {
            const int col = bcol + wn * 32 + nt * 8 + ccol;
            const float sb0 = __ldg(&sB[col]), sb1 = __ldg(&sB[col + 1]);
            const float bi0 = __ldg(&bias[col]), bi1 = __ldg(&bias[col + 1]);
            float v0 = ((float)accM[mt][nt][0] * 16384.f +
                        (float)accX[mt][nt][0] * 128.f) * (sa0 * sb0) + bi0;
            float v1 = ((float)accM[mt][nt][1] * 16384.f +
                        (float)accX[mt][nt][1] * 128.f) * (sa0 * sb1) + bi1;
            float v2 = ((float)accM[mt][nt][2] * 16384.f +
                        (float)accX[mt][nt][2] * 128.f) * (sa1 * sb0) + bi0;
            float v3 = ((float)accM[mt][nt][3] * 16384.f +
                        (float)accX[mt][nt][3] * 128.f) * (sa1 * sb1) + bi1;
            if (Cf) {
                float2 w0 = { v0, v1 }, w1 = { v2, v3 };
                *(float2*)&Cf[row0 * N + col]       = w0;
                *(float2*)&Cf[(row0 + 8) * N + col] = w1;
            } else {
                uint32_t h0, l0, h1, l1;
                split_pack(v0, v1, h0, l0);
                split_pack(v2, v3, h1, l1);
                *(uint32_t*)&Ch[row0 * N + col]       = h0;
                *(uint32_t*)&Cl[row0 * N + col]       = l0;
                *(uint32_t*)&Ch[(row0 + 8) * N + col] = h1;
                *(uint32_t*)&Cl[(row0 + 8) * N + col] = l1;
            }
        }
    }
}

// ---------------------------------------------------------------------------
// HMMA causal GQA flash attention (bf16 3-term; fp32 Y output)
// ---------------------------------------------------------------------------
#define ATSTR 272
#define AT64  (64 * ATSTR)
#define AQ_B  (128 * ATSTR)
#define AKV_B (4 * AT64)
#define ATTN_SMEM (2 * AQ_B + 2 * AKV_B)

__device__ __forceinline__ void attn_load_kv(
    uint32_t base, int tid,
    const __nv_bfloat16* __restrict__ Kh, const __nv_bfloat16* __restrict__ Kl,
    const __nv_bfloat16* __restrict__ Vh, const __nv_bfloat16* __restrict__ Vl,
    size_t grow0, int gcol)
{
    const __nv_bfloat16* srcs[4] = { Kh, Kl, Vh, Vl };
    #pragma unroll
    for (int t = 0; t < 4; t++) {
        const __nv_bfloat16* s = srcs[t] + grow0 * KVD + gcol;
        #pragma unroll
        for (int i = 0; i < 4; i++) {
            int ch = tid + i * 256;
            int r = ch >> 4, c = ch & 15;
            cpasync16(base + t * AT64 + r * ATSTR + c * 16,
                      s + (size_t)r * KVD + c * 8);
        }
    }
    CP_COMMIT();
}

__global__ __launch_bounds__(256, 1) void attn_mma(
    const __nv_bfloat16* __restrict__ Qh_, const __nv_bfloat16* __restrict__ Ql_,
    const __nv_bfloat16* __restrict__ Kh_, const __nv_bfloat16* __restrict__ Kl_,
    const __nv_bfloat16* __restrict__ Vh_, const __nv_bfloat16* __restrict__ Vl_,
    float* __restrict__ Yf_)
{
    extern __shared__ char sm_[];
    const uint32_t sb = smem_u32(sm_);
    const int tid  = threadIdx.x;
    const int lane = tid & 31;
    const int w    = tid >> 5;
    const int qt   = (int)gridDim.x - 1 - (int)blockIdx.x;
    const int bh   = blockIdx.y;
    const int b    = bh >> 5, h = bh & 31, g = h >> 2;
    const int ktmax = 2 * qt + 1;
    const size_t qrow0 = (size_t)b * TT + (size_t)qt * 128;
    const size_t krow0 = (size_t)b * TT;
    const int gcol = g * DH;

    {
        const __nv_bfloat16* q0 = Qh_ + qrow0 * DD + h * DH;
        const __nv_bfloat16* q1 = Ql_ + qrow0 * DD + h * DH;
        #pragma unroll
        for (int i = 0; i < 8; i++) {
            int ch = tid + i * 256;
            int r = ch >> 4, c = ch & 15;
            cpasync16(sb + r * ATSTR + c * 16,        q0 + (size_t)r * DD + c * 8);
            cpasync16(sb + AQ_B + r * ATSTR + c * 16, q1 + (size_t)r * DD + c * 8);
        }
        CP_COMMIT();
    }
    attn_load_kv(sb + 2 * AQ_B, tid, Kh_, Kl_, Vh_, Vl_, krow0, gcol);
    attn_load_kv(sb + 2 * AQ_B + AKV_B, tid, Kh_, Kl_, Vh_, Vl_, krow0 + 64, gcol);

    float o[16][4];
    #pragma unroll
    for (int i = 0; i < 16; i++)
        #pragma unroll
        for (int j = 0; j < 4; j++) o[i][j] = 0.f;
    float m_lo = -1e30f, m_hi = -1e30f, l_lo = 0.f, l_hi = 0.f;

    const int wrow = qt * 128 + w * 16;
    const int rl   = lane >> 2;
    const float SC = 0.088388347648318447f * 1.4426950408889634f;

    for (int kt = 0; kt <= ktmax; kt++) {
        if (kt < ktmax) { CP_WAIT1(); } else { CP_WAIT0(); }
        __syncthreads();
        const uint32_t kb = sb + 2 * AQ_B + (kt & 1) * AKV_B;

        if (kt * 64 <= wrow + 15) {
            float s[8][4];
            #pragma unroll
            for (int j = 0; j < 8; j++)
                #pragma unroll
                for (int e = 0; e < 4; e++) s[j][e] = 0.f;

            #pragma unroll
            for (int ks = 0; ks < 8; ks++) {
                uint32_t qh[4], ql[4];
                uint32_t ra = sb + (w * 16 + (lane & 15)) * ATSTR
                            + ks * 32 + ((lane >> 4) << 4);
                ldsm4(qh[0], qh[1], qh[2], qh[3], ra);
                ldsm4(ql[0], ql[1], ql[2], ql[3], ra + AQ_B);
                uint32_t kh[4][4], kl[4][4];
                #pragma unroll
                for (int np = 0; np < 4; np++) {
                    uint32_t rb = kb
                        + (np * 16 + (lane & 7) + ((lane >> 4) << 3)) * ATSTR
                        + ks * 32 + (((lane >> 3) & 1) << 4);
                    ldsm4(kh[np][0], kh[np][1], kh[np][2], kh[np][3], rb);
                    ldsm4(kl[np][0], kl[np][1], kl[np][2], kl[np][3], rb + AT64);
                }
                #pragma unroll
                for (int np = 0; np < 4; np++) {
                    mma16816(s[2 * np],     qh, kh[np][0], kh[np][1]);
                    mma16816(s[2 * np + 1], qh, kh[np][2], kh[np][3]);
                }
                #pragma unroll
                for (int np = 0; np < 4; np++) {
                    mma16816(s[2 * np],     qh, kl[np][0], kl[np][1]);
                    mma16816(s[2 * np + 1], qh, kl[np][2], kl[np][3]);
                }
                #pragma unroll
                for (int np = 0; np < 4; np++) {
                    mma16816(s[2 * np],     ql, kh[np][0], kh[np][1]);
                    mma16816(s[2 * np + 1], ql, kh[np][2], kh[np][3]);
                }
            }

            #pragma unroll
            for (int j = 0; j < 8; j++)
                #pragma unroll
                for (int e = 0; e < 4; e++) s[j][e] *= SC;
            if (kt * 64 + 63 > wrow) {
                const int row_lo = wrow + rl, row_hi = row_lo + 8;
                #pragma unroll
                for (int j = 0; j < 8; j++) {
                    int c0 = kt * 64 + j * 8 + ((lane & 3) << 1);
                    if (c0 > row_lo)     s[j][0] = -1e30f;
                    if (c0 + 1 > row_lo) s[j][1] = -1e30f;
                    if (c0 > row_hi)     s[j][2] = -1e30f;
                    if (c0 + 1 > row_hi) s[j][3] = -1e30f;
                }
            }

            float mx0 = -1e30f, mx1 = -1e30f;
            #pragma unroll
            for (int j = 0; j < 8; j++) {
                mx0 = fmaxf(mx0, fmaxf(s[j][0], s[j][1]));
                mx1 = fmaxf(mx1, fmaxf(s[j][2], s[j][3]));
            }
            mx0 = fmaxf(mx0, __shfl_xor_sync(0xffffffffu, mx0, 1));
            mx0 = fmaxf(mx0, __shfl_xor_sync(0xffffffffu, mx0, 2));
            mx1 = fmaxf(mx1, __shfl_xor_sync(0xffffffffu, mx1, 1));
            mx1 = fmaxf(mx1, __shfl_xor_sync(0xffffffffu, mx1, 2));
            float mn0 = fmaxf(m_lo, mx0), mn1 = fmaxf(m_hi, mx1);
            float c0 = ex2f(m_lo - mn0), c1 = ex2f(m_hi - mn1);
            float su0 = 0.f, su1 = 0.f;
            #pragma unroll
            for (int j = 0; j < 8; j++) {
                s[j][0] = ex2f(s[j][0] - mn0);
                s[j][1] = ex2f(s[j][1] - mn0);
                s[j][2] = ex2f(s[j][2] - mn1);
                s[j][3] = ex2f(s[j][3] - mn1);
                su0 += s[j][0] + s[j][1];
                su1 += s[j][2] + s[j][3];
            }
            su0 += __shfl_xor_sync(0xffffffffu, su0, 1);
            su0 += __shfl_xor_sync(0xffffffffu, su0, 2);
            su1 += __shfl_xor_sync(0xffffffffu, su1, 1);
            su1 += __shfl_xor_sync(0xffffffffu, su1, 2);
            l_lo = l_lo * c0 + su0;  l_hi = l_hi * c1 + su1;
            m_lo = mn0;              m_hi = mn1;
            #pragma unroll
            for (int nt = 0; nt < 16; nt++) {
                o[nt][0] *= c0; o[nt][1] *= c0;
                o[nt][2] *= c1; o[nt][3] *= c1;
            }

            #pragma unroll
            for (int ks = 0; ks < 4; ks++) {
                uint32_t ph[4], pl[4];
                split_pack(s[2 * ks][0],     s[2 * ks][1],     ph[0], pl[0]);
                split_pack(s[2 * ks][2],     s[2 * ks][3],     ph[1], pl[1]);
                split_pack(s[2 * ks + 1][0], s[2 * ks + 1][1], ph[2], pl[2]);
                split_pack(s[2 * ks + 1][2], s[2 * ks + 1][3], ph[3], pl[3]);
                #pragma unroll
                for (int npp = 0; npp < 4; npp++) {
                    uint32_t vh0[4], vl0[4], vh1[4], vl1[4];
                    uint32_t rv = kb + 2 * AT64
                        + (ks * 16 + (lane & 15)) * ATSTR
                        + npp * 64 + ((lane >> 4) << 4);
                    ldsm4t(vh0[0], vh0[1], vh0[2], vh0[3], rv);
                    ldsm4t(vl0[0], vl0[1], vl0[2], vl0[3], rv + AT64);
                    ldsm4t(vh1[0], vh1[1], vh1[2], vh1[3], rv + 32);
                    ldsm4t(vl1[0], vl1[1], vl1[2], vl1[3], rv + 32 + AT64);
                    float* o0 = o[4 * npp];     float* o1 = o[4 * npp + 1];
                    float* o2 = o[4 * npp + 2]; float* o3 = o[4 * npp + 3];
                    mma16816(o0, ph, vh0[0], vh0[1]);
                    mma16816(o1, ph, vh0[2], vh0[3]);
                    mma16816(o2, ph, vh1[0], vh1[1]);
                    mma16816(o3, ph, vh1[2], vh1[3]);
                    mma16816(o0, ph, vl0[0], vl0[1]);
                    mma16816(o1, ph, vl0[2], vl0[3]);
                    mma16816(o2, ph, vl1[0], vl1[1]);
                    mma16816(o3, ph, vl1[2], vl1[3]);
                    mma16816(o0, pl, vh0[0], vh0[1]);
                    mma16816(o1, pl, vh0[2], vh0[3]);
                    mma16816(o2, pl, vh1[0], vh1[1]);
                    mma16816(o3, pl, vh1[2], vh1[3]);
                }
            }
        }
        __syncthreads();
        if (kt + 2 <= ktmax)
            attn_load_kv(sb + 2 * AQ_B + (kt & 1) * AKV_B, tid,
                         Kh_, Kl_, Vh_, Vl_, krow0 + (size_t)(kt + 2) * 64, gcol);
    }

    const float i0 = 1.f / l_lo, i1 = 1.f / l_hi;
    const size_t row_lo = qrow0 + w * 16 + rl;
    const size_t row_hi = row_lo + 8;
    const int colb = h * DH + ((lane & 3) << 1);
    #pragma unroll
    for (int nt = 0; nt < 16; nt++) {
        int col = colb + nt * 8;
        float2 w0 = { o[nt][0] * i0, o[nt][1] * i0 };
        float2 w1 = { o[nt][2] * i1, o[nt][3] * i1 };
        *(float2*)&Yf_[row_lo * DD + col] = w0;
        *(float2*)&Yf_[row_hi * DD + col] = w1;
    }
}

// ---------------------------------------------------------------------------
extern "C" void kernel_launch(void* const* d_in, const int* in_sizes, int n_in,
                              void* d_out, int out_size)
{
    (void)in_sizes; (void)n_in; (void)out_size;
    const float* X  = (const float*)d_in[0];
    const float* Wq = (const float*)d_in[1];
    const float* bq = (const float*)d_in[2];
    const float* Wk = (const float*)d_in[3];
    const float* bk = (const float*)d_in[4];
    const float* Wv = (const float*)d_in[5];
    const float* bv = (const float*)d_in[6];
    const float* Wo = (const float*)d_in[7];
    const float* bo = (const float*)d_in[8];
    float* out = (float*)d_out;

    int8_t *X0, *X1, *Wq0, *Wq1, *Wk0, *Wk1, *Wv0, *Wv1, *Wo0, *Wo1, *Y0, *Y1;
    float *sX, *sWq, *sWk, *sWv, *sWo, *sY, *Yf;
    __nv_bfloat16 *Qh, *Ql, *Kh, *Kl, *Vh, *Vl;
    cudaGetSymbolAddress((void**)&X0, g_X0);   cudaGetSymbolAddress((void**)&X1, g_X1);
    cudaGetSymbolAddress((void**)&Wq0, g_Wq0); cudaGetSymbolAddress((void**)&Wq1, g_Wq1);
    cudaGetSymbolAddress((void**)&Wk0, g_Wk0); cudaGetSymbolAddress((void**)&Wk1, g_Wk1);
    cudaGetSymbolAddress((void**)&Wv0, g_Wv0); cudaGetSymbolAddress((void**)&Wv1, g_Wv1);
    cudaGetSymbolAddress((void**)&Wo0, g_Wo0); cudaGetSymbolAddress((void**)&Wo1, g_Wo1);
    cudaGetSymbolAddress((void**)&Y0, g_Y0);   cudaGetSymbolAddress((void**)&Y1, g_Y1);
    cudaGetSymbolAddress((void**)&sX, g_sX);   cudaGetSymbolAddress((void**)&sWq, g_sWq);
    cudaGetSymbolAddress((void**)&sWk, g_sWk); cudaGetSymbolAddress((void**)&sWv, g_sWv);
    cudaGetSymbolAddress((void**)&sWo, g_sWo); cudaGetSymbolAddress((void**)&sY, g_sY);
    cudaGetSymbolAddress((void**)&Yf, g_Yf);
    cudaGetSymbolAddress((void**)&Qh, g_Q_hi); cudaGetSymbolAddress((void**)&Ql, g_Q_lo);
    cudaGetSymbolAddress((void**)&Kh, g_K_hi); cudaGetSymbolAddress((void**)&Kl, g_K_lo);
    cudaGetSymbolAddress((void**)&Vh, g_V_hi); cudaGetSymbolAddress((void**)&Vl, g_V_lo);

    cudaFuncSetAttribute(gemm_i8,
                         cudaFuncAttributeMaxDynamicSharedMemorySize, GEMM_SMEM);
    cudaFuncSetAttribute(attn_mma,
                         cudaFuncAttributeMaxDynamicSharedMemorySize, ATTN_SMEM);

    // int8 2-slice splits (one block per row)
    split_i8<<<MTOT, 128>>>(X,  X0,  X1,  sX,  DD);
    split_i8<<<DD,   128>>>(Wq, Wq0, Wq1, sWq, DD);
    split_i8<<<KVD,  128>>>(Wk, Wk0, Wk1, sWk, DD);
    split_i8<<<KVD,  128>>>(Wv, Wv0, Wv1, sWv, DD);
    split_i8<<<DD,   128>>>(Wo, Wo0, Wo1, sWo, DD);

    // projections (int8) -> bf16 hi/lo for attention
    gemm_i8<<<dim3(DD / 128,  MTOT / 128), 256, GEMM_SMEM>>>(
        X0, X1, sX, Wq0, Wq1, sWq, bq, nullptr, Qh, Ql, MTOT, DD,  DD);
    gemm_i8<<<dim3(KVD / 128, MTOT / 128), 256, GEMM_SMEM>>>(
        X0, X1, sX, Wk0, Wk1, sWk, bk, nullptr, Kh, Kl, MTOT, KVD, DD);
    gemm_i8<<<dim3(KVD / 128, MTOT / 128), 256, GEMM_SMEM>>>(
        X0, X1, sX, Wv0, Wv1, sWv, bv, nullptr, Vh, Vl, MTOT, KVD, DD);

    // attention (bf16 HMMA) -> fp32 Y
    attn_mma<<<dim3(TT / 128, BB * HH), 256, ATTN_SMEM>>>(
        Qh, Ql, Kh, Kl, Vh, Vl, Yf);

    // re-quantize Y, output projection (int8) -> fp32 out
    split_i8<<<MTOT, 128>>>(Yf, Y0, Y1, sY, DD);
    gemm_i8<<<dim3(DD / 128, MTOT / 128), 256, GEMM_SMEM>>>(
        Y0, Y1, sY, Wo0, Wo1, sWo, bo, out, nullptr, nullptr, MTOT, DD, DD);
}

// round 9
// speedup vs baseline: 2.4012x; 2.4012x over previous
#include <cuda_runtime.h>
#include <cuda_bf16.h>
#include <cuda_fp16.h>
#include <cstdint>

#define BB   2
#define TT   2048
#define DD   4096
#define HH   32
#define GG   8
#define DH   128
#define KVD  (GG*DH)     /* 1024 */
#define NQKV (DD+2*KVD)  /* 6144 */
#define MTOT (BB*TT)     /* 4096 */

// bf16 hi/lo operands
__device__ __nv_bfloat16 g_X_hi[(size_t)MTOT * DD],  g_X_lo[(size_t)MTOT * DD];
__device__ __nv_bfloat16 g_Wqkv_hi[(size_t)NQKV * DD], g_Wqkv_lo[(size_t)NQKV * DD];
__device__ __nv_bfloat16 g_Q_hi[(size_t)MTOT * DD],  g_Q_lo[(size_t)MTOT * DD];
__device__ __nv_bfloat16 g_K_hi[(size_t)MTOT * KVD], g_K_lo[(size_t)MTOT * KVD];
__device__ __nv_bfloat16 g_V_hi[(size_t)MTOT * KVD], g_V_lo[(size_t)MTOT * KVD];
// fp16 operands for O projection (2-product scheme)
__device__ __half g_Wo_f[(size_t)DD * DD];
__device__ __half g_Y_h[(size_t)MTOT * DD], g_Y_l[(size_t)MTOT * DD];

// ---------------------------------------------------------------------------
__device__ __forceinline__ uint32_t smem_u32(const void* p) {
    uint32_t a;
    asm("{ .reg .u64 t; cvta.to.shared.u64 t, %1; cvt.u32.u64 %0, t; }"
        : "=r"(a) : "l"(p));
    return a;
}
__device__ __forceinline__ void ldsm4(uint32_t& r0, uint32_t& r1, uint32_t& r2,
                                      uint32_t& r3, uint32_t addr) {
    asm volatile("ldmatrix.sync.aligned.m8n8.x4.shared.b16 {%0,%1,%2,%3}, [%4];"
                 : "=r"(r0), "=r"(r1), "=r"(r2), "=r"(r3) : "r"(addr));
}
__device__ __forceinline__ void ldsm4t(uint32_t& r0, uint32_t& r1, uint32_t& r2,
                                       uint32_t& r3, uint32_t addr) {
    asm volatile("ldmatrix.sync.aligned.m8n8.x4.trans.shared.b16 {%0,%1,%2,%3}, [%4];"
                 : "=r"(r0), "=r"(r1), "=r"(r2), "=r"(r3) : "r"(addr));
}
__device__ __forceinline__ void mma16816(float* c, const uint32_t* a,
                                         uint32_t b0, uint32_t b1) {
    asm volatile(
        "mma.sync.aligned.m16n8k16.row.col.f32.bf16.bf16.f32 "
        "{%0,%1,%2,%3}, {%4,%5,%6,%7}, {%8,%9}, {%0,%1,%2,%3};"
        : "+f"(c[0]), "+f"(c[1]), "+f"(c[2]), "+f"(c[3])
        : "r"(a[0]), "r"(a[1]), "r"(a[2]), "r"(a[3]), "r"(b0), "r"(b1));
}
__device__ __forceinline__ void mma16816h(float* c, const uint32_t* a,
                                          uint32_t b0, uint32_t b1) {
    asm volatile(
        "mma.sync.aligned.m16n8k16.row.col.f32.f16.f16.f32 "
        "{%0,%1,%2,%3}, {%4,%5,%6,%7}, {%8,%9}, {%0,%1,%2,%3};"
        : "+f"(c[0]), "+f"(c[1]), "+f"(c[2]), "+f"(c[3])
        : "r"(a[0]), "r"(a[1]), "r"(a[2]), "r"(a[3]), "r"(b0), "r"(b1));
}
__device__ __forceinline__ void cpasync16(uint32_t dst, const void* src) {
    asm volatile("cp.async.cg.shared.global [%0], [%1], 16;"
                 :: "r"(dst), "l"(src) : "memory");
}
#define CP_COMMIT() asm volatile("cp.async.commit_group;" ::: "memory")
#define CP_WAIT1()  asm volatile("cp.async.wait_group 1;" ::: "memory")
#define CP_WAIT0()  asm volatile("cp.async.wait_group 0;" ::: "memory")

__device__ __forceinline__ float ex2f(float x) {
    float y;
    asm("ex2.approx.ftz.f32 %0, %1;" : "=f"(y) : "f"(x));
    return y;
}
__device__ __forceinline__ void split_pack(float a, float b,
                                           uint32_t& h, uint32_t& l) {
    __nv_bfloat162 hb = __floats2bfloat162_rn(a, b);
    __nv_bfloat162 lb = __floats2bfloat162_rn(a - __low2float(hb),
                                              b - __high2float(hb));
    h = *reinterpret_cast<uint32_t*>(&hb);
    l = *reinterpret_cast<uint32_t*>(&lb);
}
__device__ __forceinline__ void split_pack_h(float a, float b,
                                             uint32_t& h, uint32_t& l) {
    __half2 hb = __floats2half2_rn(a, b);
    float2 bk = __half22float2(hb);
    __half2 lb = __floats2half2_rn(a - bk.x, b - bk.y);
    h = *reinterpret_cast<uint32_t*>(&hb);
    l = *reinterpret_cast<uint32_t*>(&lb);
}

// ---------------------------------------------------------------------------
// fp32 -> (bf16 hi, bf16 lo)
__global__ void split_bf16(const float* __restrict__ x,
                           __nv_bfloat16* __restrict__ hi,
                           __nv_bfloat16* __restrict__ lo, int n4)
{
    int i = blockIdx.x * blockDim.x + threadIdx.x;
    if (i >= n4) return;
    float4 v = ((const float4*)x)[i];
    uint32_t h0, l0, h1, l1;
    split_pack(v.x, v.y, h0, l0);
    split_pack(v.z, v.w, h1, l1);
    ((uint32_t*)hi)[2 * i] = h0; ((uint32_t*)hi)[2 * i + 1] = h1;
    ((uint32_t*)lo)[2 * i] = l0; ((uint32_t*)lo)[2 * i + 1] = l1;
}
// fp32 -> fp16 (single)
__global__ void conv_f16(const float* __restrict__ x,
                         __half* __restrict__ y, int n4)
{
    int i = blockIdx.x * blockDim.x + threadIdx.x;
    if (i >= n4) return;
    float4 v = ((const float4*)x)[i];
    __half2 a = __floats2half2_rn(v.x, v.y);
    __half2 b = __floats2half2_rn(v.z, v.w);
    ((uint32_t*)y)[2 * i]     = *reinterpret_cast<uint32_t*>(&a);
    ((uint32_t*)y)[2 * i + 1] = *reinterpret_cast<uint32_t*>(&b);
}

// ---------------------------------------------------------------------------
// Merged QKV GEMM (bf16 3-term): CTA 128x256, 8 warps 64x64, K-chunk 32.
// Output routed per column tile: [0,4096)->Q, [4096,5120)->K, [5120,6144)->V.
// ---------------------------------------------------------------------------
#define GK    32
#define RS    40
#define A_SUB (128 * RS * 2)
#define B_SUB (256 * RS * 2)
#define STAGE_B (2 * A_SUB + 2 * B_SUB)
#define GEMM_SMEM (2 * STAGE_B)

struct GemmPtrs { const __nv_bfloat16 *ah, *al, *bh, *bl; };

__device__ __forceinline__ void load_stage(
    uint32_t sb, int tid, const GemmPtrs& p, int K, int k0)
{
    #pragma unroll
    for (int t = 0; t < 12; t++) {
        const int id = t * 256 + tid;
        const __nv_bfloat16* src;
        uint32_t dst;
        if (id < 1024) {
            const int x = id & 511;
            const int r = x >> 2, c8 = (x & 3) << 3;
            src = (id < 512 ? p.ah : p.al) + (size_t)r * K + k0 + c8;
            dst = sb + (id < 512 ? 0u : (uint32_t)A_SUB) + r * (RS * 2) + c8 * 2;
        } else {
            const int v = id - 1024;
            const int x = v & 1023;
            const int r = x >> 2, c8 = (x & 3) << 3;
            src = (v < 1024 ? p.bh : p.bl) + (size_t)r * K + k0 + c8;
            dst = sb + 2 * A_SUB + (v < 1024 ? 0u : (uint32_t)B_SUB)
                + r * (RS * 2) + c8 * 2;
        }
        cpasync16(dst, src);
    }
}

__global__ __launch_bounds__(256, 1) void gemm_qkv(
    const __nv_bfloat16* __restrict__ Ahi, const __nv_bfloat16* __restrict__ Alo,
    const __nv_bfloat16* __restrict__ Bhi, const __nv_bfloat16* __restrict__ Blo,
    const float* __restrict__ bq, const float* __restrict__ bk,
    const float* __restrict__ bv,
    __nv_bfloat16* __restrict__ Qh, __nv_bfloat16* __restrict__ Ql,
    __nv_bfloat16* __restrict__ Kh, __nv_bfloat16* __restrict__ Kl,
    __nv_bfloat16* __restrict__ Vh, __nv_bfloat16* __restrict__ Vl)
{
    extern __shared__ char sm_[];
    const uint32_t smem_base = smem_u32(sm_);
    const int tid  = threadIdx.x;
    const int wid  = tid >> 5;
    const int lane = tid & 31;
    const int wm   = wid >> 2;
    const int wn   = wid & 3;
    const int brow = blockIdx.y << 7;
    const int bcol = blockIdx.x << 8;
    const int K    = DD;

    // route output
    __nv_bfloat16 *Ch, *Cl; const float* bias; int outN, obase;
    if (bcol < DD)            { Ch = Qh; Cl = Ql; bias = bq; outN = DD;  obase = bcol; }
    else if (bcol < DD + KVD) { Ch = Kh; Cl = Kl; bias = bk; outN = KVD; obase = bcol - DD; }
    else                      { Ch = Vh; Cl = Vl; bias = bv; outN = KVD; obase = bcol - DD - KVD; }

    GemmPtrs p;
    p.ah = Ahi + (size_t)brow * K;  p.al = Alo + (size_t)brow * K;
    p.bh = Bhi + (size_t)bcol * K;  p.bl = Blo + (size_t)bcol * K;

    float acc[4][8][4];
    #pragma unroll
    for (int i = 0; i < 4; i++)
        #pragma unroll
        for (int j = 0; j < 8; j++)
            #pragma unroll
            for (int k = 0; k < 4; k++) acc[i][j][k] = 0.f;

    const int nchunks = K / GK;

    load_stage(smem_base, tid, p, K, 0);            CP_COMMIT();
    load_stage(smem_base + STAGE_B, tid, p, K, GK); CP_COMMIT();
    CP_WAIT1();
    __syncthreads();

    const int a_row = lane & 15;
    const int a_kb  = (lane >> 4) << 4;
    const int b_row = (lane & 7) + ((lane >> 4) << 3);
    const int b_kb  = ((lane >> 3) & 1) << 4;

    for (int chunk = 0; chunk < nchunks; chunk++) {
        const uint32_t sb = smem_base + (chunk & 1) * STAGE_B;

        #pragma unroll
        for (int ks = 0; ks < 2; ks++) {
            uint32_t ah[4][4], al[4][4];
            #pragma unroll
            for (int mt = 0; mt < 4; mt++) {
                uint32_t ra = sb + (wm * 64 + mt * 16 + a_row) * (RS * 2)
                            + ks * 32 + a_kb;
                ldsm4(ah[mt][0], ah[mt][1], ah[mt][2], ah[mt][3], ra);
                ldsm4(al[mt][0], al[mt][1], al[mt][2], al[mt][3], ra + A_SUB);
            }
            #pragma unroll
            for (int bt = 0; bt < 4; bt++) {
                uint32_t bh[4], bl[4];
                uint32_t rb = sb + 2 * A_SUB
                            + (wn * 64 + bt * 16 + b_row) * (RS * 2)
                            + ks * 32 + b_kb;
                ldsm4(bh[0], bh[1], bh[2], bh[3], rb);
                ldsm4(bl[0], bl[1], bl[2], bl[3], rb + B_SUB);
                #pragma unroll
                for (int mt = 0; mt < 4; mt++) {
                    mma16816(acc[mt][bt * 2],     ah[mt], bh[0], bh[1]);
                    mma16816(acc[mt][bt * 2 + 1], ah[mt], bh[2], bh[3]);
                }
                #pragma unroll
                for (int mt = 0; mt < 4; mt++) {
                    mma16816(acc[mt][bt * 2],     ah[mt], bl[0], bl[1]);
                    mma16816(acc[mt][bt * 2 + 1], ah[mt], bl[2], bl[3]);
                }
                #pragma unroll
                for (int mt = 0; mt < 4; mt++) {
                    mma16816(acc[mt][bt * 2],     al[mt], bh[0], bh[1]);
                    mma16816(acc[mt][bt * 2 + 1], al[mt], bh[2], bh[3]);
                }
            }
        }
        __syncthreads();

        if (chunk + 2 < nchunks) {
            load_stage(smem_base + (chunk & 1) * STAGE_B, tid, p, K,
                       (chunk + 2) * GK);
            CP_COMMIT();
            CP_WAIT1();
            __syncthreads();
        } else if (chunk + 1 < nchunks) {
            CP_WAIT0();
            __syncthreads();
        }
    }

    const int crow = lane >> 2;
    const int ccol = (lane & 3) << 1;
    #pragma unroll
    for (int nt = 0; nt < 8; nt++) {
        const int col = obase + wn * 64 + nt * 8 + ccol;
        float b0 = __ldg(&bias[col]), b1 = __ldg(&bias[col + 1]);
        #pragma unroll
        for (int mt = 0; mt < 4; mt++) {
            size_t row0 = (size_t)(brow + wm * 64 + mt * 16 + crow);
            float x0 = acc[mt][nt][0] + b0, x1 = acc[mt][nt][1] + b1;
            float x2 = acc[mt][nt][2] + b0, x3 = acc[mt][nt][3] + b1;
            uint32_t h0, l0, h1, l1;
            split_pack(x0, x1, h0, l0);
            split_pack(x2, x3, h1, l1);
            *(uint32_t*)&Ch[row0 * outN + col]       = h0;
            *(uint32_t*)&Cl[row0 * outN + col]       = l0;
            *(uint32_t*)&Ch[(row0 + 8) * outN + col] = h1;
            *(uint32_t*)&Cl[(row0 + 8) * outN + col] = l1;
        }
    }
}

// ---------------------------------------------------------------------------
// fp16 2-product GEMM (O projection): C = (Yh+Yl) @ Wo^T + bias, fp32 out.
// A split fp16 (hi,lo); B single fp16.  CTA 128x256, warps 64x64, K-chunk 32.
// ---------------------------------------------------------------------------
#define A16SUB (128 * 80)               /* 10240 B */
#define B16SUB (256 * 80)               /* 20480 B */
#define STAGE16 (2 * A16SUB + B16SUB)   /* 40960 B */
#define GEMMF_SMEM (2 * STAGE16)        /* 81920 B */

__device__ __forceinline__ void load_stage_f16(
    uint32_t sb, int tid, const __half* ah, const __half* al,
    const __half* b, int K, int k0)
{
    #pragma unroll
    for (int t = 0; t < 8; t++) {
        const int id = t * 256 + tid;         // 0..2047
        if (id < 1024) {                       // A hi/lo
            const int x = id & 511;
            const int r = x >> 2, cb = (x & 3) << 4;
            const __half* src = (id < 512 ? ah : al) + (size_t)r * K + k0 + (cb >> 1);
            cpasync16(sb + (id < 512 ? 0u : (uint32_t)A16SUB) + r * 80 + cb, src);
        } else {                               // B
            const int x = id - 1024;
            const int r = x >> 2, cb = (x & 3) << 4;
            cpasync16(sb + 2 * A16SUB + r * 80 + cb,
                      b + (size_t)r * K + k0 + (cb >> 1));
        }
    }
}

__global__ __launch_bounds__(256, 1) void gemm_f16(
    const __half* __restrict__ Ah, const __half* __restrict__ Al,
    const __half* __restrict__ B,
    const float* __restrict__ bias, float* __restrict__ Cf, int N, int K)
{
    extern __shared__ char sm_[];
    const uint32_t smem_base = smem_u32(sm_);
    const int tid  = threadIdx.x;
    const int wid  = tid >> 5;
    const int lane = tid & 31;
    const int wm   = wid >> 2;
    const int wn   = wid & 3;
    const int brow = blockIdx.y << 7;
    const int bcol = blockIdx.x << 8;

    const __half* pa = Ah + (size_t)brow * K;
    const __half* pl = Al + (size_t)brow * K;
    const __half* pb = B  + (size_t)bcol * K;

    float acc[4][8][4];
    #pragma unroll
    for (int i = 0; i < 4; i++)
        #pragma unroll
        for (int j = 0; j < 8; j++)
            #pragma unroll
            for (int k = 0; k < 4; k++) acc[i][j][k] = 0.f;

    const int nchunks = K / GK;

    load_stage_f16(smem_base, tid, pa, pl, pb, K, 0);            CP_COMMIT();
    load_stage_f16(smem_base + STAGE16, tid, pa, pl, pb, K, GK); CP_COMMIT();
    CP_WAIT1();
    __syncthreads();

    const int a_row = lane & 15;
    const int a_kb  = (lane >> 4) << 4;
    const int b_row = (lane & 7) + ((lane >> 4) << 3);
    const int b_kb  = ((lane >> 3) & 1) << 4;

    for (int chunk = 0; chunk < nchunks; chunk++) {
        const uint32_t sb = smem_base + (chunk & 1) * STAGE16;

        #pragma unroll
        for (int ks = 0; ks < 2; ks++) {
            uint32_t ah[4][4], al[4][4], bh[4][4];
            #pragma unroll
            for (int mt = 0; mt < 4; mt++) {
                uint32_t ra = sb + (wm * 64 + mt * 16 + a_row) * 80
                            + ks * 32 + a_kb;
                ldsm4(ah[mt][0], ah[mt][1], ah[mt][2], ah[mt][3], ra);
                ldsm4(al[mt][0], al[mt][1], al[mt][2], al[mt][3], ra + A16SUB);
            }
            #pragma unroll
            for (int bt = 0; bt < 4; bt++) {
                uint32_t rb = sb + 2 * A16SUB
                            + (wn * 64 + bt * 16 + b_row) * 80
                            + ks * 32 + b_kb;
                ldsm4(bh[bt][0], bh[bt][1], bh[bt][2], bh[bt][3], rb);
            }
            // term hi (32 independent accumulators)
            #pragma unroll
            for (int bt = 0; bt < 4; bt++)
                #pragma unroll
                for (int mt = 0; mt < 4; mt++) {
                    mma16816h(acc[mt][bt * 2],     ah[mt], bh[bt][0], bh[bt][1]);
                    mma16816h(acc[mt][bt * 2 + 1], ah[mt], bh[bt][2], bh[bt][3]);
                }
            // term lo
            #pragma unroll
            for (int bt = 0; bt < 4; bt++)
                #pragma unroll
                for (int mt = 0; mt < 4; mt++) {
                    mma16816h(acc[mt][bt * 2],     al[mt], bh[bt][0], bh[bt][1]);
                    mma16816h(acc[mt][bt * 2 + 1], al[mt], bh[bt][2], bh[bt][3]);
                }
        }
        __syncthreads();

        if (chunk + 2 < nchunks) {
            load_stage_f16(smem_base + (chunk & 1) * STAGE16, tid, pa, pl, pb,
                           K, (chunk + 2) * GK);
            CP_COMMIT();
            CP_WAIT1();
            __syncthreads();
        } else if (chunk + 1 < nchunks) {
            CP_WAIT0();
            __syncthreads();
        }
    }

    const int crow = lane >> 2;
    const int ccol = (lane & 3) << 1;
    #pragma unroll
    for (int nt = 0; nt < 8; nt++) {
        const int col = bcol + wn * 64 + nt * 8 + ccol;
        float b0 = __ldg(&bias[col]), b1 = __ldg(&bias[col + 1]);
        #pragma unroll
        for (int mt = 0; mt < 4; mt++) {
            size_t row0 = (size_t)(brow + wm * 64 + mt * 16 + crow);
            float2 v0 = { acc[mt][nt][0] + b0, acc[mt][nt][1] + b1 };
            float2 v1 = { acc[mt][nt][2] + b0, acc[mt][nt][3] + b1 };
            *(float2*)&Cf[row0 * N + col]       = v0;
            *(float2*)&Cf[(row0 + 8) * N + col] = v1;
        }
    }
}

// ---------------------------------------------------------------------------
// HMMA causal GQA flash attention (bf16 3-term); Y output as fp16 hi/lo.
// ---------------------------------------------------------------------------
#define ATSTR 272
#define AT64  (64 * ATSTR)
#define AQ_B  (128 * ATSTR)
#define AKV_B (4 * AT64)
#define ATTN_SMEM (2 * AQ_B + 2 * AKV_B)

__device__ __forceinline__ void attn_load_kv(
    uint32_t base, int tid,
    const __nv_bfloat16* __restrict__ Kh, const __nv_bfloat16* __restrict__ Kl,
    const __nv_bfloat16* __restrict__ Vh, const __nv_bfloat16* __restrict__ Vl,
    size_t grow0, int gcol)
{
    const __nv_bfloat16* srcs[4] = { Kh, Kl, Vh, Vl };
    #pragma unroll
    for (int t = 0; t < 4; t++) {
        const __nv_bfloat16* s = srcs[t] + grow0 * KVD + gcol;
        #pragma unroll
        for (int i = 0; i < 4; i++) {
            int ch = tid + i * 256;
            int r = ch >> 4, c = ch & 15;
            cpasync16(base + t * AT64 + r * ATSTR + c * 16,
                      s + (size_t)r * KVD + c * 8);
        }
    }
    CP_COMMIT();
}

__global__ __launch_bounds__(256, 1) void attn_mma(
    const __nv_bfloat16* __restrict__ Qh_, const __nv_bfloat16* __restrict__ Ql_,
    const __nv_bfloat16* __restrict__ Kh_, const __nv_bfloat16* __restrict__ Kl_,
    const __nv_bfloat16* __restrict__ Vh_, const __nv_bfloat16* __restrict__ Vl_,
    __half* __restrict__ Yh_, __half* __restrict__ Yl_)
{
    extern __shared__ char sm_[];
    const uint32_t sb = smem_u32(sm_);
    const int tid  = threadIdx.x;
    const int lane = tid & 31;
    const int w    = tid >> 5;
    const int qt   = (int)gridDim.x - 1 - (int)blockIdx.x;
    const int bh   = blockIdx.y;
    const int b    = bh >> 5, h = bh & 31, g = h >> 2;
    const int ktmax = 2 * qt + 1;
    const size_t qrow0 = (size_t)b * TT + (size_t)qt * 128;
    const size_t krow0 = (size_t)b * TT;
    const int gcol = g * DH;

    {
        const __nv_bfloat16* q0 = Qh_ + qrow0 * DD + h * DH;
        const __nv_bfloat16* q1 = Ql_ + qrow0 * DD + h * DH;
        #pragma unroll
        for (int i = 0; i < 8; i++) {
            int ch = tid + i * 256;
            int r = ch >> 4, c = ch & 15;
            cpasync16(sb + r * ATSTR + c * 16,        q0 + (size_t)r * DD + c * 8);
            cpasync16(sb + AQ_B + r * ATSTR + c * 16, q1 + (size_t)r * DD + c * 8);
        }
        CP_COMMIT();
    }
    attn_load_kv(sb + 2 * AQ_B, tid, Kh_, Kl_, Vh_, Vl_, krow0, gcol);
    attn_load_kv(sb + 2 * AQ_B + AKV_B, tid, Kh_, Kl_, Vh_, Vl_, krow0 + 64, gcol);

    float o[16][4];
    #pragma unroll
    for (int i = 0; i < 16; i++)
        #pragma unroll
        for (int j = 0; j < 4; j++) o[i][j] = 0.f;
    float m_lo = -1e30f, m_hi = -1e30f, l_lo = 0.f, l_hi = 0.f;

    const int wrow = qt * 128 + w * 16;
    const int rl   = lane >> 2;
    const float SC = 0.088388347648318447f * 1.4426950408889634f;

    for (int kt = 0; kt <= ktmax; kt++) {
        if (kt < ktmax) { CP_WAIT1(); } else { CP_WAIT0(); }
        __syncthreads();
        const uint32_t kb = sb + 2 * AQ_B + (kt & 1) * AKV_B;

        if (kt * 64 <= wrow + 15) {
            float s[8][4];
            #pragma unroll
            for (int j = 0; j < 8; j++)
                #pragma unroll
                for (int e = 0; e < 4; e++) s[j][e] = 0.f;

            #pragma unroll
            for (int ks = 0; ks < 8; ks++) {
                uint32_t qh[4], ql[4];
                uint32_t ra = sb + (w * 16 + (lane & 15)) * ATSTR
                            + ks * 32 + ((lane >> 4) << 4);
                ldsm4(qh[0], qh[1], qh[2], qh[3], ra);
                ldsm4(ql[0], ql[1], ql[2], ql[3], ra + AQ_B);
                uint32_t kh[4][4], kl[4][4];
                #pragma unroll
                for (int np = 0; np < 4; np++) {
                    uint32_t rb = kb
                        + (np * 16 + (lane & 7) + ((lane >> 4) << 3)) * ATSTR
                        + ks * 32 + (((lane >> 3) & 1) << 4);
                    ldsm4(kh[np][0], kh[np][1], kh[np][2], kh[np][3], rb);
                    ldsm4(kl[np][0], kl[np][1], kl[np][2], kl[np][3], rb + AT64);
                }
                #pragma unroll
                for (int np = 0; np < 4; np++) {
                    mma16816(s[2 * np],     qh, kh[np][0], kh[np][1]);
                    mma16816(s[2 * np + 1], qh, kh[np][2], kh[np][3]);
                }
                #pragma unroll
                for (int np = 0; np < 4; np++) {
                    mma16816(s[2 * np],     qh, kl[np][0], kl[np][1]);
                    mma16816(s[2 * np + 1], qh, kl[np][2], kl[np][3]);
                }
                #pragma unroll
                for (int np = 0; np < 4; np++) {
                    mma16816(s[2 * np],     ql, kh[np][0], kh[np][1]);
                    mma16816(s[2 * np + 1], ql, kh[np][2], kh[np][3]);
                }
            }

            #pragma unroll
            for (int j = 0; j < 8; j++)
                #pragma unroll
                for (int e = 0; e < 4; e++) s[j][e] *= SC;
            if (kt * 64 + 63 > wrow) {
                const int row_lo = wrow + rl, row_hi = row_lo + 8;
                #pragma unroll
                for (int j = 0; j < 8; j++) {
                    int c0 = kt * 64 + j * 8 + ((lane & 3) << 1);
                    if (c0 > row_lo)     s[j][0] = -1e30f;
                    if (c0 + 1 > row_lo) s[j][1] = -1e30f;
                    if (c0 > row_hi)     s[j][2] = -1e30f;
                    if (c0 + 1 > row_hi) s[j][3] = -1e30f;
                }
            }

            float mx0 = -1e30f, mx1 = -1e30f;
            #pragma unroll
            for (int j = 0; j < 8; j++) {
                mx0 = fmaxf(mx0, fmaxf(s[j][0], s[j][1]));
                mx1 = fmaxf(mx1, fmaxf(s[j][2], s[j][3]));
            }
            mx0 = fmaxf(mx0, __shfl_xor_sync(0xffffffffu, mx0, 1));
            mx0 = fmaxf(mx0, __shfl_xor_sync(0xffffffffu, mx0, 2));
            mx1 = fmaxf(mx1, __shfl_xor_sync(0xffffffffu, mx1, 1));
            mx1 = fmaxf(mx1, __shfl_xor_sync(0xffffffffu, mx1, 2));
            float mn0 = fmaxf(m_lo, mx0), mn1 = fmaxf(m_hi, mx1);
            float c0 = ex2f(m_lo - mn0), c1 = ex2f(m_hi - mn1);
            float su0 = 0.f, su1 = 0.f;
            #pragma unroll
            for (int j = 0; j < 8; j++) {
                s[j][0] = ex2f(s[j][0] - mn0);
                s[j][1] = ex2f(s[j][1] - mn0);
                s[j][2] = ex2f(s[j][2] - mn1);
                s[j][3] = ex2f(s[j][3] - mn1);
                su0 += s[j][0] + s[j][1];
                su1 += s[j][2] + s[j][3];
            }
            su0 += __shfl_xor_sync(0xffffffffu, su0, 1);
            su0 += __shfl_xor_sync(0xffffffffu, su0, 2);
            su1 += __shfl_xor_sync(0xffffffffu, su1, 1);
            su1 += __shfl_xor_sync(0xffffffffu, su1, 2);
            l_lo = l_lo * c0 + su0;  l_hi = l_hi * c1 + su1;
            m_lo = mn0;              m_hi = mn1;
            #pragma unroll
            for (int nt = 0; nt < 16; nt++) {
                o[nt][0] *= c0; o[nt][1] *= c0;
                o[nt][2] *= c1; o[nt][3] *= c1;
            }

            #pragma unroll
            for (int ks = 0; ks < 4; ks++) {
                uint32_t ph[4], pl[4];
                split_pack(s[2 * ks][0],     s[2 * ks][1],     ph[0], pl[0]);
                split_pack(s[2 * ks][2],     s[2 * ks][3],     ph[1], pl[1]);
                split_pack(s[2 * ks + 1][0], s[2 * ks + 1][1], ph[2], pl[2]);
                split_pack(s[2 * ks + 1][2], s[2 * ks + 1][3], ph[3], pl[3]);
                #pragma unroll
                for (int npp = 0; npp < 4; npp++) {
                    uint32_t vh0[4], vl0[4], vh1[4], vl1[4];
                    uint32_t rv = kb + 2 * AT64
                        + (ks * 16 + (lane & 15)) * ATSTR
                        + npp * 64 + ((lane >> 4) << 4);
                    ldsm4t(vh0[0], vh0[1], vh0[2], vh0[3], rv);
                    ldsm4t(vl0[0], vl0[1], vl0[2], vl0[3], rv + AT64);
                    ldsm4t(vh1[0], vh1[1], vh1[2], vh1[3], rv + 32);
                    ldsm4t(vl1[0], vl1[1], vl1[2], vl1[3], rv + 32 + AT64);
                    float* o0 = o[4 * npp];     float* o1 = o[4 * npp + 1];
                    float* o2 = o[4 * npp + 2]; float* o3 = o[4 * npp + 3];
                    mma16816(o0, ph, vh0[0], vh0[1]);
                    mma16816(o1, ph, vh0[2], vh0[3]);
                    mma16816(o2, ph, vh1[0], vh1[1]);
                    mma16816(o3, ph, vh1[2], vh1[3]);
                    mma16816(o0, ph, vl0[0], vl0[1]);
                    mma16816(o1, ph, vl0[2], vl0[3]);
                    mma16816(o2, ph, vl1[0], vl1[1]);
                    mma16816(o3, ph, vl1[2], vl1[3]);
                    mma16816(o0, pl, vh0[0], vh0[1]);
                    mma16816(o1, pl, vh0[2], vh0[3]);
                    mma16816(o2, pl, vh1[0], vh1[1]);
                    mma16816(o3, pl, vh1[2], vh1[3]);
                }
            }
        }
        __syncthreads();
        if (kt + 2 <= ktmax)
            attn_load_kv(sb + 2 * AQ_B + (kt & 1) * AKV_B, tid,
                         Kh_, Kl_, Vh_, Vl_, krow0 + (size_t)(kt + 2) * 64, gcol);
    }

    const float i0 = 1.f / l_lo, i1 = 1.f / l_hi;
    const size_t row_lo = qrow0 + w * 16 + rl;
    const size_t row_hi = row_lo + 8;
    const int colb = h * DH + ((lane & 3) << 1);
    #pragma unroll
    for (int nt = 0; nt < 16; nt++) {
        int col = colb + nt * 8;
        uint32_t h0, l0, h1, l1;
        split_pack_h(o[nt][0] * i0, o[nt][1] * i0, h0, l0);
        split_pack_h(o[nt][2] * i1, o[nt][3] * i1, h1, l1);
        *(uint32_t*)&Yh_[row_lo * DD + col] = h0;
        *(uint32_t*)&Yl_[row_lo * DD + col] = l0;
        *(uint32_t*)&Yh_[row_hi * DD + col] = h1;
        *(uint32_t*)&Yl_[row_hi * DD + col] = l1;
    }
}

// ---------------------------------------------------------------------------
extern "C" void kernel_launch(void* const* d_in, const int* in_sizes, int n_in,
                              void* d_out, int out_size)
{
    (void)in_sizes; (void)n_in; (void)out_size;
    const float* X  = (const float*)d_in[0];
    const float* Wq = (const float*)d_in[1];
    const float* bq = (const float*)d_in[2];
    const float* Wk = (const float*)d_in[3];
    const float* bk = (const float*)d_in[4];
    const float* Wv = (const float*)d_in[5];
    const float* bv = (const float*)d_in[6];
    const float* Wo = (const float*)d_in[7];
    const float* bo = (const float*)d_in[8];
    float* out = (float*)d_out;

    __nv_bfloat16 *Xh, *Xl, *Wh, *Wl, *Qh, *Ql, *Kh, *Kl, *Vh, *Vl;
    __half *Wof, *Yh, *Yl;
    cudaGetSymbolAddress((void**)&Xh, g_X_hi);   cudaGetSymbolAddress((void**)&Xl, g_X_lo);
    cudaGetSymbolAddress((void**)&Wh, g_Wqkv_hi); cudaGetSymbolAddress((void**)&Wl, g_Wqkv_lo);
    cudaGetSymbolAddress((void**)&Qh, g_Q_hi);   cudaGetSymbolAddress((void**)&Ql, g_Q_lo);
    cudaGetSymbolAddress((void**)&Kh, g_K_hi);   cudaGetSymbolAddress((void**)&Kl, g_K_lo);
    cudaGetSymbolAddress((void**)&Vh, g_V_hi);   cudaGetSymbolAddress((void**)&Vl, g_V_lo);
    cudaGetSymbolAddress((void**)&Wof, g_Wo_f);
    cudaGetSymbolAddress((void**)&Yh, g_Y_h);    cudaGetSymbolAddress((void**)&Yl, g_Y_l);

    cudaFuncSetAttribute(gemm_qkv,
                         cudaFuncAttributeMaxDynamicSharedMemorySize, GEMM_SMEM);
    cudaFuncSetAttribute(gemm_f16,
                         cudaFuncAttributeMaxDynamicSharedMemorySize, GEMMF_SMEM);
    cudaFuncSetAttribute(attn_mma,
                         cudaFuncAttributeMaxDynamicSharedMemorySize, ATTN_SMEM);

    const int nXD = MTOT * DD / 4, nDD = DD * DD / 4, nKD = KVD * DD / 4;
    split_bf16<<<(nXD + 255) / 256, 256>>>(X,  Xh, Xl, nXD);
    split_bf16<<<(nDD + 255) / 256, 256>>>(Wq, Wh, Wl, nDD);
    split_bf16<<<(nKD + 255) / 256, 256>>>(Wk, Wh + (size_t)DD * DD,
                                               Wl + (size_t)DD * DD, nKD);
    split_bf16<<<(nKD + 255) / 256, 256>>>(Wv, Wh + (size_t)(DD + KVD) * DD,
                                               Wl + (size_t)(DD + KVD) * DD, nKD);
    conv_f16<<<(nDD + 255) / 256, 256>>>(Wo, Wof, nDD);

    // merged QKV projection (bf16 3-term)
    gemm_qkv<<<dim3(NQKV / 256, MTOT / 128), 256, GEMM_SMEM>>>(
        Xh, Xl, Wh, Wl, bq, bk, bv, Qh, Ql, Kh, Kl, Vh, Vl);

    // attention (bf16 3-term) -> Y fp16 hi/lo
    attn_mma<<<dim3(TT / 128, BB * HH), 256, ATTN_SMEM>>>(
        Qh, Ql, Kh, Kl, Vh, Vl, Yh, Yl);

    // O projection (fp16 2-product) -> fp32 out
    gemm_f16<<<dim3(DD / 256, MTOT / 128), 256, GEMMF_SMEM>>>(
        Yh, Yl, Wof, bo, out, DD, DD);
}

// round 10
// speedup vs baseline: 2.9364x; 1.2229x over previous
#include <cuda_runtime.h>
#include <cuda_bf16.h>
#include <cuda_fp16.h>
#include <cstdint>

#define BB   2
#define TT   2048
#define DD   4096
#define HH   32
#define GG   8
#define DH   128
#define KVD  (GG*DH)     /* 1024 */
#define NQKV (DD+2*KVD)  /* 6144 */
#define MTOT (BB*TT)     /* 4096 */

// fp16 operands for QKV projection (2-product scheme)
__device__ __half g_X_h16[(size_t)MTOT * DD], g_X_l16[(size_t)MTOT * DD];
__device__ __half g_Wqkv_f[(size_t)NQKV * DD];
// bf16 hi/lo attention inputs
__device__ __nv_bfloat16 g_Q_hi[(size_t)MTOT * DD],  g_Q_lo[(size_t)MTOT * DD];
__device__ __nv_bfloat16 g_K_hi[(size_t)MTOT * KVD], g_K_lo[(size_t)MTOT * KVD];
__device__ __nv_bfloat16 g_V_hi[(size_t)MTOT * KVD], g_V_lo[(size_t)MTOT * KVD];
// fp16 operands for O projection (2-product scheme)
__device__ __half g_Wo_f[(size_t)DD * DD];
__device__ __half g_Y_h[(size_t)MTOT * DD], g_Y_l[(size_t)MTOT * DD];

// ---------------------------------------------------------------------------
__device__ __forceinline__ uint32_t smem_u32(const void* p) {
    uint32_t a;
    asm("{ .reg .u64 t; cvta.to.shared.u64 t, %1; cvt.u32.u64 %0, t; }"
        : "=r"(a) : "l"(p));
    return a;
}
__device__ __forceinline__ void ldsm4(uint32_t& r0, uint32_t& r1, uint32_t& r2,
                                      uint32_t& r3, uint32_t addr) {
    asm volatile("ldmatrix.sync.aligned.m8n8.x4.shared.b16 {%0,%1,%2,%3}, [%4];"
                 : "=r"(r0), "=r"(r1), "=r"(r2), "=r"(r3) : "r"(addr));
}
__device__ __forceinline__ void ldsm4t(uint32_t& r0, uint32_t& r1, uint32_t& r2,
                                       uint32_t& r3, uint32_t addr) {
    asm volatile("ldmatrix.sync.aligned.m8n8.x4.trans.shared.b16 {%0,%1,%2,%3}, [%4];"
                 : "=r"(r0), "=r"(r1), "=r"(r2), "=r"(r3) : "r"(addr));
}
__device__ __forceinline__ void mma16816(float* c, const uint32_t* a,
                                         uint32_t b0, uint32_t b1) {
    asm volatile(
        "mma.sync.aligned.m16n8k16.row.col.f32.bf16.bf16.f32 "
        "{%0,%1,%2,%3}, {%4,%5,%6,%7}, {%8,%9}, {%0,%1,%2,%3};"
        : "+f"(c[0]), "+f"(c[1]), "+f"(c[2]), "+f"(c[3])
        : "r"(a[0]), "r"(a[1]), "r"(a[2]), "r"(a[3]), "r"(b0), "r"(b1));
}
__device__ __forceinline__ void mma16816h(float* c, const uint32_t* a,
                                          uint32_t b0, uint32_t b1) {
    asm volatile(
        "mma.sync.aligned.m16n8k16.row.col.f32.f16.f16.f32 "
        "{%0,%1,%2,%3}, {%4,%5,%6,%7}, {%8,%9}, {%0,%1,%2,%3};"
        : "+f"(c[0]), "+f"(c[1]), "+f"(c[2]), "+f"(c[3])
        : "r"(a[0]), "r"(a[1]), "r"(a[2]), "r"(a[3]), "r"(b0), "r"(b1));
}
__device__ __forceinline__ void cpasync16(uint32_t dst, const void* src) {
    asm volatile("cp.async.cg.shared.global [%0], [%1], 16;"
                 :: "r"(dst), "l"(src) : "memory");
}
#define CP_COMMIT() asm volatile("cp.async.commit_group;" ::: "memory")
#define CP_WAIT1()  asm volatile("cp.async.wait_group 1;" ::: "memory")
#define CP_WAIT0()  asm volatile("cp.async.wait_group 0;" ::: "memory")

__device__ __forceinline__ float ex2f(float x) {
    float y;
    asm("ex2.approx.ftz.f32 %0, %1;" : "=f"(y) : "f"(x));
    return y;
}
__device__ __forceinline__ void split_pack(float a, float b,
                                           uint32_t& h, uint32_t& l) {
    __nv_bfloat162 hb = __floats2bfloat162_rn(a, b);
    __nv_bfloat162 lb = __floats2bfloat162_rn(a - __low2float(hb),
                                              b - __high2float(hb));
    h = *reinterpret_cast<uint32_t*>(&hb);
    l = *reinterpret_cast<uint32_t*>(&lb);
}
__device__ __forceinline__ void split_pack_h(float a, float b,
                                             uint32_t& h, uint32_t& l) {
    __half2 hb = __floats2half2_rn(a, b);
    float2 bk = __half22float2(hb);
    __half2 lb = __floats2half2_rn(a - bk.x, b - bk.y);
    h = *reinterpret_cast<uint32_t*>(&hb);
    l = *reinterpret_cast<uint32_t*>(&lb);
}

// ---------------------------------------------------------------------------
// fp32 -> (fp16 hi, fp16 lo)
__global__ void split_f16(const float* __restrict__ x,
                          __half* __restrict__ hi,
                          __half* __restrict__ lo, int n4)
{
    int i = blockIdx.x * blockDim.x + threadIdx.x;
    if (i >= n4) return;
    float4 v = ((const float4*)x)[i];
    uint32_t h0, l0, h1, l1;
    split_pack_h(v.x, v.y, h0, l0);
    split_pack_h(v.z, v.w, h1, l1);
    ((uint32_t*)hi)[2 * i] = h0; ((uint32_t*)hi)[2 * i + 1] = h1;
    ((uint32_t*)lo)[2 * i] = l0; ((uint32_t*)lo)[2 * i + 1] = l1;
}
// fp32 -> fp16 (single)
__global__ void conv_f16(const float* __restrict__ x,
                         __half* __restrict__ y, int n4)
{
    int i = blockIdx.x * blockDim.x + threadIdx.x;
    if (i >= n4) return;
    float4 v = ((const float4*)x)[i];
    __half2 a = __floats2half2_rn(v.x, v.y);
    __half2 b = __floats2half2_rn(v.z, v.w);
    ((uint32_t*)y)[2 * i]     = *reinterpret_cast<uint32_t*>(&a);
    ((uint32_t*)y)[2 * i + 1] = *reinterpret_cast<uint32_t*>(&b);
}

// ---------------------------------------------------------------------------
// fp16 2-product GEMM mainloop pieces (shared by QKV and O projections).
// CTA tile 128x256, 8 warps 64x64, K-chunk 32.
// Smem stage: Ah[128][40] Al[128][40] B[256][40]  (fp16, 80 B rows)
// ---------------------------------------------------------------------------
#define GK      32
#define A16SUB  (128 * 80)              /* 10240 B */
#define B16SUB  (256 * 80)              /* 20480 B */
#define STAGE16 (2 * A16SUB + B16SUB)   /* 40960 B */
#define GEMMF_SMEM (2 * STAGE16)        /* 81920 B */

__device__ __forceinline__ void load_stage_f16(
    uint32_t sb, int tid, const __half* ah, const __half* al,
    const __half* b, int K, int k0)
{
    #pragma unroll
    for (int t = 0; t < 8; t++) {
        const int id = t * 256 + tid;         // 0..2047
        if (id < 1024) {                       // A hi/lo
            const int x = id & 511;
            const int r = x >> 2, cb = (x & 3) << 4;
            const __half* src = (id < 512 ? ah : al) + (size_t)r * K + k0 + (cb >> 1);
            cpasync16(sb + (id < 512 ? 0u : (uint32_t)A16SUB) + r * 80 + cb, src);
        } else {                               // B
            const int x = id - 1024;
            const int r = x >> 2, cb = (x & 3) << 4;
            cpasync16(sb + 2 * A16SUB + r * 80 + cb,
                      b + (size_t)r * K + k0 + (cb >> 1));
        }
    }
}

// mainloop body macro-ized via inline function computing acc
struct F16Frags { uint32_t ah[4][4], al[4][4], bh[4][4]; };

__device__ __forceinline__ void f16_chunk(
    float acc[4][8][4], uint32_t sb, int wm, int wn, int lane)
{
    const int a_row = lane & 15;
    const int a_kb  = (lane >> 4) << 4;
    const int b_row = (lane & 7) + ((lane >> 4) << 3);
    const int b_kb  = ((lane >> 3) & 1) << 4;
    #pragma unroll
    for (int ks = 0; ks < 2; ks++) {
        uint32_t ah[4][4], al[4][4], bh[4][4];
        #pragma unroll
        for (int mt = 0; mt < 4; mt++) {
            uint32_t ra = sb + (wm * 64 + mt * 16 + a_row) * 80
                        + ks * 32 + a_kb;
            ldsm4(ah[mt][0], ah[mt][1], ah[mt][2], ah[mt][3], ra);
            ldsm4(al[mt][0], al[mt][1], al[mt][2], al[mt][3], ra + A16SUB);
        }
        #pragma unroll
        for (int bt = 0; bt < 4; bt++) {
            uint32_t rb = sb + 2 * A16SUB
                        + (wn * 64 + bt * 16 + b_row) * 80
                        + ks * 32 + b_kb;
            ldsm4(bh[bt][0], bh[bt][1], bh[bt][2], bh[bt][3], rb);
        }
        #pragma unroll
        for (int bt = 0; bt < 4; bt++)
            #pragma unroll
            for (int mt = 0; mt < 4; mt++) {
                mma16816h(acc[mt][bt * 2],     ah[mt], bh[bt][0], bh[bt][1]);
                mma16816h(acc[mt][bt * 2 + 1], ah[mt], bh[bt][2], bh[bt][3]);
            }
        #pragma unroll
        for (int bt = 0; bt < 4; bt++)
            #pragma unroll
            for (int mt = 0; mt < 4; mt++) {
                mma16816h(acc[mt][bt * 2],     al[mt], bh[bt][0], bh[bt][1]);
                mma16816h(acc[mt][bt * 2 + 1], al[mt], bh[bt][2], bh[bt][3]);
            }
    }
}

// ---------------------------------------------------------------------------
// QKV projection (fp16 2-product) -> bf16 hi/lo outputs, routed per col tile
// ---------------------------------------------------------------------------
__global__ __launch_bounds__(256, 1) void gemm_qkv16(
    const __half* __restrict__ Ah, const __half* __restrict__ Al,
    const __half* __restrict__ B,
    const float* __restrict__ bq, const float* __restrict__ bk,
    const float* __restrict__ bv,
    __nv_bfloat16* __restrict__ Qh, __nv_bfloat16* __restrict__ Ql,
    __nv_bfloat16* __restrict__ Kh, __nv_bfloat16* __restrict__ Kl,
    __nv_bfloat16* __restrict__ Vh, __nv_bfloat16* __restrict__ Vl)
{
    extern __shared__ char sm_[];
    const uint32_t smem_base = smem_u32(sm_);
    const int tid  = threadIdx.x;
    const int wid  = tid >> 5;
    const int lane = tid & 31;
    const int wm   = wid >> 2;
    const int wn   = wid & 3;
    const int brow = blockIdx.y << 7;
    const int bcol = blockIdx.x << 8;
    const int K    = DD;

    __nv_bfloat16 *Ch, *Cl; const float* bias; int outN, obase;
    if (bcol < DD)            { Ch = Qh; Cl = Ql; bias = bq; outN = DD;  obase = bcol; }
    else if (bcol < DD + KVD) { Ch = Kh; Cl = Kl; bias = bk; outN = KVD; obase = bcol - DD; }
    else                      { Ch = Vh; Cl = Vl; bias = bv; outN = KVD; obase = bcol - DD - KVD; }

    const __half* pa = Ah + (size_t)brow * K;
    const __half* pl = Al + (size_t)brow * K;
    const __half* pb = B  + (size_t)bcol * K;

    float acc[4][8][4];
    #pragma unroll
    for (int i = 0; i < 4; i++)
        #pragma unroll
        for (int j = 0; j < 8; j++)
            #pragma unroll
            for (int k = 0; k < 4; k++) acc[i][j][k] = 0.f;

    const int nchunks = K / GK;

    load_stage_f16(smem_base, tid, pa, pl, pb, K, 0);            CP_COMMIT();
    load_stage_f16(smem_base + STAGE16, tid, pa, pl, pb, K, GK); CP_COMMIT();
    CP_WAIT1();
    __syncthreads();

    for (int chunk = 0; chunk < nchunks; chunk++) {
        f16_chunk(acc, smem_base + (chunk & 1) * STAGE16, wm, wn, lane);
        __syncthreads();
        if (chunk + 2 < nchunks) {
            load_stage_f16(smem_base + (chunk & 1) * STAGE16, tid, pa, pl, pb,
                           K, (chunk + 2) * GK);
            CP_COMMIT();
            CP_WAIT1();
            __syncthreads();
        } else if (chunk + 1 < nchunks) {
            CP_WAIT0();
            __syncthreads();
        }
    }

    const int crow = lane >> 2;
    const int ccol = (lane & 3) << 1;
    #pragma unroll
    for (int nt = 0; nt < 8; nt++) {
        const int col = obase + wn * 64 + nt * 8 + ccol;
        float b0 = __ldg(&bias[col]), b1 = __ldg(&bias[col + 1]);
        #pragma unroll
        for (int mt = 0; mt < 4; mt++) {
            size_t row0 = (size_t)(brow + wm * 64 + mt * 16 + crow);
            float x0 = acc[mt][nt][0] + b0, x1 = acc[mt][nt][1] + b1;
            float x2 = acc[mt][nt][2] + b0, x3 = acc[mt][nt][3] + b1;
            uint32_t h0, l0, h1, l1;
            split_pack(x0, x1, h0, l0);
            split_pack(x2, x3, h1, l1);
            *(uint32_t*)&Ch[row0 * outN + col]       = h0;
            *(uint32_t*)&Cl[row0 * outN + col]       = l0;
            *(uint32_t*)&Ch[(row0 + 8) * outN + col] = h1;
            *(uint32_t*)&Cl[(row0 + 8) * outN + col] = l1;
        }
    }
}

// ---------------------------------------------------------------------------
// O projection (fp16 2-product) -> fp32 out
// ---------------------------------------------------------------------------
__global__ __launch_bounds__(256, 1) void gemm_f16(
    const __half* __restrict__ Ah, const __half* __restrict__ Al,
    const __half* __restrict__ B,
    const float* __restrict__ bias, float* __restrict__ Cf, int N, int K)
{
    extern __shared__ char sm_[];
    const uint32_t smem_base = smem_u32(sm_);
    const int tid  = threadIdx.x;
    const int wid  = tid >> 5;
    const int lane = tid & 31;
    const int wm   = wid >> 2;
    const int wn   = wid & 3;
    const int brow = blockIdx.y << 7;
    const int bcol = blockIdx.x << 8;

    const __half* pa = Ah + (size_t)brow * K;
    const __half* pl = Al + (size_t)brow * K;
    const __half* pb = B  + (size_t)bcol * K;

    float acc[4][8][4];
    #pragma unroll
    for (int i = 0; i < 4; i++)
        #pragma unroll
        for (int j = 0; j < 8; j++)
            #pragma unroll
            for (int k = 0; k < 4; k++) acc[i][j][k] = 0.f;

    const int nchunks = K / GK;

    load_stage_f16(smem_base, tid, pa, pl, pb, K, 0);            CP_COMMIT();
    load_stage_f16(smem_base + STAGE16, tid, pa, pl, pb, K, GK); CP_COMMIT();
    CP_WAIT1();
    __syncthreads();

    for (int chunk = 0; chunk < nchunks; chunk++) {
        f16_chunk(acc, smem_base + (chunk & 1) * STAGE16, wm, wn, lane);
        __syncthreads();
        if (chunk + 2 < nchunks) {
            load_stage_f16(smem_base + (chunk & 1) * STAGE16, tid, pa, pl, pb,
                           K, (chunk + 2) * GK);
            CP_COMMIT();
            CP_WAIT1();
            __syncthreads();
        } else if (chunk + 1 < nchunks) {
            CP_WAIT0();
            __syncthreads();
        }
    }

    const int crow = lane >> 2;
    const int ccol = (lane & 3) << 1;
    #pragma unroll
    for (int nt = 0; nt < 8; nt++) {
        const int col = bcol + wn * 64 + nt * 8 + ccol;
        float b0 = __ldg(&bias[col]), b1 = __ldg(&bias[col + 1]);
        #pragma unroll
        for (int mt = 0; mt < 4; mt++) {
            size_t row0 = (size_t)(brow + wm * 64 + mt * 16 + crow);
            float2 v0 = { acc[mt][nt][0] + b0, acc[mt][nt][1] + b1 };
            float2 v1 = { acc[mt][nt][2] + b0, acc[mt][nt][3] + b1 };
            *(float2*)&Cf[row0 * N + col]       = v0;
            *(float2*)&Cf[(row0 + 8) * N + col] = v1;
        }
    }
}

// ---------------------------------------------------------------------------
// HMMA causal GQA flash attention (bf16 3-term); Y output as fp16 hi/lo.
// ---------------------------------------------------------------------------
#define ATSTR 272
#define AT64  (64 * ATSTR)
#define AQ_B  (128 * ATSTR)
#define AKV_B (4 * AT64)
#define ATTN_SMEM (2 * AQ_B + 2 * AKV_B)

__device__ __forceinline__ void attn_load_kv(
    uint32_t base, int tid,
    const __nv_bfloat16* __restrict__ Kh, const __nv_bfloat16* __restrict__ Kl,
    const __nv_bfloat16* __restrict__ Vh, const __nv_bfloat16* __restrict__ Vl,
    size_t grow0, int gcol)
{
    const __nv_bfloat16* srcs[4] = { Kh, Kl, Vh, Vl };
    #pragma unroll
    for (int t = 0; t < 4; t++) {
        const __nv_bfloat16* s = srcs[t] + grow0 * KVD + gcol;
        #pragma unroll
        for (int i = 0; i < 4; i++) {
            int ch = tid + i * 256;
            int r = ch >> 4, c = ch & 15;
            cpasync16(base + t * AT64 + r * ATSTR + c * 16,
                      s + (size_t)r * KVD + c * 8);
        }
    }
    CP_COMMIT();
}

__global__ __launch_bounds__(256, 1) void attn_mma(
    const __nv_bfloat16* __restrict__ Qh_, const __nv_bfloat16* __restrict__ Ql_,
    const __nv_bfloat16* __restrict__ Kh_, const __nv_bfloat16* __restrict__ Kl_,
    const __nv_bfloat16* __restrict__ Vh_, const __nv_bfloat16* __restrict__ Vl_,
    __half* __restrict__ Yh_, __half* __restrict__ Yl_)
{
    extern __shared__ char sm_[];
    const uint32_t sb = smem_u32(sm_);
    const int tid  = threadIdx.x;
    const int lane = tid & 31;
    const int w    = tid >> 5;
    const int qt   = (int)gridDim.x - 1 - (int)blockIdx.x;
    const int bh   = blockIdx.y;
    const int b    = bh >> 5, h = bh & 31, g = h >> 2;
    const int ktmax = 2 * qt + 1;
    const size_t qrow0 = (size_t)b * TT + (size_t)qt * 128;
    const size_t krow0 = (size_t)b * TT;
    const int gcol = g * DH;

    {
        const __nv_bfloat16* q0 = Qh_ + qrow0 * DD + h * DH;
        const __nv_bfloat16* q1 = Ql_ + qrow0 * DD + h * DH;
        #pragma unroll
        for (int i = 0; i < 8; i++) {
            int ch = tid + i * 256;
            int r = ch >> 4, c = ch & 15;
            cpasync16(sb + r * ATSTR + c * 16,        q0 + (size_t)r * DD + c * 8);
            cpasync16(sb + AQ_B + r * ATSTR + c * 16, q1 + (size_t)r * DD + c * 8);
        }
        CP_COMMIT();
    }
    attn_load_kv(sb + 2 * AQ_B, tid, Kh_, Kl_, Vh_, Vl_, krow0, gcol);
    attn_load_kv(sb + 2 * AQ_B + AKV_B, tid, Kh_, Kl_, Vh_, Vl_, krow0 + 64, gcol);

    float o[16][4];
    #pragma unroll
    for (int i = 0; i < 16; i++)
        #pragma unroll
        for (int j = 0; j < 4; j++) o[i][j] = 0.f;
    float m_lo = -1e30f, m_hi = -1e30f, l_lo = 0.f, l_hi = 0.f;

    const int wrow = qt * 128 + w * 16;
    const int rl   = lane >> 2;
    const float SC = 0.088388347648318447f * 1.4426950408889634f;

    for (int kt = 0; kt <= ktmax; kt++) {
        if (kt < ktmax) { CP_WAIT1(); } else { CP_WAIT0(); }
        __syncthreads();
        const uint32_t kb = sb + 2 * AQ_B + (kt & 1) * AKV_B;

        if (kt * 64 <= wrow + 15) {
            float s[8][4];
            #pragma unroll
            for (int j = 0; j < 8; j++)
                #pragma unroll
                for (int e = 0; e < 4; e++) s[j][e] = 0.f;

            #pragma unroll
            for (int ks = 0; ks < 8; ks++) {
                uint32_t qh[4], ql[4];
                uint32_t ra = sb + (w * 16 + (lane & 15)) * ATSTR
                            + ks * 32 + ((lane >> 4) << 4);
                ldsm4(qh[0], qh[1], qh[2], qh[3], ra);
                ldsm4(ql[0], ql[1], ql[2], ql[3], ra + AQ_B);
                uint32_t kh[4][4], kl[4][4];
                #pragma unroll
                for (int np = 0; np < 4; np++) {
                    uint32_t rb = kb
                        + (np * 16 + (lane & 7) + ((lane >> 4) << 3)) * ATSTR
                        + ks * 32 + (((lane >> 3) & 1) << 4);
                    ldsm4(kh[np][0], kh[np][1], kh[np][2], kh[np][3], rb);
                    ldsm4(kl[np][0], kl[np][1], kl[np][2], kl[np][3], rb + AT64);
                }
                #pragma unroll
                for (int np = 0; np < 4; np++) {
                    mma16816(s[2 * np],     qh, kh[np][0], kh[np][1]);
                    mma16816(s[2 * np + 1], qh, kh[np][2], kh[np][3]);
                }
                #pragma unroll
                for (int np = 0; np < 4; np++) {
                    mma16816(s[2 * np],     qh, kl[np][0], kl[np][1]);
                    mma16816(s[2 * np + 1], qh, kl[np][2], kl[np][3]);
                }
                #pragma unroll
                for (int np = 0; np < 4; np++) {
                    mma16816(s[2 * np],     ql, kh[np][0], kh[np][1]);
                    mma16816(s[2 * np + 1], ql, kh[np][2], kh[np][3]);
                }
            }

            #pragma unroll
            for (int j = 0; j < 8; j++)
                #pragma unroll
                for (int e = 0; e < 4; e++) s[j][e] *= SC;
            if (kt * 64 + 63 > wrow) {
                const int row_lo = wrow + rl, row_hi = row_lo + 8;
                #pragma unroll
                for (int j = 0; j < 8; j++) {
                    int c0 = kt * 64 + j * 8 + ((lane & 3) << 1);
                    if (c0 > row_lo)     s[j][0] = -1e30f;
                    if (c0 + 1 > row_lo) s[j][1] = -1e30f;
                    if (c0 > row_hi)     s[j][2] = -1e30f;
                    if (c0 + 1 > row_hi) s[j][3] = -1e30f;
                }
            }

            float mx0 = -1e30f, mx1 = -1e30f;
            #pragma unroll
            for (int j = 0; j < 8; j++) {
                mx0 = fmaxf(mx0, fmaxf(s[j][0], s[j][1]));
                mx1 = fmaxf(mx1, fmaxf(s[j][2], s[j][3]));
            }
            mx0 = fmaxf(mx0, __shfl_xor_sync(0xffffffffu, mx0, 1));
            mx0 = fmaxf(mx0, __shfl_xor_sync(0xffffffffu, mx0, 2));
            mx1 = fmaxf(mx1, __shfl_xor_sync(0xffffffffu, mx1, 1));
            mx1 = fmaxf(mx1, __shfl_xor_sync(0xffffffffu, mx1, 2));
            float mn0 = fmaxf(m_lo, mx0), mn1 = fmaxf(m_hi, mx1);
            float c0 = ex2f(m_lo - mn0), c1 = ex2f(m_hi - mn1);
            float su0 = 0.f, su1 = 0.f;
            #pragma unroll
            for (int j = 0; j < 8; j++) {
                s[j][0] = ex2f(s[j][0] - mn0);
                s[j][1] = ex2f(s[j][1] - mn0);
                s[j][2] = ex2f(s[j][2] - mn1);
                s[j][3] = ex2f(s[j][3] - mn1);
                su0 += s[j][0] + s[j][1];
                su1 += s[j][2] + s[j][3];
            }
            su0 += __shfl_xor_sync(0xffffffffu, su0, 1);
            su0 += __shfl_xor_sync(0xffffffffu, su0, 2);
            su1 += __shfl_xor_sync(0xffffffffu, su1, 1);
            su1 += __shfl_xor_sync(0xffffffffu, su1, 2);
            l_lo = l_lo * c0 + su0;  l_hi = l_hi * c1 + su1;
            m_lo = mn0;              m_hi = mn1;
            #pragma unroll
            for (int nt = 0; nt < 16; nt++) {
                o[nt][0] *= c0; o[nt][1] *= c0;
                o[nt][2] *= c1; o[nt][3] *= c1;
            }

            #pragma unroll
            for (int ks = 0; ks < 4; ks++) {
                uint32_t ph[4], pl[4];
                split_pack(s[2 * ks][0],     s[2 * ks][1],     ph[0], pl[0]);
                split_pack(s[2 * ks][2],     s[2 * ks][3],     ph[1], pl[1]);
                split_pack(s[2 * ks + 1][0], s[2 * ks + 1][1], ph[2], pl[2]);
                split_pack(s[2 * ks + 1][2], s[2 * ks + 1][3], ph[3], pl[3]);
                #pragma unroll
                for (int npp = 0; npp < 4; npp++) {
                    uint32_t vh0[4], vl0[4], vh1[4], vl1[4];
                    uint32_t rv = kb + 2 * AT64
                        + (ks * 16 + (lane & 15)) * ATSTR
                        + npp * 64 + ((lane >> 4) << 4);
                    ldsm4t(vh0[0], vh0[1], vh0[2], vh0[3], rv);
                    ldsm4t(vl0[0], vl0[1], vl0[2], vl0[3], rv + AT64);
                    ldsm4t(vh1[0], vh1[1], vh1[2], vh1[3], rv + 32);
                    ldsm4t(vl1[0], vl1[1], vl1[2], vl1[3], rv + 32 + AT64);
                    float* o0 = o[4 * npp];     float* o1 = o[4 * npp + 1];
                    float* o2 = o[4 * npp + 2]; float* o3 = o[4 * npp + 3];
                    mma16816(o0, ph, vh0[0], vh0[1]);
                    mma16816(o1, ph, vh0[2], vh0[3]);
                    mma16816(o2, ph, vh1[0], vh1[1]);
                    mma16816(o3, ph, vh1[2], vh1[3]);
                    mma16816(o0, ph, vl0[0], vl0[1]);
                    mma16816(o1, ph, vl0[2], vl0[3]);
                    mma16816(o2, ph, vl1[0], vl1[1]);
                    mma16816(o3, ph, vl1[2], vl1[3]);
                    mma16816(o0, pl, vh0[0], vh0[1]);
                    mma16816(o1, pl, vh0[2], vh0[3]);
                    mma16816(o2, pl, vh1[0], vh1[1]);
                    mma16816(o3, pl, vh1[2], vh1[3]);
                }
            }
        }
        __syncthreads();
        if (kt + 2 <= ktmax)
            attn_load_kv(sb + 2 * AQ_B + (kt & 1) * AKV_B, tid,
                         Kh_, Kl_, Vh_, Vl_, krow0 + (size_t)(kt + 2) * 64, gcol);
    }

    const float i0 = 1.f / l_lo, i1 = 1.f / l_hi;
    const size_t row_lo = qrow0 + w * 16 + rl;
    const size_t row_hi = row_lo + 8;
    const int colb = h * DH + ((lane & 3) << 1);
    #pragma unroll
    for (int nt = 0; nt < 16; nt++) {
        int col = colb + nt * 8;
        uint32_t h0, l0, h1, l1;
        split_pack_h(o[nt][0] * i0, o[nt][1] * i0, h0, l0);
        split_pack_h(o[nt][2] * i1, o[nt][3] * i1, h1, l1);
        *(uint32_t*)&Yh_[row_lo * DD + col] = h0;
        *(uint32_t*)&Yl_[row_lo * DD + col] = l0;
        *(uint32_t*)&Yh_[row_hi * DD + col] = h1;
        *(uint32_t*)&Yl_[row_hi * DD + col] = l1;
    }
}

// ---------------------------------------------------------------------------
extern "C" void kernel_launch(void* const* d_in, const int* in_sizes, int n_in,
                              void* d_out, int out_size)
{
    (void)in_sizes; (void)n_in; (void)out_size;
    const float* X  = (const float*)d_in[0];
    const float* Wq = (const float*)d_in[1];
    const float* bq = (const float*)d_in[2];
    const float* Wk = (const float*)d_in[3];
    const float* bk = (const float*)d_in[4];
    const float* Wv = (const float*)d_in[5];
    const float* bv = (const float*)d_in[6];
    const float* Wo = (const float*)d_in[7];
    const float* bo = (const float*)d_in[8];
    float* out = (float*)d_out;

    __half *Xh16, *Xl16, *Wqkvf, *Wof, *Yh, *Yl;
    __nv_bfloat16 *Qh, *Ql, *Kh, *Kl, *Vh, *Vl;
    cudaGetSymbolAddress((void**)&Xh16, g_X_h16);  cudaGetSymbolAddress((void**)&Xl16, g_X_l16);
    cudaGetSymbolAddress((void**)&Wqkvf, g_Wqkv_f);
    cudaGetSymbolAddress((void**)&Qh, g_Q_hi);   cudaGetSymbolAddress((void**)&Ql, g_Q_lo);
    cudaGetSymbolAddress((void**)&Kh, g_K_hi);   cudaGetSymbolAddress((void**)&Kl, g_K_lo);
    cudaGetSymbolAddress((void**)&Vh, g_V_hi);   cudaGetSymbolAddress((void**)&Vl, g_V_lo);
    cudaGetSymbolAddress((void**)&Wof, g_Wo_f);
    cudaGetSymbolAddress((void**)&Yh, g_Y_h);    cudaGetSymbolAddress((void**)&Yl, g_Y_l);

    cudaFuncSetAttribute(gemm_qkv16,
                         cudaFuncAttributeMaxDynamicSharedMemorySize, GEMMF_SMEM);
    cudaFuncSetAttribute(gemm_f16,
                         cudaFuncAttributeMaxDynamicSharedMemorySize, GEMMF_SMEM);
    cudaFuncSetAttribute(attn_mma,
                         cudaFuncAttributeMaxDynamicSharedMemorySize, ATTN_SMEM);

    const int nXD = MTOT * DD / 4, nDD = DD * DD / 4, nKD = KVD * DD / 4;
    split_f16<<<(nXD + 255) / 256, 256>>>(X, Xh16, Xl16, nXD);
    conv_f16<<<(nDD + 255) / 256, 256>>>(Wq, Wqkvf, nDD);
    conv_f16<<<(nKD + 255) / 256, 256>>>(Wk, Wqkvf + (size_t)DD * DD, nKD);
    conv_f16<<<(nKD + 255) / 256, 256>>>(Wv, Wqkvf + (size_t)(DD + KVD) * DD, nKD);
    conv_f16<<<(nDD + 255) / 256, 256>>>(Wo, Wof, nDD);

    // merged QKV projection (fp16 2-product) -> bf16 hi/lo
    gemm_qkv16<<<dim3(NQKV / 256, MTOT / 128), 256, GEMMF_SMEM>>>(
        Xh16, Xl16, Wqkvf, bq, bk, bv, Qh, Ql, Kh, Kl, Vh, Vl);

    // attention (bf16 3-term) -> Y fp16 hi/lo
    attn_mma<<<dim3(TT / 128, BB * HH), 256, ATTN_SMEM>>>(
        Qh, Ql, Kh, Kl, Vh, Vl, Yh, Yl);

    // O projection (fp16 2-product) -> fp32 out
    gemm_f16<<<dim3(DD / 256, MTOT / 128), 256, GEMMF_SMEM>>>(
        Yh, Yl, Wof, bo, out, DD, DD);
}

// round 11
// speedup vs baseline: 3.1762x; 1.0817x over previous
#include <cuda_runtime.h>
#include <cuda_bf16.h>
#include <cuda_fp16.h>
#include <cstdint>

#define BB   2
#define TT   2048
#define DD   4096
#define HH   32
#define GG   8
#define DH   128
#define KVD  (GG*DH)     /* 1024 */
#define NQKV (DD+2*KVD)  /* 6144 */
#define MTOT (BB*TT)     /* 4096 */

// fp16 operands
__device__ __half g_X_h16[(size_t)MTOT * DD], g_X_l16[(size_t)MTOT * DD];
__device__ __half g_Wqkv_f[(size_t)NQKV * DD];
__device__ __half g_Q_h16[(size_t)MTOT * DD], g_Q_l16[(size_t)MTOT * DD];
__device__ __half g_K_f[(size_t)MTOT * KVD];
__device__ __half g_V_f[(size_t)MTOT * KVD];
__device__ __half g_Wo_f[(size_t)DD * DD];
__device__ __half g_Y_h[(size_t)MTOT * DD], g_Y_l[(size_t)MTOT * DD];

// ---------------------------------------------------------------------------
__device__ __forceinline__ uint32_t smem_u32(const void* p) {
    uint32_t a;
    asm("{ .reg .u64 t; cvta.to.shared.u64 t, %1; cvt.u32.u64 %0, t; }"
        : "=r"(a) : "l"(p));
    return a;
}
__device__ __forceinline__ void ldsm4(uint32_t& r0, uint32_t& r1, uint32_t& r2,
                                      uint32_t& r3, uint32_t addr) {
    asm volatile("ldmatrix.sync.aligned.m8n8.x4.shared.b16 {%0,%1,%2,%3}, [%4];"
                 : "=r"(r0), "=r"(r1), "=r"(r2), "=r"(r3) : "r"(addr));
}
__device__ __forceinline__ void ldsm4t(uint32_t& r0, uint32_t& r1, uint32_t& r2,
                                       uint32_t& r3, uint32_t addr) {
    asm volatile("ldmatrix.sync.aligned.m8n8.x4.trans.shared.b16 {%0,%1,%2,%3}, [%4];"
                 : "=r"(r0), "=r"(r1), "=r"(r2), "=r"(r3) : "r"(addr));
}
__device__ __forceinline__ void mma16816h(float* c, const uint32_t* a,
                                          uint32_t b0, uint32_t b1) {
    asm volatile(
        "mma.sync.aligned.m16n8k16.row.col.f32.f16.f16.f32 "
        "{%0,%1,%2,%3}, {%4,%5,%6,%7}, {%8,%9}, {%0,%1,%2,%3};"
        : "+f"(c[0]), "+f"(c[1]), "+f"(c[2]), "+f"(c[3])
        : "r"(a[0]), "r"(a[1]), "r"(a[2]), "r"(a[3]), "r"(b0), "r"(b1));
}
__device__ __forceinline__ void cpasync16(uint32_t dst, const void* src) {
    asm volatile("cp.async.cg.shared.global [%0], [%1], 16;"
                 :: "r"(dst), "l"(src) : "memory");
}
#define CP_COMMIT() asm volatile("cp.async.commit_group;" ::: "memory")
#define CP_WAIT1()  asm volatile("cp.async.wait_group 1;" ::: "memory")
#define CP_WAIT0()  asm volatile("cp.async.wait_group 0;" ::: "memory")

__device__ __forceinline__ float ex2f(float x) {
    float y;
    asm("ex2.approx.ftz.f32 %0, %1;" : "=f"(y) : "f"(x));
    return y;
}
__device__ __forceinline__ void split_pack_h(float a, float b,
                                             uint32_t& h, uint32_t& l) {
    __half2 hb = __floats2half2_rn(a, b);
    float2 bk = __half22float2(hb);
    __half2 lb = __floats2half2_rn(a - bk.x, b - bk.y);
    h = *reinterpret_cast<uint32_t*>(&hb);
    l = *reinterpret_cast<uint32_t*>(&lb);
}

// ---------------------------------------------------------------------------
// fp32 -> (fp16 hi, fp16 lo)
__global__ void split_f16(const float* __restrict__ x,
                          __half* __restrict__ hi,
                          __half* __restrict__ lo, int n4)
{
    int i = blockIdx.x * blockDim.x + threadIdx.x;
    if (i >= n4) return;
    float4 v = ((const float4*)x)[i];
    uint32_t h0, l0, h1, l1;
    split_pack_h(v.x, v.y, h0, l0);
    split_pack_h(v.z, v.w, h1, l1);
    ((uint32_t*)hi)[2 * i] = h0; ((uint32_t*)hi)[2 * i + 1] = h1;
    ((uint32_t*)lo)[2 * i] = l0; ((uint32_t*)lo)[2 * i + 1] = l1;
}
// all four weights fp32 -> fp16 in one launch
__global__ void conv_f16_all(const float* __restrict__ wq,
                             const float* __restrict__ wk,
                             const float* __restrict__ wv,
                             const float* __restrict__ wo,
                             __half* __restrict__ qkv, __half* __restrict__ o)
{
    const int nDD = DD * DD / 4, nKD = KVD * DD / 4;
    int i = blockIdx.x * blockDim.x + threadIdx.x;
    const float* src; __half* dst; int j = i;
    if (j < nDD)                { src = wq; dst = qkv; }
    else if ((j -= nDD) < nKD)  { src = wk; dst = qkv + (size_t)DD * DD; }
    else if ((j -= nKD) < nKD)  { src = wv; dst = qkv + (size_t)(DD + KVD) * DD; }
    else if ((j -= nKD) < nDD)  { src = wo; dst = o; }
    else return;
    float4 v = ((const float4*)src)[j];
    __half2 a = __floats2half2_rn(v.x, v.y);
    __half2 b = __floats2half2_rn(v.z, v.w);
    ((uint32_t*)dst)[2 * j]     = *reinterpret_cast<uint32_t*>(&a);
    ((uint32_t*)dst)[2 * j + 1] = *reinterpret_cast<uint32_t*>(&b);
}

// ---------------------------------------------------------------------------
// fp16 2-product GEMM mainloop (shared by QKV and O projections).
// CTA tile 128x256, 8 warps 64x64, K-chunk 32.
// ---------------------------------------------------------------------------
#define GK      32
#define A16SUB  (128 * 80)
#define B16SUB  (256 * 80)
#define STAGE16 (2 * A16SUB + B16SUB)
#define GEMMF_SMEM (2 * STAGE16)

__device__ __forceinline__ void load_stage_f16(
    uint32_t sb, int tid, const __half* ah, const __half* al,
    const __half* b, int K, int k0)
{
    #pragma unroll
    for (int t = 0; t < 8; t++) {
        const int id = t * 256 + tid;
        if (id < 1024) {
            const int x = id & 511;
            const int r = x >> 2, cb = (x & 3) << 4;
            const __half* src = (id < 512 ? ah : al) + (size_t)r * K + k0 + (cb >> 1);
            cpasync16(sb + (id < 512 ? 0u : (uint32_t)A16SUB) + r * 80 + cb, src);
        } else {
            const int x = id - 1024;
            const int r = x >> 2, cb = (x & 3) << 4;
            cpasync16(sb + 2 * A16SUB + r * 80 + cb,
                      b + (size_t)r * K + k0 + (cb >> 1));
        }
    }
}

__device__ __forceinline__ void f16_chunk(
    float acc[4][8][4], uint32_t sb, int wm, int wn, int lane)
{
    const int a_row = lane & 15;
    const int a_kb  = (lane >> 4) << 4;
    const int b_row = (lane & 7) + ((lane >> 4) << 3);
    const int b_kb  = ((lane >> 3) & 1) << 4;
    #pragma unroll
    for (int ks = 0; ks < 2; ks++) {
        uint32_t ah[4][4], al[4][4], bh[4][4];
        #pragma unroll
        for (int mt = 0; mt < 4; mt++) {
            uint32_t ra = sb + (wm * 64 + mt * 16 + a_row) * 80
                        + ks * 32 + a_kb;
            ldsm4(ah[mt][0], ah[mt][1], ah[mt][2], ah[mt][3], ra);
            ldsm4(al[mt][0], al[mt][1], al[mt][2], al[mt][3], ra + A16SUB);
        }
        #pragma unroll
        for (int bt = 0; bt < 4; bt++) {
            uint32_t rb = sb + 2 * A16SUB
                        + (wn * 64 + bt * 16 + b_row) * 80
                        + ks * 32 + b_kb;
            ldsm4(bh[bt][0], bh[bt][1], bh[bt][2], bh[bt][3], rb);
        }
        #pragma unroll
        for (int bt = 0; bt < 4; bt++)
            #pragma unroll
            for (int mt = 0; mt < 4; mt++) {
                mma16816h(acc[mt][bt * 2],     ah[mt], bh[bt][0], bh[bt][1]);
                mma16816h(acc[mt][bt * 2 + 1], ah[mt], bh[bt][2], bh[bt][3]);
            }
        #pragma unroll
        for (int bt = 0; bt < 4; bt++)
            #pragma unroll
            for (int mt = 0; mt < 4; mt++) {
                mma16816h(acc[mt][bt * 2],     al[mt], bh[bt][0], bh[bt][1]);
                mma16816h(acc[mt][bt * 2 + 1], al[mt], bh[bt][2], bh[bt][3]);
            }
    }
}

// ---------------------------------------------------------------------------
// QKV projection: Q -> fp16 hi/lo; K,V -> single fp16
// ---------------------------------------------------------------------------
__global__ __launch_bounds__(256, 1) void gemm_qkv16(
    const __half* __restrict__ Ah, const __half* __restrict__ Al,
    const __half* __restrict__ B,
    const float* __restrict__ bq, const float* __restrict__ bk,
    const float* __restrict__ bv,
    __half* __restrict__ Qh, __half* __restrict__ Ql,
    __half* __restrict__ Kf, __half* __restrict__ Vf)
{
    extern __shared__ char sm_[];
    const uint32_t smem_base = smem_u32(sm_);
    const int tid  = threadIdx.x;
    const int wid  = tid >> 5;
    const int lane = tid & 31;
    const int wm   = wid >> 2;
    const int wn   = wid & 3;
    const int brow = blockIdx.y << 7;
    const int bcol = blockIdx.x << 8;
    const int K    = DD;

    __half *Ch, *Cl; const float* bias; int outN, obase;
    if (bcol < DD)            { Ch = Qh; Cl = Ql;      bias = bq; outN = DD;  obase = bcol; }
    else if (bcol < DD + KVD) { Ch = Kf; Cl = nullptr; bias = bk; outN = KVD; obase = bcol - DD; }
    else                      { Ch = Vf; Cl = nullptr; bias = bv; outN = KVD; obase = bcol - DD - KVD; }

    const __half* pa = Ah + (size_t)brow * K;
    const __half* pl = Al + (size_t)brow * K;
    const __half* pb = B  + (size_t)bcol * K;

    float acc[4][8][4];
    #pragma unroll
    for (int i = 0; i < 4; i++)
        #pragma unroll
        for (int j = 0; j < 8; j++)
            #pragma unroll
            for (int k = 0; k < 4; k++) acc[i][j][k] = 0.f;

    const int nchunks = K / GK;

    load_stage_f16(smem_base, tid, pa, pl, pb, K, 0);            CP_COMMIT();
    load_stage_f16(smem_base + STAGE16, tid, pa, pl, pb, K, GK); CP_COMMIT();
    CP_WAIT1();
    __syncthreads();

    for (int chunk = 0; chunk < nchunks; chunk++) {
        f16_chunk(acc, smem_base + (chunk & 1) * STAGE16, wm, wn, lane);
        __syncthreads();
        if (chunk + 2 < nchunks) {
            load_stage_f16(smem_base + (chunk & 1) * STAGE16, tid, pa, pl, pb,
                           K, (chunk + 2) * GK);
            CP_COMMIT();
            CP_WAIT1();
            __syncthreads();
        } else if (chunk + 1 < nchunks) {
            CP_WAIT0();
            __syncthreads();
        }
    }

    const int crow = lane >> 2;
    const int ccol = (lane & 3) << 1;
    #pragma unroll
    for (int nt = 0; nt < 8; nt++) {
        const int col = obase + wn * 64 + nt * 8 + ccol;
        float b0 = __ldg(&bias[col]), b1 = __ldg(&bias[col + 1]);
        #pragma unroll
        for (int mt = 0; mt < 4; mt++) {
            size_t row0 = (size_t)(brow + wm * 64 + mt * 16 + crow);
            float x0 = acc[mt][nt][0] + b0, x1 = acc[mt][nt][1] + b1;
            float x2 = acc[mt][nt][2] + b0, x3 = acc[mt][nt][3] + b1;
            if (Cl) {                       // Q: split fp16 hi/lo
                uint32_t h0, l0, h1, l1;
                split_pack_h(x0, x1, h0, l0);
                split_pack_h(x2, x3, h1, l1);
                *(uint32_t*)&Ch[row0 * outN + col]       = h0;
                *(uint32_t*)&Cl[row0 * outN + col]       = l0;
                *(uint32_t*)&Ch[(row0 + 8) * outN + col] = h1;
                *(uint32_t*)&Cl[(row0 + 8) * outN + col] = l1;
            } else {                        // K/V: single fp16
                __half2 v0 = __floats2half2_rn(x0, x1);
                __half2 v1 = __floats2half2_rn(x2, x3);
                *(uint32_t*)&Ch[row0 * outN + col]       = *reinterpret_cast<uint32_t*>(&v0);
                *(uint32_t*)&Ch[(row0 + 8) * outN + col] = *reinterpret_cast<uint32_t*>(&v1);
            }
        }
    }
}

// ---------------------------------------------------------------------------
// O projection (fp16 2-product) -> fp32 out
// ---------------------------------------------------------------------------
__global__ __launch_bounds__(256, 1) void gemm_f16(
    const __half* __restrict__ Ah, const __half* __restrict__ Al,
    const __half* __restrict__ B,
    const float* __restrict__ bias, float* __restrict__ Cf, int N, int K)
{
    extern __shared__ char sm_[];
    const uint32_t smem_base = smem_u32(sm_);
    const int tid  = threadIdx.x;
    const int wid  = tid >> 5;
    const int lane = tid & 31;
    const int wm   = wid >> 2;
    const int wn   = wid & 3;
    const int brow = blockIdx.y << 7;
    const int bcol = blockIdx.x << 8;

    const __half* pa = Ah + (size_t)brow * K;
    const __half* pl = Al + (size_t)brow * K;
    const __half* pb = B  + (size_t)bcol * K;

    float acc[4][8][4];
    #pragma unroll
    for (int i = 0; i < 4; i++)
        #pragma unroll
        for (int j = 0; j < 8; j++)
            #pragma unroll
            for (int k = 0; k < 4; k++) acc[i][j][k] = 0.f;

    const int nchunks = K / GK;

    load_stage_f16(smem_base, tid, pa, pl, pb, K, 0);            CP_COMMIT();
    load_stage_f16(smem_base + STAGE16, tid, pa, pl, pb, K, GK); CP_COMMIT();
    CP_WAIT1();
    __syncthreads();

    for (int chunk = 0; chunk < nchunks; chunk++) {
        f16_chunk(acc, smem_base + (chunk & 1) * STAGE16, wm, wn, lane);
        __syncthreads();
        if (chunk + 2 < nchunks) {
            load_stage_f16(smem_base + (chunk & 1) * STAGE16, tid, pa, pl, pb,
                           K, (chunk + 2) * GK);
            CP_COMMIT();
            CP_WAIT1();
            __syncthreads();
        } else if (chunk + 1 < nchunks) {
            CP_WAIT0();
            __syncthreads();
        }
    }

    const int crow = lane >> 2;
    const int ccol = (lane & 3) << 1;
    #pragma unroll
    for (int nt = 0; nt < 8; nt++) {
        const int col = bcol + wn * 64 + nt * 8 + ccol;
        float b0 = __ldg(&bias[col]), b1 = __ldg(&bias[col + 1]);
        #pragma unroll
        for (int mt = 0; mt < 4; mt++) {
            size_t row0 = (size_t)(brow + wm * 64 + mt * 16 + crow);
            float2 v0 = { acc[mt][nt][0] + b0, acc[mt][nt][1] + b1 };
            float2 v1 = { acc[mt][nt][2] + b0, acc[mt][nt][3] + b1 };
            *(float2*)&Cf[row0 * N + col]       = v0;
            *(float2*)&Cf[(row0 + 8) * N + col] = v1;
        }
    }
}

// ---------------------------------------------------------------------------
// fp16 2-product causal GQA flash attention.
// Q split fp16 hi/lo; K,V single fp16. Y out as fp16 hi/lo.
// SMEM: Qh|Ql (2x34816) + 2 x (K|V tiles, 2x17408) = 139264 B.
// ---------------------------------------------------------------------------
#define ATSTR 272
#define AT64  (64 * ATSTR)
#define AQ_B  (128 * ATSTR)
#define AKV_B (2 * AT64)
#define ATTN_SMEM (2 * AQ_B + 2 * AKV_B)   /* 139264 */

__device__ __forceinline__ void attn_load_kv(
    uint32_t base, int tid,
    const __half* __restrict__ Kf, const __half* __restrict__ Vf,
    size_t grow0, int gcol)
{
    const __half* srcs[2] = { Kf, Vf };
    #pragma unroll
    for (int t = 0; t < 2; t++) {
        const __half* s = srcs[t] + grow0 * KVD + gcol;
        #pragma unroll
        for (int i = 0; i < 4; i++) {
            int ch = tid + i * 256;
            int r = ch >> 4, c = ch & 15;
            cpasync16(base + t * AT64 + r * ATSTR + c * 16,
                      s + (size_t)r * KVD + c * 8);
        }
    }
    CP_COMMIT();
}

__global__ __launch_bounds__(256, 1) void attn_mma(
    const __half* __restrict__ Qh_, const __half* __restrict__ Ql_,
    const __half* __restrict__ Kf_, const __half* __restrict__ Vf_,
    __half* __restrict__ Yh_, __half* __restrict__ Yl_)
{
    extern __shared__ char sm_[];
    const uint32_t sb = smem_u32(sm_);
    const int tid  = threadIdx.x;
    const int lane = tid & 31;
    const int w    = tid >> 5;
    const int qt   = (int)gridDim.x - 1 - (int)blockIdx.x;
    const int bh   = blockIdx.y;
    const int b    = bh >> 5, h = bh & 31, g = h >> 2;
    const int ktmax = 2 * qt + 1;
    const size_t qrow0 = (size_t)b * TT + (size_t)qt * 128;
    const size_t krow0 = (size_t)b * TT;
    const int gcol = g * DH;

    {
        const __half* q0 = Qh_ + qrow0 * DD + h * DH;
        const __half* q1 = Ql_ + qrow0 * DD + h * DH;
        #pragma unroll
        for (int i = 0; i < 8; i++) {
            int ch = tid + i * 256;
            int r = ch >> 4, c = ch & 15;
            cpasync16(sb + r * ATSTR + c * 16,        q0 + (size_t)r * DD + c * 8);
            cpasync16(sb + AQ_B + r * ATSTR + c * 16, q1 + (size_t)r * DD + c * 8);
        }
        CP_COMMIT();
    }
    attn_load_kv(sb + 2 * AQ_B, tid, Kf_, Vf_, krow0, gcol);
    attn_load_kv(sb + 2 * AQ_B + AKV_B, tid, Kf_, Vf_, krow0 + 64, gcol);

    float o[16][4];
    #pragma unroll
    for (int i = 0; i < 16; i++)
        #pragma unroll
        for (int j = 0; j < 4; j++) o[i][j] = 0.f;
    float m_lo = -1e30f, m_hi = -1e30f, l_lo = 0.f, l_hi = 0.f;

    const int wrow = qt * 128 + w * 16;
    const int rl   = lane >> 2;
    const float SC = 0.088388347648318447f * 1.4426950408889634f;

    for (int kt = 0; kt <= ktmax; kt++) {
        if (kt < ktmax) { CP_WAIT1(); } else { CP_WAIT0(); }
        __syncthreads();
        const uint32_t kb = sb + 2 * AQ_B + (kt & 1) * AKV_B;

        if (kt * 64 <= wrow + 15) {
            float s[8][4];
            #pragma unroll
            for (int j = 0; j < 8; j++)
                #pragma unroll
                for (int e = 0; e < 4; e++) s[j][e] = 0.f;

            // ---- S = Q K^T (Qhi·K then Qlo·K) ----
            #pragma unroll
            for (int ks = 0; ks < 8; ks++) {
                uint32_t qh[4], ql[4];
                uint32_t ra = sb + (w * 16 + (lane & 15)) * ATSTR
                            + ks * 32 + ((lane >> 4) << 4);
                ldsm4(qh[0], qh[1], qh[2], qh[3], ra);
                ldsm4(ql[0], ql[1], ql[2], ql[3], ra + AQ_B);
                uint32_t kf[4][4];
                #pragma unroll
                for (int np = 0; np < 4; np++) {
                    uint32_t rb = kb
                        + (np * 16 + (lane & 7) + ((lane >> 4) << 3)) * ATSTR
                        + ks * 32 + (((lane >> 3) & 1) << 4);
                    ldsm4(kf[np][0], kf[np][1], kf[np][2], kf[np][3], rb);
                }
                #pragma unroll
                for (int np = 0; np < 4; np++) {
                    mma16816h(s[2 * np],     qh, kf[np][0], kf[np][1]);
                    mma16816h(s[2 * np + 1], qh, kf[np][2], kf[np][3]);
                }
                #pragma unroll
                for (int np = 0; np < 4; np++) {
                    mma16816h(s[2 * np],     ql, kf[np][0], kf[np][1]);
                    mma16816h(s[2 * np + 1], ql, kf[np][2], kf[np][3]);
                }
            }

            #pragma unroll
            for (int j = 0; j < 8; j++)
                #pragma unroll
                for (int e = 0; e < 4; e++) s[j][e] *= SC;
            if (kt * 64 + 63 > wrow) {
                const int row_lo = wrow + rl, row_hi = row_lo + 8;
                #pragma unroll
                for (int j = 0; j < 8; j++) {
                    int c0 = kt * 64 + j * 8 + ((lane & 3) << 1);
                    if (c0 > row_lo)     s[j][0] = -1e30f;
                    if (c0 + 1 > row_lo) s[j][1] = -1e30f;
                    if (c0 > row_hi)     s[j][2] = -1e30f;
                    if (c0 + 1 > row_hi) s[j][3] = -1e30f;
                }
            }

            float mx0 = -1e30f, mx1 = -1e30f;
            #pragma unroll
            for (int j = 0; j < 8; j++) {
                mx0 = fmaxf(mx0, fmaxf(s[j][0], s[j][1]));
                mx1 = fmaxf(mx1, fmaxf(s[j][2], s[j][3]));
            }
            mx0 = fmaxf(mx0, __shfl_xor_sync(0xffffffffu, mx0, 1));
            mx0 = fmaxf(mx0, __shfl_xor_sync(0xffffffffu, mx0, 2));
            mx1 = fmaxf(mx1, __shfl_xor_sync(0xffffffffu, mx1, 1));
            mx1 = fmaxf(mx1, __shfl_xor_sync(0xffffffffu, mx1, 2));
            float mn0 = fmaxf(m_lo, mx0), mn1 = fmaxf(m_hi, mx1);
            float c0 = ex2f(m_lo - mn0), c1 = ex2f(m_hi - mn1);
            float su0 = 0.f, su1 = 0.f;
            #pragma unroll
            for (int j = 0; j < 8; j++) {
                s[j][0] = ex2f(s[j][0] - mn0);
                s[j][1] = ex2f(s[j][1] - mn0);
                s[j][2] = ex2f(s[j][2] - mn1);
                s[j][3] = ex2f(s[j][3] - mn1);
                su0 += s[j][0] + s[j][1];
                su1 += s[j][2] + s[j][3];
            }
            su0 += __shfl_xor_sync(0xffffffffu, su0, 1);
            su0 += __shfl_xor_sync(0xffffffffu, su0, 2);
            su1 += __shfl_xor_sync(0xffffffffu, su1, 1);
            su1 += __shfl_xor_sync(0xffffffffu, su1, 2);
            l_lo = l_lo * c0 + su0;  l_hi = l_hi * c1 + su1;
            m_lo = mn0;              m_hi = mn1;
            #pragma unroll
            for (int nt = 0; nt < 16; nt++) {
                o[nt][0] *= c0; o[nt][1] *= c0;
                o[nt][2] *= c1; o[nt][3] *= c1;
            }

            // ---- O += P V (Phi·V then Plo·V) ----
            #pragma unroll
            for (int ks = 0; ks < 4; ks++) {
                uint32_t ph[4], pl[4];
                split_pack_h(s[2 * ks][0],     s[2 * ks][1],     ph[0], pl[0]);
                split_pack_h(s[2 * ks][2],     s[2 * ks][3],     ph[1], pl[1]);
                split_pack_h(s[2 * ks + 1][0], s[2 * ks + 1][1], ph[2], pl[2]);
                split_pack_h(s[2 * ks + 1][2], s[2 * ks + 1][3], ph[3], pl[3]);
                #pragma unroll
                for (int npp = 0; npp < 4; npp++) {
                    uint32_t vh0[4], vh1[4];
                    uint32_t rv = kb + AT64
                        + (ks * 16 + (lane & 15)) * ATSTR
                        + npp * 64 + ((lane >> 4) << 4);
                    ldsm4t(vh0[0], vh0[1], vh0[2], vh0[3], rv);
                    ldsm4t(vh1[0], vh1[1], vh1[2], vh1[3], rv + 32);
                    float* o0 = o[4 * npp];     float* o1 = o[4 * npp + 1];
                    float* o2 = o[4 * npp + 2]; float* o3 = o[4 * npp + 3];
                    mma16816h(o0, ph, vh0[0], vh0[1]);
                    mma16816h(o1, ph, vh0[2], vh0[3]);
                    mma16816h(o2, ph, vh1[0], vh1[1]);
                    mma16816h(o3, ph, vh1[2], vh1[3]);
                    mma16816h(o0, pl, vh0[0], vh0[1]);
                    mma16816h(o1, pl, vh0[2], vh0[3]);
                    mma16816h(o2, pl, vh1[0], vh1[1]);
                    mma16816h(o3, pl, vh1[2], vh1[3]);
                }
            }
        }
        __syncthreads();
        if (kt + 2 <= ktmax)
            attn_load_kv(sb + 2 * AQ_B + (kt & 1) * AKV_B, tid,
                         Kf_, Vf_, krow0 + (size_t)(kt + 2) * 64, gcol);
    }

    const float i0 = 1.f / l_lo, i1 = 1.f / l_hi;
    const size_t row_lo = qrow0 + w * 16 + rl;
    const size_t row_hi = row_lo + 8;
    const int colb = h * DH + ((lane & 3) << 1);
    #pragma unroll
    for (int nt = 0; nt < 16; nt++) {
        int col = colb + nt * 8;
        uint32_t h0, l0, h1, l1;
        split_pack_h(o[nt][0] * i0, o[nt][1] * i0, h0, l0);
        split_pack_h(o[nt][2] * i1, o[nt][3] * i1, h1, l1);
        *(uint32_t*)&Yh_[row_lo * DD + col] = h0;
        *(uint32_t*)&Yl_[row_lo * DD + col] = l0;
        *(uint32_t*)&Yh_[row_hi * DD + col] = h1;
        *(uint32_t*)&Yl_[row_hi * DD + col] = l1;
    }
}

// ---------------------------------------------------------------------------
extern "C" void kernel_launch(void* const* d_in, const int* in_sizes, int n_in,
                              void* d_out, int out_size)
{
    (void)in_sizes; (void)n_in; (void)out_size;
    const float* X  = (const float*)d_in[0];
    const float* Wq = (const float*)d_in[1];
    const float* bq = (const float*)d_in[2];
    const float* Wk = (const float*)d_in[3];
    const float* bk = (const float*)d_in[4];
    const float* Wv = (const float*)d_in[5];
    const float* bv = (const float*)d_in[6];
    const float* Wo = (const float*)d_in[7];
    const float* bo = (const float*)d_in[8];
    float* out = (float*)d_out;

    __half *Xh16, *Xl16, *Wqkvf, *Wof, *Yh, *Yl, *Qh, *Ql, *Kf, *Vf;
    cudaGetSymbolAddress((void**)&Xh16, g_X_h16);  cudaGetSymbolAddress((void**)&Xl16, g_X_l16);
    cudaGetSymbolAddress((void**)&Wqkvf, g_Wqkv_f);
    cudaGetSymbolAddress((void**)&Qh, g_Q_h16);   cudaGetSymbolAddress((void**)&Ql, g_Q_l16);
    cudaGetSymbolAddress((void**)&Kf, g_K_f);     cudaGetSymbolAddress((void**)&Vf, g_V_f);
    cudaGetSymbolAddress((void**)&Wof, g_Wo_f);
    cudaGetSymbolAddress((void**)&Yh, g_Y_h);     cudaGetSymbolAddress((void**)&Yl, g_Y_l);

    cudaFuncSetAttribute(gemm_qkv16,
                         cudaFuncAttributeMaxDynamicSharedMemorySize, GEMMF_SMEM);
    cudaFuncSetAttribute(gemm_f16,
                         cudaFuncAttributeMaxDynamicSharedMemorySize, GEMMF_SMEM);
    cudaFuncSetAttribute(attn_mma,
                         cudaFuncAttributeMaxDynamicSharedMemorySize, ATTN_SMEM);

    const int nXD = MTOT * DD / 4;
    const int nW  = (2 * DD * DD + 2 * KVD * DD) / 4;
    split_f16<<<(nXD + 255) / 256, 256>>>(X, Xh16, Xl16, nXD);
    conv_f16_all<<<(nW + 255) / 256, 256>>>(Wq, Wk, Wv, Wo, Wqkvf, Wof);

    // merged QKV projection (fp16 2-product)
    gemm_qkv16<<<dim3(NQKV / 256, MTOT / 128), 256, GEMMF_SMEM>>>(
        Xh16, Xl16, Wqkvf, bq, bk, bv, Qh, Ql, Kf, Vf);

    // attention (fp16 2-product) -> Y fp16 hi/lo
    attn_mma<<<dim3(TT / 128, BB * HH), 256, ATTN_SMEM>>>(
        Qh, Ql, Kf, Vf, Yh, Yl);

    // O projection (fp16 2-product) -> fp32 out
    gemm_f16<<<dim3(DD / 256, MTOT / 128), 256, GEMMF_SMEM>>>(
        Yh, Yl, Wof, bo, out, DD, DD);
}

// round 12
// speedup vs baseline: 3.5576x; 1.1201x over previous
#include <cuda_runtime.h>
#include <cuda_bf16.h>
#include <cuda_fp16.h>
#include <cstdint>

#define BB   2
#define TT   2048
#define DD   4096
#define HH   32
#define GG   8
#define DH   128
#define KVD  (GG*DH)     /* 1024 */
#define NQKV (DD+2*KVD)  /* 6144 */
#define MTOT (BB*TT)     /* 4096 */

// fp16 operands
__device__ __half g_X_h16[(size_t)MTOT * DD], g_X_l16[(size_t)MTOT * DD];
__device__ __half g_Wqkv_f[(size_t)NQKV * DD];
__device__ __half g_Q_h16[(size_t)MTOT * DD], g_Q_l16[(size_t)MTOT * DD];
__device__ __half g_K_f[(size_t)MTOT * KVD];
__device__ __half g_V_f[(size_t)MTOT * KVD];
__device__ __half g_Wo_f[(size_t)DD * DD];
__device__ __half g_Y_h[(size_t)MTOT * DD], g_Y_l[(size_t)MTOT * DD];

// ---------------------------------------------------------------------------
__device__ __forceinline__ uint32_t smem_u32(const void* p) {
    uint32_t a;
    asm("{ .reg .u64 t; cvta.to.shared.u64 t, %1; cvt.u32.u64 %0, t; }"
        : "=r"(a) : "l"(p));
    return a;
}
__device__ __forceinline__ void ldsm4(uint32_t& r0, uint32_t& r1, uint32_t& r2,
                                      uint32_t& r3, uint32_t addr) {
    asm volatile("ldmatrix.sync.aligned.m8n8.x4.shared.b16 {%0,%1,%2,%3}, [%4];"
                 : "=r"(r0), "=r"(r1), "=r"(r2), "=r"(r3) : "r"(addr));
}
__device__ __forceinline__ void ldsm4t(uint32_t& r0, uint32_t& r1, uint32_t& r2,
                                       uint32_t& r3, uint32_t addr) {
    asm volatile("ldmatrix.sync.aligned.m8n8.x4.trans.shared.b16 {%0,%1,%2,%3}, [%4];"
                 : "=r"(r0), "=r"(r1), "=r"(r2), "=r"(r3) : "r"(addr));
}
__device__ __forceinline__ void mma16816h(float* c, const uint32_t* a,
                                          uint32_t b0, uint32_t b1) {
    asm volatile(
        "mma.sync.aligned.m16n8k16.row.col.f32.f16.f16.f32 "
        "{%0,%1,%2,%3}, {%4,%5,%6,%7}, {%8,%9}, {%0,%1,%2,%3};"
        : "+f"(c[0]), "+f"(c[1]), "+f"(c[2]), "+f"(c[3])
        : "r"(a[0]), "r"(a[1]), "r"(a[2]), "r"(a[3]), "r"(b0), "r"(b1));
}
__device__ __forceinline__ void cpasync16(uint32_t dst, const void* src) {
    asm volatile("cp.async.cg.shared.global [%0], [%1], 16;"
                 :: "r"(dst), "l"(src) : "memory");
}
#define CP_COMMIT() asm volatile("cp.async.commit_group;" ::: "memory")
#define CP_WAIT1()  asm volatile("cp.async.wait_group 1;" ::: "memory")
#define CP_WAIT0()  asm volatile("cp.async.wait_group 0;" ::: "memory")

__device__ __forceinline__ float ex2f(float x) {
    float y;
    asm("ex2.approx.ftz.f32 %0, %1;" : "=f"(y) : "f"(x));
    return y;
}
__device__ __forceinline__ void split_pack_h(float a, float b,
                                             uint32_t& h, uint32_t& l) {
    __half2 hb = __floats2half2_rn(a, b);
    float2 bk = __half22float2(hb);
    __half2 lb = __floats2half2_rn(a - bk.x, b - bk.y);
    h = *reinterpret_cast<uint32_t*>(&hb);
    l = *reinterpret_cast<uint32_t*>(&lb);
}

// ---------------------------------------------------------------------------
__global__ void split_f16(const float* __restrict__ x,
                          __half* __restrict__ hi,
                          __half* __restrict__ lo, int n4)
{
    int i = blockIdx.x * blockDim.x + threadIdx.x;
    if (i >= n4) return;
    float4 v = ((const float4*)x)[i];
    uint32_t h0, l0, h1, l1;
    split_pack_h(v.x, v.y, h0, l0);
    split_pack_h(v.z, v.w, h1, l1);
    ((uint32_t*)hi)[2 * i] = h0; ((uint32_t*)hi)[2 * i + 1] = h1;
    ((uint32_t*)lo)[2 * i] = l0; ((uint32_t*)lo)[2 * i + 1] = l1;
}
__global__ void conv_f16_all(const float* __restrict__ wq,
                             const float* __restrict__ wk,
                             const float* __restrict__ wv,
                             const float* __restrict__ wo,
                             __half* __restrict__ qkv, __half* __restrict__ o)
{
    const int nDD = DD * DD / 4, nKD = KVD * DD / 4;
    int i = blockIdx.x * blockDim.x + threadIdx.x;
    const float* src; __half* dst; int j = i;
    if (j < nDD)                { src = wq; dst = qkv; }
    else if ((j -= nDD) < nKD)  { src = wk; dst = qkv + (size_t)DD * DD; }
    else if ((j -= nKD) < nKD)  { src = wv; dst = qkv + (size_t)(DD + KVD) * DD; }
    else if ((j -= nKD) < nDD)  { src = wo; dst = o; }
    else return;
    float4 v = ((const float4*)src)[j];
    __half2 a = __floats2half2_rn(v.x, v.y);
    __half2 b = __floats2half2_rn(v.z, v.w);
    ((uint32_t*)dst)[2 * j]     = *reinterpret_cast<uint32_t*>(&a);
    ((uint32_t*)dst)[2 * j + 1] = *reinterpret_cast<uint32_t*>(&b);
}

// ---------------------------------------------------------------------------
// fp16 2-product GEMM: CTA tile 64x256, 8 warps of 32x64, K-chunk 32.
// 2 CTAs/SM (smem 60 KB, <=128 regs).
// ---------------------------------------------------------------------------
#define GK      32
#define A16SUB  (64 * 80)               /* 5120 B  */
#define B16SUB  (256 * 80)              /* 20480 B */
#define STAGE16 (2 * A16SUB + B16SUB)   /* 30720 B */
#define GEMMF_SMEM (2 * STAGE16)        /* 61440 B */

__device__ __forceinline__ void load_stage_f16(
    uint32_t sb, int tid, const __half* ah, const __half* al,
    const __half* b, int K, int k0)
{
    #pragma unroll
    for (int t = 0; t < 6; t++) {
        const int id = t * 256 + tid;          // 0..1535
        if (id < 512) {                         // A hi/lo: 64 rows x 32 cols
            const int x = id & 255;
            const int r = x >> 2, cb = (x & 3) << 4;
            const __half* src = (id < 256 ? ah : al) + (size_t)r * K + k0 + (cb >> 1);
            cpasync16(sb + (id < 256 ? 0u : (uint32_t)A16SUB) + r * 80 + cb, src);
        } else {                                // B: 256 rows x 32 cols
            const int x = id - 512;
            const int r = x >> 2, cb = (x & 3) << 4;
            cpasync16(sb + 2 * A16SUB + r * 80 + cb,
                      b + (size_t)r * K + k0 + (cb >> 1));
        }
    }
}

__device__ __forceinline__ void f16_chunk(
    float acc[2][8][4], uint32_t sb, int wm, int wn, int lane)
{
    const int a_row = lane & 15;
    const int a_kb  = (lane >> 4) << 4;
    const int b_row = (lane & 7) + ((lane >> 4) << 3);
    const int b_kb  = ((lane >> 3) & 1) << 4;
    #pragma unroll
    for (int ks = 0; ks < 2; ks++) {
        uint32_t ah[2][4], al[2][4], bh[4][4];
        #pragma unroll
        for (int mt = 0; mt < 2; mt++) {
            uint32_t ra = sb + (wm * 32 + mt * 16 + a_row) * 80
                        + ks * 32 + a_kb;
            ldsm4(ah[mt][0], ah[mt][1], ah[mt][2], ah[mt][3], ra);
            ldsm4(al[mt][0], al[mt][1], al[mt][2], al[mt][3], ra + A16SUB);
        }
        #pragma unroll
        for (int bt = 0; bt < 4; bt++) {
            uint32_t rb = sb + 2 * A16SUB
                        + (wn * 64 + bt * 16 + b_row) * 80
                        + ks * 32 + b_kb;
            ldsm4(bh[bt][0], bh[bt][1], bh[bt][2], bh[bt][3], rb);
        }
        #pragma unroll
        for (int bt = 0; bt < 4; bt++)
            #pragma unroll
            for (int mt = 0; mt < 2; mt++) {
                mma16816h(acc[mt][bt * 2],     ah[mt], bh[bt][0], bh[bt][1]);
                mma16816h(acc[mt][bt * 2 + 1], ah[mt], bh[bt][2], bh[bt][3]);
            }
        #pragma unroll
        for (int bt = 0; bt < 4; bt++)
            #pragma unroll
            for (int mt = 0; mt < 2; mt++) {
                mma16816h(acc[mt][bt * 2],     al[mt], bh[bt][0], bh[bt][1]);
                mma16816h(acc[mt][bt * 2 + 1], al[mt], bh[bt][2], bh[bt][3]);
            }
    }
}

// ---------------------------------------------------------------------------
// QKV projection: Q -> fp16 hi/lo; K,V -> single fp16
// ---------------------------------------------------------------------------
__global__ __launch_bounds__(256, 2) void gemm_qkv16(
    const __half* __restrict__ Ah, const __half* __restrict__ Al,
    const __half* __restrict__ B,
    const float* __restrict__ bq, const float* __restrict__ bk,
    const float* __restrict__ bv,
    __half* __restrict__ Qh, __half* __restrict__ Ql,
    __half* __restrict__ Kf, __half* __restrict__ Vf)
{
    extern __shared__ char sm_[];
    const uint32_t smem_base = smem_u32(sm_);
    const int tid  = threadIdx.x;
    const int wid  = tid >> 5;
    const int lane = tid & 31;
    const int wm   = wid >> 2;
    const int wn   = wid & 3;
    const int brow = blockIdx.y << 6;      // 64 rows
    const int bcol = blockIdx.x << 8;
    const int K    = DD;

    __half *Ch, *Cl; const float* bias; int outN, obase;
    if (bcol < DD)            { Ch = Qh; Cl = Ql;      bias = bq; outN = DD;  obase = bcol; }
    else if (bcol < DD + KVD) { Ch = Kf; Cl = nullptr; bias = bk; outN = KVD; obase = bcol - DD; }
    else                      { Ch = Vf; Cl = nullptr; bias = bv; outN = KVD; obase = bcol - DD - KVD; }

    const __half* pa = Ah + (size_t)brow * K;
    const __half* pl = Al + (size_t)brow * K;
    const __half* pb = B  + (size_t)bcol * K;

    float acc[2][8][4];
    #pragma unroll
    for (int i = 0; i < 2; i++)
        #pragma unroll
        for (int j = 0; j < 8; j++)
            #pragma unroll
            for (int k = 0; k < 4; k++) acc[i][j][k] = 0.f;

    const int nchunks = K / GK;

    load_stage_f16(smem_base, tid, pa, pl, pb, K, 0);            CP_COMMIT();
    load_stage_f16(smem_base + STAGE16, tid, pa, pl, pb, K, GK); CP_COMMIT();
    CP_WAIT1();
    __syncthreads();

    for (int chunk = 0; chunk < nchunks; chunk++) {
        f16_chunk(acc, smem_base + (chunk & 1) * STAGE16, wm, wn, lane);
        __syncthreads();
        if (chunk + 2 < nchunks) {
            load_stage_f16(smem_base + (chunk & 1) * STAGE16, tid, pa, pl, pb,
                           K, (chunk + 2) * GK);
            CP_COMMIT();
            CP_WAIT1();
            __syncthreads();
        } else if (chunk + 1 < nchunks) {
            CP_WAIT0();
            __syncthreads();
        }
    }

    const int crow = lane >> 2;
    const int ccol = (lane & 3) << 1;
    #pragma unroll
    for (int nt = 0; nt < 8; nt++) {
        const int col = obase + wn * 64 + nt * 8 + ccol;
        float b0 = __ldg(&bias[col]), b1 = __ldg(&bias[col + 1]);
        #pragma unroll
        for (int mt = 0; mt < 2; mt++) {
            size_t row0 = (size_t)(brow + wm * 32 + mt * 16 + crow);
            float x0 = acc[mt][nt][0] + b0, x1 = acc[mt][nt][1] + b1;
            float x2 = acc[mt][nt][2] + b0, x3 = acc[mt][nt][3] + b1;
            if (Cl) {
                uint32_t h0, l0, h1, l1;
                split_pack_h(x0, x1, h0, l0);
                split_pack_h(x2, x3, h1, l1);
                *(uint32_t*)&Ch[row0 * outN + col]       = h0;
                *(uint32_t*)&Cl[row0 * outN + col]       = l0;
                *(uint32_t*)&Ch[(row0 + 8) * outN + col] = h1;
                *(uint32_t*)&Cl[(row0 + 8) * outN + col] = l1;
            } else {
                __half2 v0 = __floats2half2_rn(x0, x1);
                __half2 v1 = __floats2half2_rn(x2, x3);
                *(uint32_t*)&Ch[row0 * outN + col]       = *reinterpret_cast<uint32_t*>(&v0);
                *(uint32_t*)&Ch[(row0 + 8) * outN + col] = *reinterpret_cast<uint32_t*>(&v1);
            }
        }
    }
}

// ---------------------------------------------------------------------------
// O projection (fp16 2-product) -> fp32 out
// ---------------------------------------------------------------------------
__global__ __launch_bounds__(256, 2) void gemm_f16(
    const __half* __restrict__ Ah, const __half* __restrict__ Al,
    const __half* __restrict__ B,
    const float* __restrict__ bias, float* __restrict__ Cf, int N, int K)
{
    extern __shared__ char sm_[];
    const uint32_t smem_base = smem_u32(sm_);
    const int tid  = threadIdx.x;
    const int wid  = tid >> 5;
    const int lane = tid & 31;
    const int wm   = wid >> 2;
    const int wn   = wid & 3;
    const int brow = blockIdx.y << 6;
    const int bcol = blockIdx.x << 8;

    const __half* pa = Ah + (size_t)brow * K;
    const __half* pl = Al + (size_t)brow * K;
    const __half* pb = B  + (size_t)bcol * K;

    float acc[2][8][4];
    #pragma unroll
    for (int i = 0; i < 2; i++)
        #pragma unroll
        for (int j = 0; j < 8; j++)
            #pragma unroll
            for (int k = 0; k < 4; k++) acc[i][j][k] = 0.f;

    const int nchunks = K / GK;

    load_stage_f16(smem_base, tid, pa, pl, pb, K, 0);            CP_COMMIT();
    load_stage_f16(smem_base + STAGE16, tid, pa, pl, pb, K, GK); CP_COMMIT();
    CP_WAIT1();
    __syncthreads();

    for (int chunk = 0; chunk < nchunks; chunk++) {
        f16_chunk(acc, smem_base + (chunk & 1) * STAGE16, wm, wn, lane);
        __syncthreads();
        if (chunk + 2 < nchunks) {
            load_stage_f16(smem_base + (chunk & 1) * STAGE16, tid, pa, pl, pb,
                           K, (chunk + 2) * GK);
            CP_COMMIT();
            CP_WAIT1();
            __syncthreads();
        } else if (chunk + 1 < nchunks) {
            CP_WAIT0();
            __syncthreads();
        }
    }

    const int crow = lane >> 2;
    const int ccol = (lane & 3) << 1;
    #pragma unroll
    for (int nt = 0; nt < 8; nt++) {
        const int col = bcol + wn * 64 + nt * 8 + ccol;
        float b0 = __ldg(&bias[col]), b1 = __ldg(&bias[col + 1]);
        #pragma unroll
        for (int mt = 0; mt < 2; mt++) {
            size_t row0 = (size_t)(brow + wm * 32 + mt * 16 + crow);
            float2 v0 = { acc[mt][nt][0] + b0, acc[mt][nt][1] + b1 };
            float2 v1 = { acc[mt][nt][2] + b0, acc[mt][nt][3] + b1 };
            *(float2*)&Cf[row0 * N + col]       = v0;
            *(float2*)&Cf[(row0 + 8) * N + col] = v1;
        }
    }
}

// ---------------------------------------------------------------------------
// fp16 2-product causal GQA flash attention.
// CTA = 128 threads (4 warps), q-tile 64 rows, k-tile 64. 2 CTAs/SM.
// SMEM: Qh|Ql (2x17408) + 2 x (K|V, 2x17408) = 104448 B.
// ---------------------------------------------------------------------------
#define ATSTR 272
#define AT64  (64 * ATSTR)              /* 17408 */
#define AQ_B  AT64
#define AKV_B (2 * AT64)
#define ATTN_SMEM (2 * AQ_B + 2 * AKV_B)   /* 104448 */

__device__ __forceinline__ void attn_load_kv(
    uint32_t base, int tid,
    const __half* __restrict__ Kf, const __half* __restrict__ Vf,
    size_t grow0, int gcol)
{
    const __half* srcs[2] = { Kf, Vf };
    #pragma unroll
    for (int t = 0; t < 2; t++) {
        const __half* s = srcs[t] + grow0 * KVD + gcol;
        #pragma unroll
        for (int i = 0; i < 8; i++) {
            int ch = tid + i * 128;           // 0..1023
            int r = ch >> 4, c = ch & 15;
            cpasync16(base + t * AT64 + r * ATSTR + c * 16,
                      s + (size_t)r * KVD + c * 8);
        }
    }
    CP_COMMIT();
}

__global__ __launch_bounds__(128, 2) void attn_mma(
    const __half* __restrict__ Qh_, const __half* __restrict__ Ql_,
    const __half* __restrict__ Kf_, const __half* __restrict__ Vf_,
    __half* __restrict__ Yh_, __half* __restrict__ Yl_)
{
    extern __shared__ char sm_[];
    const uint32_t sb = smem_u32(sm_);
    const int tid  = threadIdx.x;
    const int lane = tid & 31;
    const int w    = tid >> 5;              // 0..3
    const int qt   = (int)gridDim.x - 1 - (int)blockIdx.x;  // heavy first
    const int bh   = blockIdx.y;
    const int b    = bh >> 5, h = bh & 31, g = h >> 2;
    const int ktmax = qt;
    const size_t qrow0 = (size_t)b * TT + (size_t)qt * 64;
    const size_t krow0 = (size_t)b * TT;
    const int gcol = g * DH;

    {
        const __half* q0 = Qh_ + qrow0 * DD + h * DH;
        const __half* q1 = Ql_ + qrow0 * DD + h * DH;
        #pragma unroll
        for (int i = 0; i < 8; i++) {
            int ch = tid + i * 128;           // 0..1023 -> 64 rows x 16 chunks
            int r = ch >> 4, c = ch & 15;
            cpasync16(sb + r * ATSTR + c * 16,        q0 + (size_t)r * DD + c * 8);
            cpasync16(sb + AQ_B + r * ATSTR + c * 16, q1 + (size_t)r * DD + c * 8);
        }
        CP_COMMIT();
    }
    attn_load_kv(sb + 2 * AQ_B, tid, Kf_, Vf_, krow0, gcol);
    if (ktmax >= 1)
        attn_load_kv(sb + 2 * AQ_B + AKV_B, tid, Kf_, Vf_, krow0 + 64, gcol);
    else
        CP_COMMIT();   // keep group count consistent

    float o[16][4];
    #pragma unroll
    for (int i = 0; i < 16; i++)
        #pragma unroll
        for (int j = 0; j < 4; j++) o[i][j] = 0.f;
    float m_lo = -1e30f, m_hi = -1e30f, l_lo = 0.f, l_hi = 0.f;

    const int wrow = qt * 64 + w * 16;
    const int rl   = lane >> 2;
    const float SC = 0.088388347648318447f * 1.4426950408889634f;

    for (int kt = 0; kt <= ktmax; kt++) {
        if (kt < ktmax) { CP_WAIT1(); } else { CP_WAIT0(); }
        __syncthreads();
        const uint32_t kb = sb + 2 * AQ_B + (kt & 1) * AKV_B;

        {
            float s[8][4];
            #pragma unroll
            for (int j = 0; j < 8; j++)
                #pragma unroll
                for (int e = 0; e < 4; e++) s[j][e] = 0.f;

            // ---- S = Q K^T ----
            #pragma unroll
            for (int ks = 0; ks < 8; ks++) {
                uint32_t qh[4], ql[4];
                uint32_t ra = sb + (w * 16 + (lane & 15)) * ATSTR
                            + ks * 32 + ((lane >> 4) << 4);
                ldsm4(qh[0], qh[1], qh[2], qh[3], ra);
                ldsm4(ql[0], ql[1], ql[2], ql[3], ra + AQ_B);
                uint32_t kf[4][4];
                #pragma unroll
                for (int np = 0; np < 4; np++) {
                    uint32_t rb = kb
                        + (np * 16 + (lane & 7) + ((lane >> 4) << 3)) * ATSTR
                        + ks * 32 + (((lane >> 3) & 1) << 4);
                    ldsm4(kf[np][0], kf[np][1], kf[np][2], kf[np][3], rb);
                }
                #pragma unroll
                for (int np = 0; np < 4; np++) {
                    mma16816h(s[2 * np],     qh, kf[np][0], kf[np][1]);
                    mma16816h(s[2 * np + 1], qh, kf[np][2], kf[np][3]);
                }
                #pragma unroll
                for (int np = 0; np < 4; np++) {
                    mma16816h(s[2 * np],     ql, kf[np][0], kf[np][1]);
                    mma16816h(s[2 * np + 1], ql, kf[np][2], kf[np][3]);
                }
            }

            #pragma unroll
            for (int j = 0; j < 8; j++)
                #pragma unroll
                for (int e = 0; e < 4; e++) s[j][e] *= SC;
            if (kt * 64 + 63 > wrow) {
                const int row_lo = wrow + rl, row_hi = row_lo + 8;
                #pragma unroll
                for (int j = 0; j < 8; j++) {
                    int c0 = kt * 64 + j * 8 + ((lane & 3) << 1);
                    if (c0 > row_lo)     s[j][0] = -1e30f;
                    if (c0 + 1 > row_lo) s[j][1] = -1e30f;
                    if (c0 > row_hi)     s[j][2] = -1e30f;
                    if (c0 + 1 > row_hi) s[j][3] = -1e30f;
                }
            }

            float mx0 = -1e30f, mx1 = -1e30f;
            #pragma unroll
            for (int j = 0; j < 8; j++) {
                mx0 = fmaxf(mx0, fmaxf(s[j][0], s[j][1]));
                mx1 = fmaxf(mx1, fmaxf(s[j][2], s[j][3]));
            }
            mx0 = fmaxf(mx0, __shfl_xor_sync(0xffffffffu, mx0, 1));
            mx0 = fmaxf(mx0, __shfl_xor_sync(0xffffffffu, mx0, 2));
            mx1 = fmaxf(mx1, __shfl_xor_sync(0xffffffffu, mx1, 1));
            mx1 = fmaxf(mx1, __shfl_xor_sync(0xffffffffu, mx1, 2));
            float mn0 = fmaxf(m_lo, mx0), mn1 = fmaxf(m_hi, mx1);
            float c0 = ex2f(m_lo - mn0), c1 = ex2f(m_hi - mn1);
            float su0 = 0.f, su1 = 0.f;
            #pragma unroll
            for (int j = 0; j < 8; j++) {
                s[j][0] = ex2f(s[j][0] - mn0);
                s[j][1] = ex2f(s[j][1] - mn0);
                s[j][2] = ex2f(s[j][2] - mn1);
                s[j][3] = ex2f(s[j][3] - mn1);
                su0 += s[j][0] + s[j][1];
                su1 += s[j][2] + s[j][3];
            }
            su0 += __shfl_xor_sync(0xffffffffu, su0, 1);
            su0 += __shfl_xor_sync(0xffffffffu, su0, 2);
            su1 += __shfl_xor_sync(0xffffffffu, su1, 1);
            su1 += __shfl_xor_sync(0xffffffffu, su1, 2);
            l_lo = l_lo * c0 + su0;  l_hi = l_hi * c1 + su1;
            m_lo = mn0;              m_hi = mn1;
            #pragma unroll
            for (int nt = 0; nt < 16; nt++) {
                o[nt][0] *= c0; o[nt][1] *= c0;
                o[nt][2] *= c1; o[nt][3] *= c1;
            }

            // ---- O += P V ----
            #pragma unroll
            for (int ks = 0; ks < 4; ks++) {
                uint32_t ph[4], pl[4];
                split_pack_h(s[2 * ks][0],     s[2 * ks][1],     ph[0], pl[0]);
                split_pack_h(s[2 * ks][2],     s[2 * ks][3],     ph[1], pl[1]);
                split_pack_h(s[2 * ks + 1][0], s[2 * ks + 1][1], ph[2], pl[2]);
                split_pack_h(s[2 * ks + 1][2], s[2 * ks + 1][3], ph[3], pl[3]);
                #pragma unroll
                for (int npp = 0; npp < 4; npp++) {
                    uint32_t vh0[4], vh1[4];
                    uint32_t rv = kb + AT64
                        + (ks * 16 + (lane & 15)) * ATSTR
                        + npp * 64 + ((lane >> 4) << 4);
                    ldsm4t(vh0[0], vh0[1], vh0[2], vh0[3], rv);
                    ldsm4t(vh1[0], vh1[1], vh1[2], vh1[3], rv + 32);
                    float* o0 = o[4 * npp];     float* o1 = o[4 * npp + 1];
                    float* o2 = o[4 * npp + 2]; float* o3 = o[4 * npp + 3];
                    mma16816h(o0, ph, vh0[0], vh0[1]);
                    mma16816h(o1, ph, vh0[2], vh0[3]);
                    mma16816h(o2, ph, vh1[0], vh1[1]);
                    mma16816h(o3, ph, vh1[2], vh1[3]);
                    mma16816h(o0, pl, vh0[0], vh0[1]);
                    mma16816h(o1, pl, vh0[2], vh0[3]);
                    mma16816h(o2, pl, vh1[0], vh1[1]);
                    mma16816h(o3, pl, vh1[2], vh1[3]);
                }
            }
        }
        __syncthreads();
        if (kt + 2 <= ktmax)
            attn_load_kv(sb + 2 * AQ_B + (kt & 1) * AKV_B, tid,
                         Kf_, Vf_, krow0 + (size_t)(kt + 2) * 64, gcol);
    }

    const float i0 = 1.f / l_lo, i1 = 1.f / l_hi;
    const size_t row_lo = qrow0 + w * 16 + rl;
    const size_t row_hi = row_lo + 8;
    const int colb = h * DH + ((lane & 3) << 1);
    #pragma unroll
    for (int nt = 0; nt < 16; nt++) {
        int col = colb + nt * 8;
        uint32_t h0, l0, h1, l1;
        split_pack_h(o[nt][0] * i0, o[nt][1] * i0, h0, l0);
        split_pack_h(o[nt][2] * i1, o[nt][3] * i1, h1, l1);
        *(uint32_t*)&Yh_[row_lo * DD + col] = h0;
        *(uint32_t*)&Yl_[row_lo * DD + col] = l0;
        *(uint32_t*)&Yh_[row_hi * DD + col] = h1;
        *(uint32_t*)&Yl_[row_hi * DD + col] = l1;
    }
}

// ---------------------------------------------------------------------------
extern "C" void kernel_launch(void* const* d_in, const int* in_sizes, int n_in,
                              void* d_out, int out_size)
{
    (void)in_sizes; (void)n_in; (void)out_size;
    const float* X  = (const float*)d_in[0];
    const float* Wq = (const float*)d_in[1];
    const float* bq = (const float*)d_in[2];
    const float* Wk = (const float*)d_in[3];
    const float* bk = (const float*)d_in[4];
    const float* Wv = (const float*)d_in[5];
    const float* bv = (const float*)d_in[6];
    const float* Wo = (const float*)d_in[7];
    const float* bo = (const float*)d_in[8];
    float* out = (float*)d_out;

    __half *Xh16, *Xl16, *Wqkvf, *Wof, *Yh, *Yl, *Qh, *Ql, *Kf, *Vf;
    cudaGetSymbolAddress((void**)&Xh16, g_X_h16);  cudaGetSymbolAddress((void**)&Xl16, g_X_l16);
    cudaGetSymbolAddress((void**)&Wqkvf, g_Wqkv_f);
    cudaGetSymbolAddress((void**)&Qh, g_Q_h16);   cudaGetSymbolAddress((void**)&Ql, g_Q_l16);
    cudaGetSymbolAddress((void**)&Kf, g_K_f);     cudaGetSymbolAddress((void**)&Vf, g_V_f);
    cudaGetSymbolAddress((void**)&Wof, g_Wo_f);
    cudaGetSymbolAddress((void**)&Yh, g_Y_h);     cudaGetSymbolAddress((void**)&Yl, g_Y_l);

    cudaFuncSetAttribute(gemm_qkv16,
                         cudaFuncAttributeMaxDynamicSharedMemorySize, GEMMF_SMEM);
    cudaFuncSetAttribute(gemm_f16,
                         cudaFuncAttributeMaxDynamicSharedMemorySize, GEMMF_SMEM);
    cudaFuncSetAttribute(attn_mma,
                         cudaFuncAttributeMaxDynamicSharedMemorySize, ATTN_SMEM);

    const int nXD = MTOT * DD / 4;
    const int nW  = (2 * DD * DD + 2 * KVD * DD) / 4;
    split_f16<<<(nXD + 255) / 256, 256>>>(X, Xh16, Xl16, nXD);
    conv_f16_all<<<(nW + 255) / 256, 256>>>(Wq, Wk, Wv, Wo, Wqkvf, Wof);

    // merged QKV projection (fp16 2-product), 64x256 tiles, 2 CTAs/SM
    gemm_qkv16<<<dim3(NQKV / 256, MTOT / 64), 256, GEMMF_SMEM>>>(
        Xh16, Xl16, Wqkvf, bq, bk, bv, Qh, Ql, Kf, Vf);

    // attention (fp16 2-product), q-tile 64, 2 CTAs/SM
    attn_mma<<<dim3(TT / 64, BB * HH), 128, ATTN_SMEM>>>(
        Qh, Ql, Kf, Vf, Yh, Yl);

    // O projection (fp16 2-product) -> fp32 out
    gemm_f16<<<dim3(DD / 256, MTOT / 64), 256, GEMMF_SMEM>>>(
        Yh, Yl, Wof, bo, out, DD, DD);
}

// round 13
// speedup vs baseline: 3.5874x; 1.0084x over previous
#include <cuda_runtime.h>
#include <cuda_bf16.h>
#include <cuda_fp16.h>
#include <cstdint>

#define BB   2
#define TT   2048
#define DD   4096
#define HH   32
#define GG   8
#define DH   128
#define KVD  (GG*DH)     /* 1024 */
#define NQKV (DD+2*KVD)  /* 6144 */
#define MTOT (BB*TT)     /* 4096 */

// fp16 operands
__device__ __half g_X_h16[(size_t)MTOT * DD], g_X_l16[(size_t)MTOT * DD];
__device__ __half g_Wqkv_f[(size_t)NQKV * DD];
__device__ __half g_Q_h16[(size_t)MTOT * DD], g_Q_l16[(size_t)MTOT * DD];
__device__ __half g_K_f[(size_t)MTOT * KVD];
__device__ __half g_V_f[(size_t)MTOT * KVD];
__device__ __half g_Wo_f[(size_t)DD * DD];
__device__ __half g_Y_h[(size_t)MTOT * DD], g_Y_l[(size_t)MTOT * DD];

// ---------------------------------------------------------------------------
__device__ __forceinline__ uint32_t smem_u32(const void* p) {
    uint32_t a;
    asm("{ .reg .u64 t; cvta.to.shared.u64 t, %1; cvt.u32.u64 %0, t; }"
        : "=r"(a) : "l"(p));
    return a;
}
__device__ __forceinline__ void ldsm4(uint32_t& r0, uint32_t& r1, uint32_t& r2,
                                      uint32_t& r3, uint32_t addr) {
    asm volatile("ldmatrix.sync.aligned.m8n8.x4.shared.b16 {%0,%1,%2,%3}, [%4];"
                 : "=r"(r0), "=r"(r1), "=r"(r2), "=r"(r3) : "r"(addr));
}
__device__ __forceinline__ void ldsm4t(uint32_t& r0, uint32_t& r1, uint32_t& r2,
                                       uint32_t& r3, uint32_t addr) {
    asm volatile("ldmatrix.sync.aligned.m8n8.x4.trans.shared.b16 {%0,%1,%2,%3}, [%4];"
                 : "=r"(r0), "=r"(r1), "=r"(r2), "=r"(r3) : "r"(addr));
}
__device__ __forceinline__ void mma16816h(float* c, const uint32_t* a,
                                          uint32_t b0, uint32_t b1) {
    asm volatile(
        "mma.sync.aligned.m16n8k16.row.col.f32.f16.f16.f32 "
        "{%0,%1,%2,%3}, {%4,%5,%6,%7}, {%8,%9}, {%0,%1,%2,%3};"
        : "+f"(c[0]), "+f"(c[1]), "+f"(c[2]), "+f"(c[3])
        : "r"(a[0]), "r"(a[1]), "r"(a[2]), "r"(a[3]), "r"(b0), "r"(b1));
}
__device__ __forceinline__ void cpasync16(uint32_t dst, const void* src) {
    asm volatile("cp.async.cg.shared.global [%0], [%1], 16;"
                 :: "r"(dst), "l"(src) : "memory");
}
#define CP_COMMIT() asm volatile("cp.async.commit_group;" ::: "memory")
#define CP_WAIT1()  asm volatile("cp.async.wait_group 1;" ::: "memory")
#define CP_WAIT0()  asm volatile("cp.async.wait_group 0;" ::: "memory")

__device__ __forceinline__ float ex2f(float x) {
    float y;
    asm("ex2.approx.ftz.f32 %0, %1;" : "=f"(y) : "f"(x));
    return y;
}
__device__ __forceinline__ void split_pack_h(float a, float b,
                                             uint32_t& h, uint32_t& l) {
    __half2 hb = __floats2half2_rn(a, b);
    float2 bk = __half22float2(hb);
    __half2 lb = __floats2half2_rn(a - bk.x, b - bk.y);
    h = *reinterpret_cast<uint32_t*>(&hb);
    l = *reinterpret_cast<uint32_t*>(&lb);
}

// ---------------------------------------------------------------------------
__global__ void split_f16(const float* __restrict__ x,
                          __half* __restrict__ hi,
                          __half* __restrict__ lo, int n4)
{
    int i = blockIdx.x * blockDim.x + threadIdx.x;
    if (i >= n4) return;
    float4 v = ((const float4*)x)[i];
    uint32_t h0, l0, h1, l1;
    split_pack_h(v.x, v.y, h0, l0);
    split_pack_h(v.z, v.w, h1, l1);
    ((uint32_t*)hi)[2 * i] = h0; ((uint32_t*)hi)[2 * i + 1] = h1;
    ((uint32_t*)lo)[2 * i] = l0; ((uint32_t*)lo)[2 * i + 1] = l1;
}
__global__ void conv_f16_all(const float* __restrict__ wq,
                             const float* __restrict__ wk,
                             const float* __restrict__ wv,
                             const float* __restrict__ wo,
                             __half* __restrict__ qkv, __half* __restrict__ o)
{
    const int nDD = DD * DD / 4, nKD = KVD * DD / 4;
    int i = blockIdx.x * blockDim.x + threadIdx.x;
    const float* src; __half* dst; int j = i;
    if (j < nDD)                { src = wq; dst = qkv; }
    else if ((j -= nDD) < nKD)  { src = wk; dst = qkv + (size_t)DD * DD; }
    else if ((j -= nKD) < nKD)  { src = wv; dst = qkv + (size_t)(DD + KVD) * DD; }
    else if ((j -= nKD) < nDD)  { src = wo; dst = o; }
    else return;
    float4 v = ((const float4*)src)[j];
    __half2 a = __floats2half2_rn(v.x, v.y);
    __half2 b = __floats2half2_rn(v.z, v.w);
    ((uint32_t*)dst)[2 * j]     = *reinterpret_cast<uint32_t*>(&a);
    ((uint32_t*)dst)[2 * j + 1] = *reinterpret_cast<uint32_t*>(&b);
}

// ---------------------------------------------------------------------------
// fp16 2-product GEMM: CTA tile 64x256, 8 warps of 32x64, K-chunk 32.
// 3-stage cp.async pipeline, ONE __syncthreads per chunk. 2 CTAs/SM.
// ---------------------------------------------------------------------------
#define GK      32
#define A16SUB  (64 * 80)               /* 5120 B  */
#define B16SUB  (256 * 80)              /* 20480 B */
#define STAGE16 (2 * A16SUB + B16SUB)   /* 30720 B */
#define GEMMF_SMEM (3 * STAGE16)        /* 92160 B */

__device__ __forceinline__ void load_stage_f16(
    uint32_t sb, int tid, const __half* ah, const __half* al,
    const __half* b, int K, int k0)
{
    #pragma unroll
    for (int t = 0; t < 6; t++) {
        const int id = t * 256 + tid;          // 0..1535
        if (id < 512) {                         // A hi/lo: 64 rows x 32 cols
            const int x = id & 255;
            const int r = x >> 2, cb = (x & 3) << 4;
            const __half* src = (id < 256 ? ah : al) + (size_t)r * K + k0 + (cb >> 1);
            cpasync16(sb + (id < 256 ? 0u : (uint32_t)A16SUB) + r * 80 + cb, src);
        } else {                                // B: 256 rows x 32 cols
            const int x = id - 512;
            const int r = x >> 2, cb = (x & 3) << 4;
            cpasync16(sb + 2 * A16SUB + r * 80 + cb,
                      b + (size_t)r * K + k0 + (cb >> 1));
        }
    }
}

__device__ __forceinline__ void f16_chunk(
    float acc[2][8][4], uint32_t sb, int wm, int wn, int lane)
{
    const int a_row = lane & 15;
    const int a_kb  = (lane >> 4) << 4;
    const int b_row = (lane & 7) + ((lane >> 4) << 3);
    const int b_kb  = ((lane >> 3) & 1) << 4;
    #pragma unroll
    for (int ks = 0; ks < 2; ks++) {
        uint32_t ah[2][4], al[2][4], bh[4][4];
        #pragma unroll
        for (int mt = 0; mt < 2; mt++) {
            uint32_t ra = sb + (wm * 32 + mt * 16 + a_row) * 80
                        + ks * 32 + a_kb;
            ldsm4(ah[mt][0], ah[mt][1], ah[mt][2], ah[mt][3], ra);
            ldsm4(al[mt][0], al[mt][1], al[mt][2], al[mt][3], ra + A16SUB);
        }
        #pragma unroll
        for (int bt = 0; bt < 4; bt++) {
            uint32_t rb = sb + 2 * A16SUB
                        + (wn * 64 + bt * 16 + b_row) * 80
                        + ks * 32 + b_kb;
            ldsm4(bh[bt][0], bh[bt][1], bh[bt][2], bh[bt][3], rb);
        }
        #pragma unroll
        for (int bt = 0; bt < 4; bt++)
            #pragma unroll
            for (int mt = 0; mt < 2; mt++) {
                mma16816h(acc[mt][bt * 2],     ah[mt], bh[bt][0], bh[bt][1]);
                mma16816h(acc[mt][bt * 2 + 1], ah[mt], bh[bt][2], bh[bt][3]);
            }
        #pragma unroll
        for (int bt = 0; bt < 4; bt++)
            #pragma unroll
            for (int mt = 0; mt < 2; mt++) {
                mma16816h(acc[mt][bt * 2],     al[mt], bh[bt][0], bh[bt][1]);
                mma16816h(acc[mt][bt * 2 + 1], al[mt], bh[bt][2], bh[bt][3]);
            }
    }
}

// 3-stage mainloop shared by both projections
__device__ __forceinline__ void f16_mainloop(
    float acc[2][8][4], uint32_t smem_base, int tid, int wm, int wn, int lane,
    const __half* pa, const __half* pl, const __half* pb, int K)
{
    const int nchunks = K / GK;
    load_stage_f16(smem_base,               tid, pa, pl, pb, K, 0);      CP_COMMIT();
    load_stage_f16(smem_base + STAGE16,     tid, pa, pl, pb, K, GK);     CP_COMMIT();

    uint32_t buf = 0;   // byte offset of current stage
    for (int chunk = 0; chunk < nchunks; chunk++) {
        if (chunk + 1 < nchunks) { CP_WAIT1(); } else { CP_WAIT0(); }
        __syncthreads();     // chunk's data ready AND everyone done with chunk-1's buffer
        if (chunk + 2 < nchunks) {
            // prefetch chunk+2 into the buffer consumed at chunk-1
            uint32_t nb = buf + 2 * STAGE16;
            if (nb >= 3 * STAGE16) nb -= 3 * STAGE16;
            load_stage_f16(smem_base + nb, tid, pa, pl, pb, K, (chunk + 2) * GK);
            CP_COMMIT();
        }
        f16_chunk(acc, smem_base + buf, wm, wn, lane);
        buf += STAGE16;
        if (buf == 3 * STAGE16) buf = 0;
    }
}

// ---------------------------------------------------------------------------
// QKV projection: Q -> fp16 hi/lo; K,V -> single fp16
// ---------------------------------------------------------------------------
__global__ __launch_bounds__(256, 2) void gemm_qkv16(
    const __half* __restrict__ Ah, const __half* __restrict__ Al,
    const __half* __restrict__ B,
    const float* __restrict__ bq, const float* __restrict__ bk,
    const float* __restrict__ bv,
    __half* __restrict__ Qh, __half* __restrict__ Ql,
    __half* __restrict__ Kf, __half* __restrict__ Vf)
{
    extern __shared__ char sm_[];
    const uint32_t smem_base = smem_u32(sm_);
    const int tid  = threadIdx.x;
    const int wid  = tid >> 5;
    const int lane = tid & 31;
    const int wm   = wid >> 2;
    const int wn   = wid & 3;
    const int brow = blockIdx.y << 6;
    const int bcol = blockIdx.x << 8;
    const int K    = DD;

    __half *Ch, *Cl; const float* bias; int outN, obase;
    if (bcol < DD)            { Ch = Qh; Cl = Ql;      bias = bq; outN = DD;  obase = bcol; }
    else if (bcol < DD + KVD) { Ch = Kf; Cl = nullptr; bias = bk; outN = KVD; obase = bcol - DD; }
    else                      { Ch = Vf; Cl = nullptr; bias = bv; outN = KVD; obase = bcol - DD - KVD; }

    const __half* pa = Ah + (size_t)brow * K;
    const __half* pl = Al + (size_t)brow * K;
    const __half* pb = B  + (size_t)bcol * K;

    float acc[2][8][4];
    #pragma unroll
    for (int i = 0; i < 2; i++)
        #pragma unroll
        for (int j = 0; j < 8; j++)
            #pragma unroll
            for (int k = 0; k < 4; k++) acc[i][j][k] = 0.f;

    f16_mainloop(acc, smem_base, tid, wm, wn, lane, pa, pl, pb, K);

    const int crow = lane >> 2;
    const int ccol = (lane & 3) << 1;
    #pragma unroll
    for (int nt = 0; nt < 8; nt++) {
        const int col = obase + wn * 64 + nt * 8 + ccol;
        float b0 = __ldg(&bias[col]), b1 = __ldg(&bias[col + 1]);
        #pragma unroll
        for (int mt = 0; mt < 2; mt++) {
            size_t row0 = (size_t)(brow + wm * 32 + mt * 16 + crow);
            float x0 = acc[mt][nt][0] + b0, x1 = acc[mt][nt][1] + b1;
            float x2 = acc[mt][nt][2] + b0, x3 = acc[mt][nt][3] + b1;
            if (Cl) {
                uint32_t h0, l0, h1, l1;
                split_pack_h(x0, x1, h0, l0);
                split_pack_h(x2, x3, h1, l1);
                *(uint32_t*)&Ch[row0 * outN + col]       = h0;
                *(uint32_t*)&Cl[row0 * outN + col]       = l0;
                *(uint32_t*)&Ch[(row0 + 8) * outN + col] = h1;
                *(uint32_t*)&Cl[(row0 + 8) * outN + col] = l1;
            } else {
                __half2 v0 = __floats2half2_rn(x0, x1);
                __half2 v1 = __floats2half2_rn(x2, x3);
                *(uint32_t*)&Ch[row0 * outN + col]       = *reinterpret_cast<uint32_t*>(&v0);
                *(uint32_t*)&Ch[(row0 + 8) * outN + col] = *reinterpret_cast<uint32_t*>(&v1);
            }
        }
    }
}

// ---------------------------------------------------------------------------
// O projection (fp16 2-product) -> fp32 out
// ---------------------------------------------------------------------------
__global__ __launch_bounds__(256, 2) void gemm_f16(
    const __half* __restrict__ Ah, const __half* __restrict__ Al,
    const __half* __restrict__ B,
    const float* __restrict__ bias, float* __restrict__ Cf, int N, int K)
{
    extern __shared__ char sm_[];
    const uint32_t smem_base = smem_u32(sm_);
    const int tid  = threadIdx.x;
    const int wid  = tid >> 5;
    const int lane = tid & 31;
    const int wm   = wid >> 2;
    const int wn   = wid & 3;
    const int brow = blockIdx.y << 6;
    const int bcol = blockIdx.x << 8;

    const __half* pa = Ah + (size_t)brow * K;
    const __half* pl = Al + (size_t)brow * K;
    const __half* pb = B  + (size_t)bcol * K;

    float acc[2][8][4];
    #pragma unroll
    for (int i = 0; i < 2; i++)
        #pragma unroll
        for (int j = 0; j < 8; j++)
            #pragma unroll
            for (int k = 0; k < 4; k++) acc[i][j][k] = 0.f;

    f16_mainloop(acc, smem_base, tid, wm, wn, lane, pa, pl, pb, K);

    const int crow = lane >> 2;
    const int ccol = (lane & 3) << 1;
    #pragma unroll
    for (int nt = 0; nt < 8; nt++) {
        const int col = bcol + wn * 64 + nt * 8 + ccol;
        float b0 = __ldg(&bias[col]), b1 = __ldg(&bias[col + 1]);
        #pragma unroll
        for (int mt = 0; mt < 2; mt++) {
            size_t row0 = (size_t)(brow + wm * 32 + mt * 16 + crow);
            float2 v0 = { acc[mt][nt][0] + b0, acc[mt][nt][1] + b1 };
            float2 v1 = { acc[mt][nt][2] + b0, acc[mt][nt][3] + b1 };
            *(float2*)&Cf[row0 * N + col]       = v0;
            *(float2*)&Cf[(row0 + 8) * N + col] = v1;
        }
    }
}

// ---------------------------------------------------------------------------
// fp16 2-product causal GQA flash attention (unchanged from R12).
// CTA = 128 threads, q-tile 64, 2 CTAs/SM. SMEM 104448 B.
// ---------------------------------------------------------------------------
#define ATSTR 272
#define AT64  (64 * ATSTR)
#define AQ_B  AT64
#define AKV_B (2 * AT64)
#define ATTN_SMEM (2 * AQ_B + 2 * AKV_B)

__device__ __forceinline__ void attn_load_kv(
    uint32_t base, int tid,
    const __half* __restrict__ Kf, const __half* __restrict__ Vf,
    size_t grow0, int gcol)
{
    const __half* srcs[2] = { Kf, Vf };
    #pragma unroll
    for (int t = 0; t < 2; t++) {
        const __half* s = srcs[t] + grow0 * KVD + gcol;
        #pragma unroll
        for (int i = 0; i < 8; i++) {
            int ch = tid + i * 128;
            int r = ch >> 4, c = ch & 15;
            cpasync16(base + t * AT64 + r * ATSTR + c * 16,
                      s + (size_t)r * KVD + c * 8);
        }
    }
    CP_COMMIT();
}

__global__ __launch_bounds__(128, 2) void attn_mma(
    const __half* __restrict__ Qh_, const __half* __restrict__ Ql_,
    const __half* __restrict__ Kf_, const __half* __restrict__ Vf_,
    __half* __restrict__ Yh_, __half* __restrict__ Yl_)
{
    extern __shared__ char sm_[];
    const uint32_t sb = smem_u32(sm_);
    const int tid  = threadIdx.x;
    const int lane = tid & 31;
    const int w    = tid >> 5;
    const int qt   = (int)gridDim.x - 1 - (int)blockIdx.x;
    const int bh   = blockIdx.y;
    const int b    = bh >> 5, h = bh & 31, g = h >> 2;
    const int ktmax = qt;
    const size_t qrow0 = (size_t)b * TT + (size_t)qt * 64;
    const size_t krow0 = (size_t)b * TT;
    const int gcol = g * DH;

    {
        const __half* q0 = Qh_ + qrow0 * DD + h * DH;
        const __half* q1 = Ql_ + qrow0 * DD + h * DH;
        #pragma unroll
        for (int i = 0; i < 8; i++) {
            int ch = tid + i * 128;
            int r = ch >> 4, c = ch & 15;
            cpasync16(sb + r * ATSTR + c * 16,        q0 + (size_t)r * DD + c * 8);
            cpasync16(sb + AQ_B + r * ATSTR + c * 16, q1 + (size_t)r * DD + c * 8);
        }
        CP_COMMIT();
    }
    attn_load_kv(sb + 2 * AQ_B, tid, Kf_, Vf_, krow0, gcol);
    if (ktmax >= 1)
        attn_load_kv(sb + 2 * AQ_B + AKV_B, tid, Kf_, Vf_, krow0 + 64, gcol);
    else
        CP_COMMIT();

    float o[16][4];
    #pragma unroll
    for (int i = 0; i < 16; i++)
        #pragma unroll
        for (int j = 0; j < 4; j++) o[i][j] = 0.f;
    float m_lo = -1e30f, m_hi = -1e30f, l_lo = 0.f, l_hi = 0.f;

    const int wrow = qt * 64 + w * 16;
    const int rl   = lane >> 2;
    const float SC = 0.088388347648318447f * 1.4426950408889634f;

    for (int kt = 0; kt <= ktmax; kt++) {
        if (kt < ktmax) { CP_WAIT1(); } else { CP_WAIT0(); }
        __syncthreads();
        const uint32_t kb = sb + 2 * AQ_B + (kt & 1) * AKV_B;

        {
            float s[8][4];
            #pragma unroll
            for (int j = 0; j < 8; j++)
                #pragma unroll
                for (int e = 0; e < 4; e++) s[j][e] = 0.f;

            #pragma unroll
            for (int ks = 0; ks < 8; ks++) {
                uint32_t qh[4], ql[4];
                uint32_t ra = sb + (w * 16 + (lane & 15)) * ATSTR
                            + ks * 32 + ((lane >> 4) << 4);
                ldsm4(qh[0], qh[1], qh[2], qh[3], ra);
                ldsm4(ql[0], ql[1], ql[2], ql[3], ra + AQ_B);
                uint32_t kf[4][4];
                #pragma unroll
                for (int np = 0; np < 4; np++) {
                    uint32_t rb = kb
                        + (np * 16 + (lane & 7) + ((lane >> 4) << 3)) * ATSTR
                        + ks * 32 + (((lane >> 3) & 1) << 4);
                    ldsm4(kf[np][0], kf[np][1], kf[np][2], kf[np][3], rb);
                }
                #pragma unroll
                for (int np = 0; np < 4; np++) {
                    mma16816h(s[2 * np],     qh, kf[np][0], kf[np][1]);
                    mma16816h(s[2 * np + 1], qh, kf[np][2], kf[np][3]);
                }
                #pragma unroll
                for (int np = 0; np < 4; np++) {
                    mma16816h(s[2 * np],     ql, kf[np][0], kf[np][1]);
                    mma16816h(s[2 * np + 1], ql, kf[np][2], kf[np][3]);
                }
            }

            #pragma unroll
            for (int j = 0; j < 8; j++)
                #pragma unroll
                for (int e = 0; e < 4; e++) s[j][e] *= SC;
            if (kt * 64 + 63 > wrow) {
                const int row_lo = wrow + rl, row_hi = row_lo + 8;
                #pragma unroll
                for (int j = 0; j < 8; j++) {
                    int c0 = kt * 64 + j * 8 + ((lane & 3) << 1);
                    if (c0 > row_lo)     s[j][0] = -1e30f;
                    if (c0 + 1 > row_lo) s[j][1] = -1e30f;
                    if (c0 > row_hi)     s[j][2] = -1e30f;
                    if (c0 + 1 > row_hi) s[j][3] = -1e30f;
                }
            }

            float mx0 = -1e30f, mx1 = -1e30f;
            #pragma unroll
            for (int j = 0; j < 8; j++) {
                mx0 = fmaxf(mx0, fmaxf(s[j][0], s[j][1]));
                mx1 = fmaxf(mx1, fmaxf(s[j][2], s[j][3]));
            }
            mx0 = fmaxf(mx0, __shfl_xor_sync(0xffffffffu, mx0, 1));
            mx0 = fmaxf(mx0, __shfl_xor_sync(0xffffffffu, mx0, 2));
            mx1 = fmaxf(mx1, __shfl_xor_sync(0xffffffffu, mx1, 1));
            mx1 = fmaxf(mx1, __shfl_xor_sync(0xffffffffu, mx1, 2));
            float mn0 = fmaxf(m_lo, mx0), mn1 = fmaxf(m_hi, mx1);
            float c0 = ex2f(m_lo - mn0), c1 = ex2f(m_hi - mn1);
            float su0 = 0.f, su1 = 0.f;
            #pragma unroll
            for (int j = 0; j < 8; j++) {
                s[j][0] = ex2f(s[j][0] - mn0);
                s[j][1] = ex2f(s[j][1] - mn0);
                s[j][2] = ex2f(s[j][2] - mn1);
                s[j][3] = ex2f(s[j][3] - mn1);
                su0 += s[j][0] + s[j][1];
                su1 += s[j][2] + s[j][3];
            }
            su0 += __shfl_xor_sync(0xffffffffu, su0, 1);
            su0 += __shfl_xor_sync(0xffffffffu, su0, 2);
            su1 += __shfl_xor_sync(0xffffffffu, su1, 1);
            su1 += __shfl_xor_sync(0xffffffffu, su1, 2);
            l_lo = l_lo * c0 + su0;  l_hi = l_hi * c1 + su1;
            m_lo = mn0;              m_hi = mn1;
            #pragma unroll
            for (int nt = 0; nt < 16; nt++) {
                o[nt][0] *= c0; o[nt][1] *= c0;
                o[nt][2] *= c1; o[nt][3] *= c1;
            }

            #pragma unroll
            for (int ks = 0; ks < 4; ks++) {
                uint32_t ph[4], pl[4];
                split_pack_h(s[2 * ks][0],     s[2 * ks][1],     ph[0], pl[0]);
                split_pack_h(s[2 * ks][2],     s[2 * ks][3],     ph[1], pl[1]);
                split_pack_h(s[2 * ks + 1][0], s[2 * ks + 1][1], ph[2], pl[2]);
                split_pack_h(s[2 * ks + 1][2], s[2 * ks + 1][3], ph[3], pl[3]);
                #pragma unroll
                for (int npp = 0; npp < 4; npp++) {
                    uint32_t vh0[4], vh1[4];
                    uint32_t rv = kb + AT64
                        + (ks * 16 + (lane & 15)) * ATSTR
                        + npp * 64 + ((lane >> 4) << 4);
                    ldsm4t(vh0[0], vh0[1], vh0[2], vh0[3], rv);
                    ldsm4t(vh1[0], vh1[1], vh1[2], vh1[3], rv + 32);
                    float* o0 = o[4 * npp];     float* o1 = o[4 * npp + 1];
                    float* o2 = o[4 * npp + 2]; float* o3 = o[4 * npp + 3];
                    mma16816h(o0, ph, vh0[0], vh0[1]);
                    mma16816h(o1, ph, vh0[2], vh0[3]);
                    mma16816h(o2, ph, vh1[0], vh1[1]);
                    mma16816h(o3, ph, vh1[2], vh1[3]);
                    mma16816h(o0, pl, vh0[0], vh0[1]);
                    mma16816h(o1, pl, vh0[2], vh0[3]);
                    mma16816h(o2, pl, vh1[0], vh1[1]);
                    mma16816h(o3, pl, vh1[2], vh1[3]);
                }
            }
        }
        __syncthreads();
        if (kt + 2 <= ktmax)
            attn_load_kv(sb + 2 * AQ_B + (kt & 1) * AKV_B, tid,
                         Kf_, Vf_, krow0 + (size_t)(kt + 2) * 64, gcol);
    }

    const float i0 = 1.f / l_lo, i1 = 1.f / l_hi;
    const size_t row_lo = qrow0 + w * 16 + rl;
    const size_t row_hi = row_lo + 8;
    const int colb = h * DH + ((lane & 3) << 1);
    #pragma unroll
    for (int nt = 0; nt < 16; nt++) {
        int col = colb + nt * 8;
        uint32_t h0, l0, h1, l1;
        split_pack_h(o[nt][0] * i0, o[nt][1] * i0, h0, l0);
        split_pack_h(o[nt][2] * i1, o[nt][3] * i1, h1, l1);
        *(uint32_t*)&Yh_[row_lo * DD + col] = h0;
        *(uint32_t*)&Yl_[row_lo * DD + col] = l0;
        *(uint32_t*)&Yh_[row_hi * DD + col] = h1;
        *(uint32_t*)&Yl_[row_hi * DD + col] = l1;
    }
}

// ---------------------------------------------------------------------------
extern "C" void kernel_launch(void* const* d_in, const int* in_sizes, int n_in,
                              void* d_out, int out_size)
{
    (void)in_sizes; (void)n_in; (void)out_size;
    const float* X  = (const float*)d_in[0];
    const float* Wq = (const float*)d_in[1];
    const float* bq = (const float*)d_in[2];
    const float* Wk = (const float*)d_in[3];
    const float* bk = (const float*)d_in[4];
    const float* Wv = (const float*)d_in[5];
    const float* bv = (const float*)d_in[6];
    const float* Wo = (const float*)d_in[7];
    const float* bo = (const float*)d_in[8];
    float* out = (float*)d_out;

    __half *Xh16, *Xl16, *Wqkvf, *Wof, *Yh, *Yl, *Qh, *Ql, *Kf, *Vf;
    cudaGetSymbolAddress((void**)&Xh16, g_X_h16);  cudaGetSymbolAddress((void**)&Xl16, g_X_l16);
    cudaGetSymbolAddress((void**)&Wqkvf, g_Wqkv_f);
    cudaGetSymbolAddress((void**)&Qh, g_Q_h16);   cudaGetSymbolAddress((void**)&Ql, g_Q_l16);
    cudaGetSymbolAddress((void**)&Kf, g_K_f);     cudaGetSymbolAddress((void**)&Vf, g_V_f);
    cudaGetSymbolAddress((void**)&Wof, g_Wo_f);
    cudaGetSymbolAddress((void**)&Yh, g_Y_h);     cudaGetSymbolAddress((void**)&Yl, g_Y_l);

    cudaFuncSetAttribute(gemm_qkv16,
                         cudaFuncAttributeMaxDynamicSharedMemorySize, GEMMF_SMEM);
    cudaFuncSetAttribute(gemm_f16,
                         cudaFuncAttributeMaxDynamicSharedMemorySize, GEMMF_SMEM);
    cudaFuncSetAttribute(attn_mma,
                         cudaFuncAttributeMaxDynamicSharedMemorySize, ATTN_SMEM);

    const int nXD = MTOT * DD / 4;
    const int nW  = (2 * DD * DD + 2 * KVD * DD) / 4;
    split_f16<<<(nXD + 255) / 256, 256>>>(X, Xh16, Xl16, nXD);
    conv_f16_all<<<(nW + 255) / 256, 256>>>(Wq, Wk, Wv, Wo, Wqkvf, Wof);

    gemm_qkv16<<<dim3(NQKV / 256, MTOT / 64), 256, GEMMF_SMEM>>>(
        Xh16, Xl16, Wqkvf, bq, bk, bv, Qh, Ql, Kf, Vf);

    attn_mma<<<dim3(TT / 64, BB * HH), 128, ATTN_SMEM>>>(
        Qh, Ql, Kf, Vf, Yh, Yl);

    gemm_f16<<<dim3(DD / 256, MTOT / 64), 256, GEMMF_SMEM>>>(
        Yh, Yl, Wof, bo, out, DD, DD);
}

// round 14
// speedup vs baseline: 3.7330x; 1.0406x over previous
#include <cuda_runtime.h>
#include <cuda_bf16.h>
#include <cuda_fp16.h>
#include <cstdint>

#define BB   2
#define TT   2048
#define DD   4096
#define HH   32
#define GG   8
#define DH   128
#define KVD  (GG*DH)     /* 1024 */
#define NQKV (DD+2*KVD)  /* 6144 */
#define MTOT (BB*TT)     /* 4096 */

// fp16 operands
__device__ __half g_X_h16[(size_t)MTOT * DD], g_X_l16[(size_t)MTOT * DD];
__device__ __half g_Wqkv_f[(size_t)NQKV * DD];
__device__ __half g_Q_h16[(size_t)MTOT * DD], g_Q_l16[(size_t)MTOT * DD];
__device__ __half g_K_f[(size_t)MTOT * KVD];
__device__ __half g_V_f[(size_t)MTOT * KVD];
__device__ __half g_Wo_f[(size_t)DD * DD];
__device__ __half g_Y_h[(size_t)MTOT * DD], g_Y_l[(size_t)MTOT * DD];

// ---------------------------------------------------------------------------
__device__ __forceinline__ uint32_t smem_u32(const void* p) {
    uint32_t a;
    asm("{ .reg .u64 t; cvta.to.shared.u64 t, %1; cvt.u32.u64 %0, t; }"
        : "=r"(a) : "l"(p));
    return a;
}
__device__ __forceinline__ void ldsm4(uint32_t& r0, uint32_t& r1, uint32_t& r2,
                                      uint32_t& r3, uint32_t addr) {
    asm volatile("ldmatrix.sync.aligned.m8n8.x4.shared.b16 {%0,%1,%2,%3}, [%4];"
                 : "=r"(r0), "=r"(r1), "=r"(r2), "=r"(r3) : "r"(addr));
}
__device__ __forceinline__ void ldsm4t(uint32_t& r0, uint32_t& r1, uint32_t& r2,
                                       uint32_t& r3, uint32_t addr) {
    asm volatile("ldmatrix.sync.aligned.m8n8.x4.trans.shared.b16 {%0,%1,%2,%3}, [%4];"
                 : "=r"(r0), "=r"(r1), "=r"(r2), "=r"(r3) : "r"(addr));
}
__device__ __forceinline__ void mma16816h(float* c, const uint32_t* a,
                                          uint32_t b0, uint32_t b1) {
    asm volatile(
        "mma.sync.aligned.m16n8k16.row.col.f32.f16.f16.f32 "
        "{%0,%1,%2,%3}, {%4,%5,%6,%7}, {%8,%9}, {%0,%1,%2,%3};"
        : "+f"(c[0]), "+f"(c[1]), "+f"(c[2]), "+f"(c[3])
        : "r"(a[0]), "r"(a[1]), "r"(a[2]), "r"(a[3]), "r"(b0), "r"(b1));
}
__device__ __forceinline__ void cpasync16(uint32_t dst, const void* src) {
    asm volatile("cp.async.cg.shared.global [%0], [%1], 16;"
                 :: "r"(dst), "l"(src) : "memory");
}
#define CP_COMMIT() asm volatile("cp.async.commit_group;" ::: "memory")
#define CP_WAIT1()  asm volatile("cp.async.wait_group 1;" ::: "memory")
#define CP_WAIT0()  asm volatile("cp.async.wait_group 0;" ::: "memory")

__device__ __forceinline__ float ex2f(float x) {
    float y;
    asm("ex2.approx.ftz.f32 %0, %1;" : "=f"(y) : "f"(x));
    return y;
}
__device__ __forceinline__ void split_pack_h(float a, float b,
                                             uint32_t& h, uint32_t& l) {
    __half2 hb = __floats2half2_rn(a, b);
    float2 bk = __half22float2(hb);
    __half2 lb = __floats2half2_rn(a - bk.x, b - bk.y);
    h = *reinterpret_cast<uint32_t*>(&hb);
    l = *reinterpret_cast<uint32_t*>(&lb);
}

// ---------------------------------------------------------------------------
__global__ void split_f16(const float* __restrict__ x,
                          __half* __restrict__ hi,
                          __half* __restrict__ lo, int n4)
{
    int i = blockIdx.x * blockDim.x + threadIdx.x;
    if (i >= n4) return;
    float4 v = ((const float4*)x)[i];
    uint32_t h0, l0, h1, l1;
    split_pack_h(v.x, v.y, h0, l0);
    split_pack_h(v.z, v.w, h1, l1);
    ((uint32_t*)hi)[2 * i] = h0; ((uint32_t*)hi)[2 * i + 1] = h1;
    ((uint32_t*)lo)[2 * i] = l0; ((uint32_t*)lo)[2 * i + 1] = l1;
}
__global__ void conv_f16_all(const float* __restrict__ wq,
                             const float* __restrict__ wk,
                             const float* __restrict__ wv,
                             const float* __restrict__ wo,
                             __half* __restrict__ qkv, __half* __restrict__ o)
{
    const int nDD = DD * DD / 4, nKD = KVD * DD / 4;
    int i = blockIdx.x * blockDim.x + threadIdx.x;
    const float* src; __half* dst; int j = i;
    if (j < nDD)                { src = wq; dst = qkv; }
    else if ((j -= nDD) < nKD)  { src = wk; dst = qkv + (size_t)DD * DD; }
    else if ((j -= nKD) < nKD)  { src = wv; dst = qkv + (size_t)(DD + KVD) * DD; }
    else if ((j -= nKD) < nDD)  { src = wo; dst = o; }
    else return;
    float4 v = ((const float4*)src)[j];
    __half2 a = __floats2half2_rn(v.x, v.y);
    __half2 b = __floats2half2_rn(v.z, v.w);
    ((uint32_t*)dst)[2 * j]     = *reinterpret_cast<uint32_t*>(&a);
    ((uint32_t*)dst)[2 * j + 1] = *reinterpret_cast<uint32_t*>(&b);
}

// ---------------------------------------------------------------------------
// fp16 2-product GEMM: CTA 128 thr (4 warps), CTA tile 64x256,
// warp tile 64x64, K-chunk 32. 3-stage cp.async, 1 sync/chunk. 2 CTAs/SM.
// ---------------------------------------------------------------------------
#define GK      32
#define A16SUB  (64 * 80)               /* 5120 B  */
#define B16SUB  (256 * 80)              /* 20480 B */
#define STAGE16 (2 * A16SUB + B16SUB)   /* 30720 B */
#define GEMMF_SMEM (3 * STAGE16)        /* 92160 B */

__device__ __forceinline__ void load_stage_f16(
    uint32_t sb, int tid, const __half* ah, const __half* al,
    const __half* b, int K, int k0)
{
    #pragma unroll
    for (int t = 0; t < 12; t++) {
        const int id = t * 128 + tid;          // 0..1535
        if (id < 512) {                         // A hi/lo: 64 rows x 32 cols
            const int x = id & 255;
            const int r = x >> 2, cb = (x & 3) << 4;
            const __half* src = (id < 256 ? ah : al) + (size_t)r * K + k0 + (cb >> 1);
            cpasync16(sb + (id < 256 ? 0u : (uint32_t)A16SUB) + r * 80 + cb, src);
        } else {                                // B: 256 rows x 32 cols
            const int x = id - 512;
            const int r = x >> 2, cb = (x & 3) << 4;
            cpasync16(sb + 2 * A16SUB + r * 80 + cb,
                      b + (size_t)r * K + k0 + (cb >> 1));
        }
    }
}

__device__ __forceinline__ void f16_chunk(
    float acc[4][8][4], uint32_t sb, int wn, int lane)
{
    const int a_row = lane & 15;
    const int a_kb  = (lane >> 4) << 4;
    const int b_row = (lane & 7) + ((lane >> 4) << 3);
    const int b_kb  = ((lane >> 3) & 1) << 4;
    #pragma unroll
    for (int ks = 0; ks < 2; ks++) {
        uint32_t ah[4][4], al[4][4], bh[4][4];
        #pragma unroll
        for (int mt = 0; mt < 4; mt++) {
            uint32_t ra = sb + (mt * 16 + a_row) * 80 + ks * 32 + a_kb;
            ldsm4(ah[mt][0], ah[mt][1], ah[mt][2], ah[mt][3], ra);
            ldsm4(al[mt][0], al[mt][1], al[mt][2], al[mt][3], ra + A16SUB);
        }
        #pragma unroll
        for (int bt = 0; bt < 4; bt++) {
            uint32_t rb = sb + 2 * A16SUB
                        + (wn * 64 + bt * 16 + b_row) * 80
                        + ks * 32 + b_kb;
            ldsm4(bh[bt][0], bh[bt][1], bh[bt][2], bh[bt][3], rb);
        }
        // term hi: 32 independent accumulators
        #pragma unroll
        for (int bt = 0; bt < 4; bt++)
            #pragma unroll
            for (int mt = 0; mt < 4; mt++) {
                mma16816h(acc[mt][bt * 2],     ah[mt], bh[bt][0], bh[bt][1]);
                mma16816h(acc[mt][bt * 2 + 1], ah[mt], bh[bt][2], bh[bt][3]);
            }
        // term lo
        #pragma unroll
        for (int bt = 0; bt < 4; bt++)
            #pragma unroll
            for (int mt = 0; mt < 4; mt++) {
                mma16816h(acc[mt][bt * 2],     al[mt], bh[bt][0], bh[bt][1]);
                mma16816h(acc[mt][bt * 2 + 1], al[mt], bh[bt][2], bh[bt][3]);
            }
    }
}

// 3-stage mainloop shared by both projections
__device__ __forceinline__ void f16_mainloop(
    float acc[4][8][4], uint32_t smem_base, int tid, int wn, int lane,
    const __half* pa, const __half* pl, const __half* pb, int K)
{
    const int nchunks = K / GK;
    load_stage_f16(smem_base,           tid, pa, pl, pb, K, 0);   CP_COMMIT();
    load_stage_f16(smem_base + STAGE16, tid, pa, pl, pb, K, GK);  CP_COMMIT();

    uint32_t buf = 0;
    for (int chunk = 0; chunk < nchunks; chunk++) {
        if (chunk + 1 < nchunks) { CP_WAIT1(); } else { CP_WAIT0(); }
        __syncthreads();
        if (chunk + 2 < nchunks) {
            uint32_t nb = buf + 2 * STAGE16;
            if (nb >= 3 * STAGE16) nb -= 3 * STAGE16;
            load_stage_f16(smem_base + nb, tid, pa, pl, pb, K, (chunk + 2) * GK);
            CP_COMMIT();
        }
        f16_chunk(acc, smem_base + buf, wn, lane);
        buf += STAGE16;
        if (buf == 3 * STAGE16) buf = 0;
    }
}

// ---------------------------------------------------------------------------
// QKV projection: Q -> fp16 hi/lo; K,V -> single fp16
// ---------------------------------------------------------------------------
__global__ __launch_bounds__(128, 2) void gemm_qkv16(
    const __half* __restrict__ Ah, const __half* __restrict__ Al,
    const __half* __restrict__ B,
    const float* __restrict__ bq, const float* __restrict__ bk,
    const float* __restrict__ bv,
    __half* __restrict__ Qh, __half* __restrict__ Ql,
    __half* __restrict__ Kf, __half* __restrict__ Vf)
{
    extern __shared__ char sm_[];
    const uint32_t smem_base = smem_u32(sm_);
    const int tid  = threadIdx.x;
    const int wn   = tid >> 5;             // warp 0..3 -> n quarter
    const int lane = tid & 31;
    const int brow = blockIdx.y << 6;
    const int bcol = blockIdx.x << 8;
    const int K    = DD;

    __half *Ch, *Cl; const float* bias; int outN, obase;
    if (bcol < DD)            { Ch = Qh; Cl = Ql;      bias = bq; outN = DD;  obase = bcol; }
    else if (bcol < DD + KVD) { Ch = Kf; Cl = nullptr; bias = bk; outN = KVD; obase = bcol - DD; }
    else                      { Ch = Vf; Cl = nullptr; bias = bv; outN = KVD; obase = bcol - DD - KVD; }

    const __half* pa = Ah + (size_t)brow * K;
    const __half* pl = Al + (size_t)brow * K;
    const __half* pb = B  + (size_t)bcol * K;

    float acc[4][8][4];
    #pragma unroll
    for (int i = 0; i < 4; i++)
        #pragma unroll
        for (int j = 0; j < 8; j++)
            #pragma unroll
            for (int k = 0; k < 4; k++) acc[i][j][k] = 0.f;

    f16_mainloop(acc, smem_base, tid, wn, lane, pa, pl, pb, K);

    const int crow = lane >> 2;
    const int ccol = (lane & 3) << 1;
    #pragma unroll
    for (int nt = 0; nt < 8; nt++) {
        const int col = obase + wn * 64 + nt * 8 + ccol;
        float b0 = __ldg(&bias[col]), b1 = __ldg(&bias[col + 1]);
        #pragma unroll
        for (int mt = 0; mt < 4; mt++) {
            size_t row0 = (size_t)(brow + mt * 16 + crow);
            float x0 = acc[mt][nt][0] + b0, x1 = acc[mt][nt][1] + b1;
            float x2 = acc[mt][nt][2] + b0, x3 = acc[mt][nt][3] + b1;
            if (Cl) {
                uint32_t h0, l0, h1, l1;
                split_pack_h(x0, x1, h0, l0);
                split_pack_h(x2, x3, h1, l1);
                *(uint32_t*)&Ch[row0 * outN + col]       = h0;
                *(uint32_t*)&Cl[row0 * outN + col]       = l0;
                *(uint32_t*)&Ch[(row0 + 8) * outN + col] = h1;
                *(uint32_t*)&Cl[(row0 + 8) * outN + col] = l1;
            } else {
                __half2 v0 = __floats2half2_rn(x0, x1);
                __half2 v1 = __floats2half2_rn(x2, x3);
                *(uint32_t*)&Ch[row0 * outN + col]       = *reinterpret_cast<uint32_t*>(&v0);
                *(uint32_t*)&Ch[(row0 + 8) * outN + col] = *reinterpret_cast<uint32_t*>(&v1);
            }
        }
    }
}

// ---------------------------------------------------------------------------
// O projection (fp16 2-product) -> fp32 out
// ---------------------------------------------------------------------------
__global__ __launch_bounds__(128, 2) void gemm_f16(
    const __half* __restrict__ Ah, const __half* __restrict__ Al,
    const __half* __restrict__ B,
    const float* __restrict__ bias, float* __restrict__ Cf, int N, int K)
{
    extern __shared__ char sm_[];
    const uint32_t smem_base = smem_u32(sm_);
    const int tid  = threadIdx.x;
    const int wn   = tid >> 5;
    const int lane = tid & 31;
    const int brow = blockIdx.y << 6;
    const int bcol = blockIdx.x << 8;

    const __half* pa = Ah + (size_t)brow * K;
    const __half* pl = Al + (size_t)brow * K;
    const __half* pb = B  + (size_t)bcol * K;

    float acc[4][8][4];
    #pragma unroll
    for (int i = 0; i < 4; i++)
        #pragma unroll
        for (int j = 0; j < 8; j++)
            #pragma unroll
            for (int k = 0; k < 4; k++) acc[i][j][k] = 0.f;

    f16_mainloop(acc, smem_base, tid, wn, lane, pa, pl, pb, K);

    const int crow = lane >> 2;
    const int ccol = (lane & 3) << 1;
    #pragma unroll
    for (int nt = 0; nt < 8; nt++) {
        const int col = bcol + wn * 64 + nt * 8 + ccol;
        float b0 = __ldg(&bias[col]), b1 = __ldg(&bias[col + 1]);
        #pragma unroll
        for (int mt = 0; mt < 4; mt++) {
            size_t row0 = (size_t)(brow + mt * 16 + crow);
            float2 v0 = { acc[mt][nt][0] + b0, acc[mt][nt][1] + b1 };
            float2 v1 = { acc[mt][nt][2] + b0, acc[mt][nt][3] + b1 };
            *(float2*)&Cf[row0 * N + col]       = v0;
            *(float2*)&Cf[(row0 + 8) * N + col] = v1;
        }
    }
}

// ---------------------------------------------------------------------------
// fp16 2-product causal GQA flash attention (unchanged from R12/R13).
// ---------------------------------------------------------------------------
#define ATSTR 272
#define AT64  (64 * ATSTR)
#define AQ_B  AT64
#define AKV_B (2 * AT64)
#define ATTN_SMEM (2 * AQ_B + 2 * AKV_B)

__device__ __forceinline__ void attn_load_kv(
    uint32_t base, int tid,
    const __half* __restrict__ Kf, const __half* __restrict__ Vf,
    size_t grow0, int gcol)
{
    const __half* srcs[2] = { Kf, Vf };
    #pragma unroll
    for (int t = 0; t < 2; t++) {
        const __half* s = srcs[t] + grow0 * KVD + gcol;
        #pragma unroll
        for (int i = 0; i < 8; i++) {
            int ch = tid + i * 128;
            int r = ch >> 4, c = ch & 15;
            cpasync16(base + t * AT64 + r * ATSTR + c * 16,
                      s + (size_t)r * KVD + c * 8);
        }
    }
    CP_COMMIT();
}

__global__ __launch_bounds__(128, 2) void attn_mma(
    const __half* __restrict__ Qh_, const __half* __restrict__ Ql_,
    const __half* __restrict__ Kf_, const __half* __restrict__ Vf_,
    __half* __restrict__ Yh_, __half* __restrict__ Yl_)
{
    extern __shared__ char sm_[];
    const uint32_t sb = smem_u32(sm_);
    const int tid  = threadIdx.x;
    const int lane = tid & 31;
    const int w    = tid >> 5;
    const int qt   = (int)gridDim.x - 1 - (int)blockIdx.x;
    const int bh   = blockIdx.y;
    const int b    = bh >> 5, h = bh & 31, g = h >> 2;
    const int ktmax = qt;
    const size_t qrow0 = (size_t)b * TT + (size_t)qt * 64;
    const size_t krow0 = (size_t)b * TT;
    const int gcol = g * DH;

    {
        const __half* q0 = Qh_ + qrow0 * DD + h * DH;
        const __half* q1 = Ql_ + qrow0 * DD + h * DH;
        #pragma unroll
        for (int i = 0; i < 8; i++) {
            int ch = tid + i * 128;
            int r = ch >> 4, c = ch & 15;
            cpasync16(sb + r * ATSTR + c * 16,        q0 + (size_t)r * DD + c * 8);
            cpasync16(sb + AQ_B + r * ATSTR + c * 16, q1 + (size_t)r * DD + c * 8);
        }
        CP_COMMIT();
    }
    attn_load_kv(sb + 2 * AQ_B, tid, Kf_, Vf_, krow0, gcol);
    if (ktmax >= 1)
        attn_load_kv(sb + 2 * AQ_B + AKV_B, tid, Kf_, Vf_, krow0 + 64, gcol);
    else
        CP_COMMIT();

    float o[16][4];
    #pragma unroll
    for (int i = 0; i < 16; i++)
        #pragma unroll
        for (int j = 0; j < 4; j++) o[i][j] = 0.f;
    float m_lo = -1e30f, m_hi = -1e30f, l_lo = 0.f, l_hi = 0.f;

    const int wrow = qt * 64 + w * 16;
    const int rl   = lane >> 2;
    const float SC = 0.088388347648318447f * 1.4426950408889634f;

    for (int kt = 0; kt <= ktmax; kt++) {
        if (kt < ktmax) { CP_WAIT1(); } else { CP_WAIT0(); }
        __syncthreads();
        const uint32_t kb = sb + 2 * AQ_B + (kt & 1) * AKV_B;

        {
            float s[8][4];
            #pragma unroll
            for (int j = 0; j < 8; j++)
                #pragma unroll
                for (int e = 0; e < 4; e++) s[j][e] = 0.f;

            #pragma unroll
            for (int ks = 0; ks < 8; ks++) {
                uint32_t qh[4], ql[4];
                uint32_t ra = sb + (w * 16 + (lane & 15)) * ATSTR
                            + ks * 32 + ((lane >> 4) << 4);
                ldsm4(qh[0], qh[1], qh[2], qh[3], ra);
                ldsm4(ql[0], ql[1], ql[2], ql[3], ra + AQ_B);
                uint32_t kf[4][4];
                #pragma unroll
                for (int np = 0; np < 4; np++) {
                    uint32_t rb = kb
                        + (np * 16 + (lane & 7) + ((lane >> 4) << 3)) * ATSTR
                        + ks * 32 + (((lane >> 3) & 1) << 4);
                    ldsm4(kf[np][0], kf[np][1], kf[np][2], kf[np][3], rb);
                }
                #pragma unroll
                for (int np = 0; np < 4; np++) {
                    mma16816h(s[2 * np],     qh, kf[np][0], kf[np][1]);
                    mma16816h(s[2 * np + 1], qh, kf[np][2], kf[np][3]);
                }
                #pragma unroll
                for (int np = 0; np < 4; np++) {
                    mma16816h(s[2 * np],     ql, kf[np][0], kf[np][1]);
                    mma16816h(s[2 * np + 1], ql, kf[np][2], kf[np][3]);
                }
            }

            #pragma unroll
            for (int j = 0; j < 8; j++)
                #pragma unroll
                for (int e = 0; e < 4; e++) s[j][e] *= SC;
            if (kt * 64 + 63 > wrow) {
                const int row_lo = wrow + rl, row_hi = row_lo + 8;
                #pragma unroll
                for (int j = 0; j < 8; j++) {
                    int c0 = kt * 64 + j * 8 + ((lane & 3) << 1);
                    if (c0 > row_lo)     s[j][0] = -1e30f;
                    if (c0 + 1 > row_lo) s[j][1] = -1e30f;
                    if (c0 > row_hi)     s[j][2] = -1e30f;
                    if (c0 + 1 > row_hi) s[j][3] = -1e30f;
                }
            }

            float mx0 = -1e30f, mx1 = -1e30f;
            #pragma unroll
            for (int j = 0; j < 8; j++) {
                mx0 = fmaxf(mx0, fmaxf(s[j][0], s[j][1]));
                mx1 = fmaxf(mx1, fmaxf(s[j][2], s[j][3]));
            }
            mx0 = fmaxf(mx0, __shfl_xor_sync(0xffffffffu, mx0, 1));
            mx0 = fmaxf(mx0, __shfl_xor_sync(0xffffffffu, mx0, 2));
            mx1 = fmaxf(mx1, __shfl_xor_sync(0xffffffffu, mx1, 1));
            mx1 = fmaxf(mx1, __shfl_xor_sync(0xffffffffu, mx1, 2));
            float mn0 = fmaxf(m_lo, mx0), mn1 = fmaxf(m_hi, mx1);
            float c0 = ex2f(m_lo - mn0), c1 = ex2f(m_hi - mn1);
            float su0 = 0.f, su1 = 0.f;
            #pragma unroll
            for (int j = 0; j < 8; j++) {
                s[j][0] = ex2f(s[j][0] - mn0);
                s[j][1] = ex2f(s[j][1] - mn0);
                s[j][2] = ex2f(s[j][2] - mn1);
                s[j][3] = ex2f(s[j][3] - mn1);
                su0 += s[j][0] + s[j][1];
                su1 += s[j][2] + s[j][3];
            }
            su0 += __shfl_xor_sync(0xffffffffu, su0, 1);
            su0 += __shfl_xor_sync(0xffffffffu, su0, 2);
            su1 += __shfl_xor_sync(0xffffffffu, su1, 1);
            su1 += __shfl_xor_sync(0xffffffffu, su1, 2);
            l_lo = l_lo * c0 + su0;  l_hi = l_hi * c1 + su1;
            m_lo = mn0;              m_hi = mn1;
            #pragma unroll
            for (int nt = 0; nt < 16; nt++) {
                o[nt][0] *= c0; o[nt][1] *= c0;
                o[nt][2] *= c1; o[nt][3] *= c1;
            }

            #pragma unroll
            for (int ks = 0; ks < 4; ks++) {
                uint32_t ph[4], pl[4];
                split_pack_h(s[2 * ks][0],     s[2 * ks][1],     ph[0], pl[0]);
                split_pack_h(s[2 * ks][2],     s[2 * ks][3],     ph[1], pl[1]);
                split_pack_h(s[2 * ks + 1][0], s[2 * ks + 1][1], ph[2], pl[2]);
                split_pack_h(s[2 * ks + 1][2], s[2 * ks + 1][3], ph[3], pl[3]);
                #pragma unroll
                for (int npp = 0; npp < 4; npp++) {
                    uint32_t vh0[4], vh1[4];
                    uint32_t rv = kb + AT64
                        + (ks * 16 + (lane & 15)) * ATSTR
                        + npp * 64 + ((lane >> 4) << 4);
                    ldsm4t(vh0[0], vh0[1], vh0[2], vh0[3], rv);
                    ldsm4t(vh1[0], vh1[1], vh1[2], vh1[3], rv + 32);
                    float* o0 = o[4 * npp];     float* o1 = o[4 * npp + 1];
                    float* o2 = o[4 * npp + 2]; float* o3 = o[4 * npp + 3];
                    mma16816h(o0, ph, vh0[0], vh0[1]);
                    mma16816h(o1, ph, vh0[2], vh0[3]);
                    mma16816h(o2, ph, vh1[0], vh1[1]);
                    mma16816h(o3, ph, vh1[2], vh1[3]);
                    mma16816h(o0, pl, vh0[0], vh0[1]);
                    mma16816h(o1, pl, vh0[2], vh0[3]);
                    mma16816h(o2, pl, vh1[0], vh1[1]);
                    mma16816h(o3, pl, vh1[2], vh1[3]);
                }
            }
        }
        __syncthreads();
        if (kt + 2 <= ktmax)
            attn_load_kv(sb + 2 * AQ_B + (kt & 1) * AKV_B, tid,
                         Kf_, Vf_, krow0 + (size_t)(kt + 2) * 64, gcol);
    }

    const float i0 = 1.f / l_lo, i1 = 1.f / l_hi;
    const size_t row_lo = qrow0 + w * 16 + rl;
    const size_t row_hi = row_lo + 8;
    const int colb = h * DH + ((lane & 3) << 1);
    #pragma unroll
    for (int nt = 0; nt < 16; nt++) {
        int col = colb + nt * 8;
        uint32_t h0, l0, h1, l1;
        split_pack_h(o[nt][0] * i0, o[nt][1] * i0, h0, l0);
        split_pack_h(o[nt][2] * i1, o[nt][3] * i1, h1, l1);
        *(uint32_t*)&Yh_[row_lo * DD + col] = h0;
        *(uint32_t*)&Yl_[row_lo * DD + col] = l0;
        *(uint32_t*)&Yh_[row_hi * DD + col] = h1;
        *(uint32_t*)&Yl_[row_hi * DD + col] = l1;
    }
}

// ---------------------------------------------------------------------------
extern "C" void kernel_launch(void* const* d_in, const int* in_sizes, int n_in,
                              void* d_out, int out_size)
{
    (void)in_sizes; (void)n_in; (void)out_size;
    const float* X  = (const float*)d_in[0];
    const float* Wq = (const float*)d_in[1];
    const float* bq = (const float*)d_in[2];
    const float* Wk = (const float*)d_in[3];
    const float* bk = (const float*)d_in[4];
    const float* Wv = (const float*)d_in[5];
    const float* bv = (const float*)d_in[6];
    const float* Wo = (const float*)d_in[7];
    const float* bo = (const float*)d_in[8];
    float* out = (float*)d_out;

    __half *Xh16, *Xl16, *Wqkvf, *Wof, *Yh, *Yl, *Qh, *Ql, *Kf, *Vf;
    cudaGetSymbolAddress((void**)&Xh16, g_X_h16);  cudaGetSymbolAddress((void**)&Xl16, g_X_l16);
    cudaGetSymbolAddress((void**)&Wqkvf, g_Wqkv_f);
    cudaGetSymbolAddress((void**)&Qh, g_Q_h16);   cudaGetSymbolAddress((void**)&Ql, g_Q_l16);
    cudaGetSymbolAddress((void**)&Kf, g_K_f);     cudaGetSymbolAddress((void**)&Vf, g_V_f);
    cudaGetSymbolAddress((void**)&Wof, g_Wo_f);
    cudaGetSymbolAddress((void**)&Yh, g_Y_h);     cudaGetSymbolAddress((void**)&Yl, g_Y_l);

    cudaFuncSetAttribute(gemm_qkv16,
                         cudaFuncAttributeMaxDynamicSharedMemorySize, GEMMF_SMEM);
    cudaFuncSetAttribute(gemm_f16,
                         cudaFuncAttributeMaxDynamicSharedMemorySize, GEMMF_SMEM);
    cudaFuncSetAttribute(attn_mma,
                         cudaFuncAttributeMaxDynamicSharedMemorySize, ATTN_SMEM);

    const int nXD = MTOT * DD / 4;
    const int nW  = (2 * DD * DD + 2 * KVD * DD) / 4;
    split_f16<<<(nXD + 255) / 256, 256>>>(X, Xh16, Xl16, nXD);
    conv_f16_all<<<(nW + 255) / 256, 256>>>(Wq, Wk, Wv, Wo, Wqkvf, Wof);

    gemm_qkv16<<<dim3(NQKV / 256, MTOT / 64), 128, GEMMF_SMEM>>>(
        Xh16, Xl16, Wqkvf, bq, bk, bv, Qh, Ql, Kf, Vf);

    attn_mma<<<dim3(TT / 64, BB * HH), 128, ATTN_SMEM>>>(
        Qh, Ql, Kf, Vf, Yh, Yl);

    gemm_f16<<<dim3(DD / 256, MTOT / 64), 128, GEMMF_SMEM>>>(
        Yh, Yl, Wof, bo, out, DD, DD);
}

// round 15
// speedup vs baseline: 4.5634x; 1.2225x over previous
#include <cuda_runtime.h>
#include <cuda_bf16.h>
#include <cuda_fp16.h>
#include <cstdint>

#define BB   2
#define TT   2048
#define DD   4096
#define HH   32
#define GG   8
#define DH   128
#define KVD  (GG*DH)     /* 1024 */
#define NQKV (DD+2*KVD)  /* 6144 */
#define MTOT (BB*TT)     /* 4096 */

// fp16 operands
__device__ __half g_X_h16[(size_t)MTOT * DD], g_X_l16[(size_t)MTOT * DD];
__device__ __half g_Wqkv_f[(size_t)NQKV * DD];
__device__ __half g_Q_h16[(size_t)MTOT * DD], g_Q_l16[(size_t)MTOT * DD];
__device__ __half g_K_f[(size_t)MTOT * KVD];
__device__ __half g_V_f[(size_t)MTOT * KVD];
__device__ __half g_Wo_f[(size_t)DD * DD];
__device__ __half g_Y_f[(size_t)MTOT * DD];

// ---------------------------------------------------------------------------
__device__ __forceinline__ uint32_t smem_u32(const void* p) {
    uint32_t a;
    asm("{ .reg .u64 t; cvta.to.shared.u64 t, %1; cvt.u32.u64 %0, t; }"
        : "=r"(a) : "l"(p));
    return a;
}
__device__ __forceinline__ void ldsm4(uint32_t& r0, uint32_t& r1, uint32_t& r2,
                                      uint32_t& r3, uint32_t addr) {
    asm volatile("ldmatrix.sync.aligned.m8n8.x4.shared.b16 {%0,%1,%2,%3}, [%4];"
                 : "=r"(r0), "=r"(r1), "=r"(r2), "=r"(r3) : "r"(addr));
}
__device__ __forceinline__ void ldsm4t(uint32_t& r0, uint32_t& r1, uint32_t& r2,
                                       uint32_t& r3, uint32_t addr) {
    asm volatile("ldmatrix.sync.aligned.m8n8.x4.trans.shared.b16 {%0,%1,%2,%3}, [%4];"
                 : "=r"(r0), "=r"(r1), "=r"(r2), "=r"(r3) : "r"(addr));
}
__device__ __forceinline__ void mma16816h(float* c, const uint32_t* a,
                                          uint32_t b0, uint32_t b1) {
    asm volatile(
        "mma.sync.aligned.m16n8k16.row.col.f32.f16.f16.f32 "
        "{%0,%1,%2,%3}, {%4,%5,%6,%7}, {%8,%9}, {%0,%1,%2,%3};"
        : "+f"(c[0]), "+f"(c[1]), "+f"(c[2]), "+f"(c[3])
        : "r"(a[0]), "r"(a[1]), "r"(a[2]), "r"(a[3]), "r"(b0), "r"(b1));
}
__device__ __forceinline__ void cpasync16(uint32_t dst, const void* src) {
    asm volatile("cp.async.cg.shared.global [%0], [%1], 16;"
                 :: "r"(dst), "l"(src) : "memory");
}
#define CP_COMMIT() asm volatile("cp.async.commit_group;" ::: "memory")
#define CP_WAIT1()  asm volatile("cp.async.wait_group 1;" ::: "memory")
#define CP_WAIT0()  asm volatile("cp.async.wait_group 0;" ::: "memory")

__device__ __forceinline__ float ex2f(float x) {
    float y;
    asm("ex2.approx.ftz.f32 %0, %1;" : "=f"(y) : "f"(x));
    return y;
}
__device__ __forceinline__ void split_pack_h(float a, float b,
                                             uint32_t& h, uint32_t& l) {
    __half2 hb = __floats2half2_rn(a, b);
    float2 bk = __half22float2(hb);
    __half2 lb = __floats2half2_rn(a - bk.x, b - bk.y);
    h = *reinterpret_cast<uint32_t*>(&hb);
    l = *reinterpret_cast<uint32_t*>(&lb);
}

// ---------------------------------------------------------------------------
__global__ void split_f16(const float* __restrict__ x,
                          __half* __restrict__ hi,
                          __half* __restrict__ lo, int n4)
{
    int i = blockIdx.x * blockDim.x + threadIdx.x;
    if (i >= n4) return;
    float4 v = ((const float4*)x)[i];
    uint32_t h0, l0, h1, l1;
    split_pack_h(v.x, v.y, h0, l0);
    split_pack_h(v.z, v.w, h1, l1);
    ((uint32_t*)hi)[2 * i] = h0; ((uint32_t*)hi)[2 * i + 1] = h1;
    ((uint32_t*)lo)[2 * i] = l0; ((uint32_t*)lo)[2 * i + 1] = l1;
}
__global__ void conv_f16_all(const float* __restrict__ wq,
                             const float* __restrict__ wk,
                             const float* __restrict__ wv,
                             const float* __restrict__ wo,
                             __half* __restrict__ qkv, __half* __restrict__ o)
{
    const int nDD = DD * DD / 4, nKD = KVD * DD / 4;
    int i = blockIdx.x * blockDim.x + threadIdx.x;
    const float* src; __half* dst; int j = i;
    if (j < nDD)                { src = wq; dst = qkv; }
    else if ((j -= nDD) < nKD)  { src = wk; dst = qkv + (size_t)DD * DD; }
    else if ((j -= nKD) < nKD)  { src = wv; dst = qkv + (size_t)(DD + KVD) * DD; }
    else if ((j -= nKD) < nDD)  { src = wo; dst = o; }
    else return;
    float4 v = ((const float4*)src)[j];
    __half2 a = __floats2half2_rn(v.x, v.y);
    __half2 b = __floats2half2_rn(v.z, v.w);
    ((uint32_t*)dst)[2 * j]     = *reinterpret_cast<uint32_t*>(&a);
    ((uint32_t*)dst)[2 * j + 1] = *reinterpret_cast<uint32_t*>(&b);
}

// ---------------------------------------------------------------------------
// Common GEMM geometry: CTA 128 thr (4 warps), CTA tile 64x256,
// warp tile 64x64, K-chunk 32, 3-stage cp.async, 1 sync/chunk, 2 CTAs/SM.
// ---------------------------------------------------------------------------
#define GK      32
#define A16SUB  (64 * 80)               /* 5120 B  */
#define B16SUB  (256 * 80)              /* 20480 B */

// ---- QKV variant: A = (hi,lo) 2 products --------------------------------
#define STAGE_Q (2 * A16SUB + B16SUB)   /* 30720 B */
#define GEMMQ_SMEM (3 * STAGE_Q)        /* 92160 B */

__device__ __forceinline__ void load_stage_q(
    uint32_t sb, int tid, const __half* ah, const __half* al,
    const __half* b, int K, int k0)
{
    #pragma unroll
    for (int t = 0; t < 12; t++) {
        const int id = t * 128 + tid;          // 0..1535
        if (id < 512) {
            const int x = id & 255;
            const int r = x >> 2, cb = (x & 3) << 4;
            const __half* src = (id < 256 ? ah : al) + (size_t)r * K + k0 + (cb >> 1);
            cpasync16(sb + (id < 256 ? 0u : (uint32_t)A16SUB) + r * 80 + cb, src);
        } else {
            const int x = id - 512;
            const int r = x >> 2, cb = (x & 3) << 4;
            cpasync16(sb + 2 * A16SUB + r * 80 + cb,
                      b + (size_t)r * K + k0 + (cb >> 1));
        }
    }
}

__device__ __forceinline__ void q_chunk(
    float acc[4][8][4], uint32_t sb, int wn, int lane)
{
    const int a_row = lane & 15;
    const int a_kb  = (lane >> 4) << 4;
    const int b_row = (lane & 7) + ((lane >> 4) << 3);
    const int b_kb  = ((lane >> 3) & 1) << 4;
    #pragma unroll
    for (int ks = 0; ks < 2; ks++) {
        uint32_t ah[4][4], al[4][4], bh[4][4];
        #pragma unroll
        for (int mt = 0; mt < 4; mt++) {
            uint32_t ra = sb + (mt * 16 + a_row) * 80 + ks * 32 + a_kb;
            ldsm4(ah[mt][0], ah[mt][1], ah[mt][2], ah[mt][3], ra);
            ldsm4(al[mt][0], al[mt][1], al[mt][2], al[mt][3], ra + A16SUB);
        }
        #pragma unroll
        for (int bt = 0; bt < 4; bt++) {
            uint32_t rb = sb + 2 * A16SUB
                        + (wn * 64 + bt * 16 + b_row) * 80
                        + ks * 32 + b_kb;
            ldsm4(bh[bt][0], bh[bt][1], bh[bt][2], bh[bt][3], rb);
        }
        #pragma unroll
        for (int bt = 0; bt < 4; bt++)
            #pragma unroll
            for (int mt = 0; mt < 4; mt++) {
                mma16816h(acc[mt][bt * 2],     ah[mt], bh[bt][0], bh[bt][1]);
                mma16816h(acc[mt][bt * 2 + 1], ah[mt], bh[bt][2], bh[bt][3]);
            }
        #pragma unroll
        for (int bt = 0; bt < 4; bt++)
            #pragma unroll
            for (int mt = 0; mt < 4; mt++) {
                mma16816h(acc[mt][bt * 2],     al[mt], bh[bt][0], bh[bt][1]);
                mma16816h(acc[mt][bt * 2 + 1], al[mt], bh[bt][2], bh[bt][3]);
            }
    }
}

// ---- O variant: A single, 1 product --------------------------------------
#define STAGE_O (A16SUB + B16SUB)       /* 25600 B */
#define GEMMO_SMEM (3 * STAGE_O)        /* 76800 B */

__device__ __forceinline__ void load_stage_o(
    uint32_t sb, int tid, const __half* a, const __half* b, int K, int k0)
{
    #pragma unroll
    for (int t = 0; t < 10; t++) {
        const int id = t * 128 + tid;          // 0..1279
        if (id < 256) {
            const int r = id >> 2, cb = (id & 3) << 4;
            cpasync16(sb + r * 80 + cb, a + (size_t)r * K + k0 + (cb >> 1));
        } else {
            const int x = id - 256;
            const int r = x >> 2, cb = (x & 3) << 4;
            cpasync16(sb + A16SUB + r * 80 + cb,
                      b + (size_t)r * K + k0 + (cb >> 1));
        }
    }
}

__device__ __forceinline__ void o_chunk(
    float acc[4][8][4], uint32_t sb, int wn, int lane)
{
    const int a_row = lane & 15;
    const int a_kb  = (lane >> 4) << 4;
    const int b_row = (lane & 7) + ((lane >> 4) << 3);
    const int b_kb  = ((lane >> 3) & 1) << 4;
    #pragma unroll
    for (int ks = 0; ks < 2; ks++) {
        uint32_t ah[4][4], bh[4][4];
        #pragma unroll
        for (int mt = 0; mt < 4; mt++) {
            uint32_t ra = sb + (mt * 16 + a_row) * 80 + ks * 32 + a_kb;
            ldsm4(ah[mt][0], ah[mt][1], ah[mt][2], ah[mt][3], ra);
        }
        #pragma unroll
        for (int bt = 0; bt < 4; bt++) {
            uint32_t rb = sb + A16SUB
                        + (wn * 64 + bt * 16 + b_row) * 80
                        + ks * 32 + b_kb;
            ldsm4(bh[bt][0], bh[bt][1], bh[bt][2], bh[bt][3], rb);
        }
        #pragma unroll
        for (int bt = 0; bt < 4; bt++)
            #pragma unroll
            for (int mt = 0; mt < 4; mt++) {
                mma16816h(acc[mt][bt * 2],     ah[mt], bh[bt][0], bh[bt][1]);
                mma16816h(acc[mt][bt * 2 + 1], ah[mt], bh[bt][2], bh[bt][3]);
            }
    }
}

// ---------------------------------------------------------------------------
// QKV projection: Q -> fp16 hi/lo; K,V -> single fp16
// ---------------------------------------------------------------------------
__global__ __launch_bounds__(128, 2) void gemm_qkv16(
    const __half* __restrict__ Ah, const __half* __restrict__ Al,
    const __half* __restrict__ B,
    const float* __restrict__ bq, const float* __restrict__ bk,
    const float* __restrict__ bv,
    __half* __restrict__ Qh, __half* __restrict__ Ql,
    __half* __restrict__ Kf, __half* __restrict__ Vf)
{
    extern __shared__ char sm_[];
    const uint32_t smem_base = smem_u32(sm_);
    const int tid  = threadIdx.x;
    const int wn   = tid >> 5;
    const int lane = tid & 31;
    const int brow = blockIdx.y << 6;
    const int bcol = blockIdx.x << 8;
    const int K    = DD;

    __half *Ch, *Cl; const float* bias; int outN, obase;
    if (bcol < DD)            { Ch = Qh; Cl = Ql;      bias = bq; outN = DD;  obase = bcol; }
    else if (bcol < DD + KVD) { Ch = Kf; Cl = nullptr; bias = bk; outN = KVD; obase = bcol - DD; }
    else                      { Ch = Vf; Cl = nullptr; bias = bv; outN = KVD; obase = bcol - DD - KVD; }

    const __half* pa = Ah + (size_t)brow * K;
    const __half* pl = Al + (size_t)brow * K;
    const __half* pb = B  + (size_t)bcol * K;

    float acc[4][8][4];
    #pragma unroll
    for (int i = 0; i < 4; i++)
        #pragma unroll
        for (int j = 0; j < 8; j++)
            #pragma unroll
            for (int k = 0; k < 4; k++) acc[i][j][k] = 0.f;

    const int nchunks = K / GK;
    load_stage_q(smem_base,           tid, pa, pl, pb, K, 0);   CP_COMMIT();
    load_stage_q(smem_base + STAGE_Q, tid, pa, pl, pb, K, GK);  CP_COMMIT();

    uint32_t buf = 0;
    for (int chunk = 0; chunk < nchunks; chunk++) {
        if (chunk + 1 < nchunks) { CP_WAIT1(); } else { CP_WAIT0(); }
        __syncthreads();
        if (chunk + 2 < nchunks) {
            uint32_t nb = buf + 2 * STAGE_Q;
            if (nb >= 3 * STAGE_Q) nb -= 3 * STAGE_Q;
            load_stage_q(smem_base + nb, tid, pa, pl, pb, K, (chunk + 2) * GK);
            CP_COMMIT();
        }
        q_chunk(acc, smem_base + buf, wn, lane);
        buf += STAGE_Q;
        if (buf == 3 * STAGE_Q) buf = 0;
    }

    const int crow = lane >> 2;
    const int ccol = (lane & 3) << 1;
    #pragma unroll
    for (int nt = 0; nt < 8; nt++) {
        const int col = obase + wn * 64 + nt * 8 + ccol;
        float b0 = __ldg(&bias[col]), b1 = __ldg(&bias[col + 1]);
        #pragma unroll
        for (int mt = 0; mt < 4; mt++) {
            size_t row0 = (size_t)(brow + mt * 16 + crow);
            float x0 = acc[mt][nt][0] + b0, x1 = acc[mt][nt][1] + b1;
            float x2 = acc[mt][nt][2] + b0, x3 = acc[mt][nt][3] + b1;
            if (Cl) {
                uint32_t h0, l0, h1, l1;
                split_pack_h(x0, x1, h0, l0);
                split_pack_h(x2, x3, h1, l1);
                *(uint32_t*)&Ch[row0 * outN + col]       = h0;
                *(uint32_t*)&Cl[row0 * outN + col]       = l0;
                *(uint32_t*)&Ch[(row0 + 8) * outN + col] = h1;
                *(uint32_t*)&Cl[(row0 + 8) * outN + col] = l1;
            } else {
                __half2 v0 = __floats2half2_rn(x0, x1);
                __half2 v1 = __floats2half2_rn(x2, x3);
                *(uint32_t*)&Ch[row0 * outN + col]       = *reinterpret_cast<uint32_t*>(&v0);
                *(uint32_t*)&Ch[(row0 + 8) * outN + col] = *reinterpret_cast<uint32_t*>(&v1);
            }
        }
    }
}

// ---------------------------------------------------------------------------
// O projection (fp16 SINGLE product) -> fp32 out
// ---------------------------------------------------------------------------
__global__ __launch_bounds__(128, 2) void gemm_o16(
    const __half* __restrict__ A, const __half* __restrict__ B,
    const float* __restrict__ bias, float* __restrict__ Cf, int N, int K)
{
    extern __shared__ char sm_[];
    const uint32_t smem_base = smem_u32(sm_);
    const int tid  = threadIdx.x;
    const int wn   = tid >> 5;
    const int lane = tid & 31;
    const int brow = blockIdx.y << 6;
    const int bcol = blockIdx.x << 8;

    const __half* pa = A + (size_t)brow * K;
    const __half* pb = B + (size_t)bcol * K;

    float acc[4][8][4];
    #pragma unroll
    for (int i = 0; i < 4; i++)
        #pragma unroll
        for (int j = 0; j < 8; j++)
            #pragma unroll
            for (int k = 0; k < 4; k++) acc[i][j][k] = 0.f;

    const int nchunks = K / GK;
    load_stage_o(smem_base,           tid, pa, pb, K, 0);   CP_COMMIT();
    load_stage_o(smem_base + STAGE_O, tid, pa, pb, K, GK);  CP_COMMIT();

    uint32_t buf = 0;
    for (int chunk = 0; chunk < nchunks; chunk++) {
        if (chunk + 1 < nchunks) { CP_WAIT1(); } else { CP_WAIT0(); }
        __syncthreads();
        if (chunk + 2 < nchunks) {
            uint32_t nb = buf + 2 * STAGE_O;
            if (nb >= 3 * STAGE_O) nb -= 3 * STAGE_O;
            load_stage_o(smem_base + nb, tid, pa, pb, K, (chunk + 2) * GK);
            CP_COMMIT();
        }
        o_chunk(acc, smem_base + buf, wn, lane);
        buf += STAGE_O;
        if (buf == 3 * STAGE_O) buf = 0;
    }

    const int crow = lane >> 2;
    const int ccol = (lane & 3) << 1;
    #pragma unroll
    for (int nt = 0; nt < 8; nt++) {
        const int col = bcol + wn * 64 + nt * 8 + ccol;
        float b0 = __ldg(&bias[col]), b1 = __ldg(&bias[col + 1]);
        #pragma unroll
        for (int mt = 0; mt < 4; mt++) {
            size_t row0 = (size_t)(brow + mt * 16 + crow);
            float2 v0 = { acc[mt][nt][0] + b0, acc[mt][nt][1] + b1 };
            float2 v1 = { acc[mt][nt][2] + b0, acc[mt][nt][3] + b1 };
            *(float2*)&Cf[row0 * N + col]       = v0;
            *(float2*)&Cf[(row0 + 8) * N + col] = v1;
        }
    }
}

// ---------------------------------------------------------------------------
// fp16 causal GQA flash attention. Q hi/lo (2-product QK); P single (1-product
// PV); Y single fp16 out. CTA 128 thr, q-tile 64, 2 CTAs/SM.
// ---------------------------------------------------------------------------
#define ATSTR 272
#define AT64  (64 * ATSTR)
#define AQ_B  AT64
#define AKV_B (2 * AT64)
#define ATTN_SMEM (2 * AQ_B + 2 * AKV_B)

__device__ __forceinline__ void attn_load_kv(
    uint32_t base, int tid,
    const __half* __restrict__ Kf, const __half* __restrict__ Vf,
    size_t grow0, int gcol)
{
    const __half* srcs[2] = { Kf, Vf };
    #pragma unroll
    for (int t = 0; t < 2; t++) {
        const __half* s = srcs[t] + grow0 * KVD + gcol;
        #pragma unroll
        for (int i = 0; i < 8; i++) {
            int ch = tid + i * 128;
            int r = ch >> 4, c = ch & 15;
            cpasync16(base + t * AT64 + r * ATSTR + c * 16,
                      s + (size_t)r * KVD + c * 8);
        }
    }
    CP_COMMIT();
}

__global__ __launch_bounds__(128, 2) void attn_mma(
    const __half* __restrict__ Qh_, const __half* __restrict__ Ql_,
    const __half* __restrict__ Kf_, const __half* __restrict__ Vf_,
    __half* __restrict__ Yf_)
{
    extern __shared__ char sm_[];
    const uint32_t sb = smem_u32(sm_);
    const int tid  = threadIdx.x;
    const int lane = tid & 31;
    const int w    = tid >> 5;
    const int qt   = (int)gridDim.x - 1 - (int)blockIdx.x;
    const int bh   = blockIdx.y;
    const int b    = bh >> 5, h = bh & 31, g = h >> 2;
    const int ktmax = qt;
    const size_t qrow0 = (size_t)b * TT + (size_t)qt * 64;
    const size_t krow0 = (size_t)b * TT;
    const int gcol = g * DH;

    {
        const __half* q0 = Qh_ + qrow0 * DD + h * DH;
        const __half* q1 = Ql_ + qrow0 * DD + h * DH;
        #pragma unroll
        for (int i = 0; i < 8; i++) {
            int ch = tid + i * 128;
            int r = ch >> 4, c = ch & 15;
            cpasync16(sb + r * ATSTR + c * 16,        q0 + (size_t)r * DD + c * 8);
            cpasync16(sb + AQ_B + r * ATSTR + c * 16, q1 + (size_t)r * DD + c * 8);
        }
        CP_COMMIT();
    }
    attn_load_kv(sb + 2 * AQ_B, tid, Kf_, Vf_, krow0, gcol);
    if (ktmax >= 1)
        attn_load_kv(sb + 2 * AQ_B + AKV_B, tid, Kf_, Vf_, krow0 + 64, gcol);
    else
        CP_COMMIT();

    float o[16][4];
    #pragma unroll
    for (int i = 0; i < 16; i++)
        #pragma unroll
        for (int j = 0; j < 4; j++) o[i][j] = 0.f;
    float m_lo = -1e30f, m_hi = -1e30f, l_lo = 0.f, l_hi = 0.f;

    const int wrow = qt * 64 + w * 16;
    const int rl   = lane >> 2;
    const float SC = 0.088388347648318447f * 1.4426950408889634f;

    for (int kt = 0; kt <= ktmax; kt++) {
        if (kt < ktmax) { CP_WAIT1(); } else { CP_WAIT0(); }
        __syncthreads();
        const uint32_t kb = sb + 2 * AQ_B + (kt & 1) * AKV_B;

        {
            float s[8][4];
            #pragma unroll
            for (int j = 0; j < 8; j++)
                #pragma unroll
                for (int e = 0; e < 4; e++) s[j][e] = 0.f;

            // ---- S = Q K^T (2-product) ----
            #pragma unroll
            for (int ks = 0; ks < 8; ks++) {
                uint32_t qh[4], ql[4];
                uint32_t ra = sb + (w * 16 + (lane & 15)) * ATSTR
                            + ks * 32 + ((lane >> 4) << 4);
                ldsm4(qh[0], qh[1], qh[2], qh[3], ra);
                ldsm4(ql[0], ql[1], ql[2], ql[3], ra + AQ_B);
                uint32_t kf[4][4];
                #pragma unroll
                for (int np = 0; np < 4; np++) {
                    uint32_t rb = kb
                        + (np * 16 + (lane & 7) + ((lane >> 4) << 3)) * ATSTR
                        + ks * 32 + (((lane >> 3) & 1) << 4);
                    ldsm4(kf[np][0], kf[np][1], kf[np][2], kf[np][3], rb);
                }
                #pragma unroll
                for (int np = 0; np < 4; np++) {
                    mma16816h(s[2 * np],     qh, kf[np][0], kf[np][1]);
                    mma16816h(s[2 * np + 1], qh, kf[np][2], kf[np][3]);
                }
                #pragma unroll
                for (int np = 0; np < 4; np++) {
                    mma16816h(s[2 * np],     ql, kf[np][0], kf[np][1]);
                    mma16816h(s[2 * np + 1], ql, kf[np][2], kf[np][3]);
                }
            }

            #pragma unroll
            for (int j = 0; j < 8; j++)
                #pragma unroll
                for (int e = 0; e < 4; e++) s[j][e] *= SC;
            if (kt * 64 + 63 > wrow) {
                const int row_lo = wrow + rl, row_hi = row_lo + 8;
                #pragma unroll
                for (int j = 0; j < 8; j++) {
                    int c0 = kt * 64 + j * 8 + ((lane & 3) << 1);
                    if (c0 > row_lo)     s[j][0] = -1e30f;
                    if (c0 + 1 > row_lo) s[j][1] = -1e30f;
                    if (c0 > row_hi)     s[j][2] = -1e30f;
                    if (c0 + 1 > row_hi) s[j][3] = -1e30f;
                }
            }

            float mx0 = -1e30f, mx1 = -1e30f;
            #pragma unroll
            for (int j = 0; j < 8; j++) {
                mx0 = fmaxf(mx0, fmaxf(s[j][0], s[j][1]));
                mx1 = fmaxf(mx1, fmaxf(s[j][2], s[j][3]));
            }
            mx0 = fmaxf(mx0, __shfl_xor_sync(0xffffffffu, mx0, 1));
            mx0 = fmaxf(mx0, __shfl_xor_sync(0xffffffffu, mx0, 2));
            mx1 = fmaxf(mx1, __shfl_xor_sync(0xffffffffu, mx1, 1));
            mx1 = fmaxf(mx1, __shfl_xor_sync(0xffffffffu, mx1, 2));
            float mn0 = fmaxf(m_lo, mx0), mn1 = fmaxf(m_hi, mx1);
            float c0 = ex2f(m_lo - mn0), c1 = ex2f(m_hi - mn1);
            float su0 = 0.f, su1 = 0.f;
            #pragma unroll
            for (int j = 0; j < 8; j++) {
                s[j][0] = ex2f(s[j][0] - mn0);
                s[j][1] = ex2f(s[j][1] - mn0);
                s[j][2] = ex2f(s[j][2] - mn1);
                s[j][3] = ex2f(s[j][3] - mn1);
                su0 += s[j][0] + s[j][1];
                su1 += s[j][2] + s[j][3];
            }
            su0 += __shfl_xor_sync(0xffffffffu, su0, 1);
            su0 += __shfl_xor_sync(0xffffffffu, su0, 2);
            su1 += __shfl_xor_sync(0xffffffffu, su1, 1);
            su1 += __shfl_xor_sync(0xffffffffu, su1, 2);
            l_lo = l_lo * c0 + su0;  l_hi = l_hi * c1 + su1;
            m_lo = mn0;              m_hi = mn1;
            #pragma unroll
            for (int nt = 0; nt < 16; nt++) {
                o[nt][0] *= c0; o[nt][1] *= c0;
                o[nt][2] *= c1; o[nt][3] *= c1;
            }

            // ---- O += P V (single P product) ----
            #pragma unroll
            for (int ks = 0; ks < 4; ks++) {
                uint32_t ph[4];
                __half2 p0 = __floats2half2_rn(s[2 * ks][0],     s[2 * ks][1]);
                __half2 p1 = __floats2half2_rn(s[2 * ks][2],     s[2 * ks][3]);
                __half2 p2 = __floats2half2_rn(s[2 * ks + 1][0], s[2 * ks + 1][1]);
                __half2 p3 = __floats2half2_rn(s[2 * ks + 1][2], s[2 * ks + 1][3]);
                ph[0] = *reinterpret_cast<uint32_t*>(&p0);
                ph[1] = *reinterpret_cast<uint32_t*>(&p1);
                ph[2] = *reinterpret_cast<uint32_t*>(&p2);
                ph[3] = *reinterpret_cast<uint32_t*>(&p3);
                #pragma unroll
                for (int npp = 0; npp < 4; npp++) {
                    uint32_t vh0[4], vh1[4];
                    uint32_t rv = kb + AT64
                        + (ks * 16 + (lane & 15)) * ATSTR
                        + npp * 64 + ((lane >> 4) << 4);
                    ldsm4t(vh0[0], vh0[1], vh0[2], vh0[3], rv);
                    ldsm4t(vh1[0], vh1[1], vh1[2], vh1[3], rv + 32);
                    mma16816h(o[4 * npp],     ph, vh0[0], vh0[1]);
                    mma16816h(o[4 * npp + 1], ph, vh0[2], vh0[3]);
                    mma16816h(o[4 * npp + 2], ph, vh1[0], vh1[1]);
                    mma16816h(o[4 * npp + 3], ph, vh1[2], vh1[3]);
                }
            }
        }
        __syncthreads();
        if (kt + 2 <= ktmax)
            attn_load_kv(sb + 2 * AQ_B + (kt & 1) * AKV_B, tid,
                         Kf_, Vf_, krow0 + (size_t)(kt + 2) * 64, gcol);
    }

    const float i0 = 1.f / l_lo, i1 = 1.f / l_hi;
    const size_t row_lo = qrow0 + w * 16 + rl;
    const size_t row_hi = row_lo + 8;
    const int colb = h * DH + ((lane & 3) << 1);
    #pragma unroll
    for (int nt = 0; nt < 16; nt++) {
        int col = colb + nt * 8;
        __half2 y0 = __floats2half2_rn(o[nt][0] * i0, o[nt][1] * i0);
        __half2 y1 = __floats2half2_rn(o[nt][2] * i1, o[nt][3] * i1);
        *(uint32_t*)&Yf_[row_lo * DD + col] = *reinterpret_cast<uint32_t*>(&y0);
        *(uint32_t*)&Yf_[row_hi * DD + col] = *reinterpret_cast<uint32_t*>(&y1);
    }
}

// ---------------------------------------------------------------------------
extern "C" void kernel_launch(void* const* d_in, const int* in_sizes, int n_in,
                              void* d_out, int out_size)
{
    (void)in_sizes; (void)n_in; (void)out_size;
    const float* X  = (const float*)d_in[0];
    const float* Wq = (const float*)d_in[1];
    const float* bq = (const float*)d_in[2];
    const float* Wk = (const float*)d_in[3];
    const float* bk = (const float*)d_in[4];
    const float* Wv = (const float*)d_in[5];
    const float* bv = (const float*)d_in[6];
    const float* Wo = (const float*)d_in[7];
    const float* bo = (const float*)d_in[8];
    float* out = (float*)d_out;

    __half *Xh16, *Xl16, *Wqkvf, *Wof, *Yf, *Qh, *Ql, *Kf, *Vf;
    cudaGetSymbolAddress((void**)&Xh16, g_X_h16);  cudaGetSymbolAddress((void**)&Xl16, g_X_l16);
    cudaGetSymbolAddress((void**)&Wqkvf, g_Wqkv_f);
    cudaGetSymbolAddress((void**)&Qh, g_Q_h16);   cudaGetSymbolAddress((void**)&Ql, g_Q_l16);
    cudaGetSymbolAddress((void**)&Kf, g_K_f);     cudaGetSymbolAddress((void**)&Vf, g_V_f);
    cudaGetSymbolAddress((void**)&Wof, g_Wo_f);
    cudaGetSymbolAddress((void**)&Yf, g_Y_f);

    cudaFuncSetAttribute(gemm_qkv16,
                         cudaFuncAttributeMaxDynamicSharedMemorySize, GEMMQ_SMEM);
    cudaFuncSetAttribute(gemm_o16,
                         cudaFuncAttributeMaxDynamicSharedMemorySize, GEMMO_SMEM);
    cudaFuncSetAttribute(attn_mma,
                         cudaFuncAttributeMaxDynamicSharedMemorySize, ATTN_SMEM);

    const int nXD = MTOT * DD / 4;
    const int nW  = (2 * DD * DD + 2 * KVD * DD) / 4;
    split_f16<<<(nXD + 255) / 256, 256>>>(X, Xh16, Xl16, nXD);
    conv_f16_all<<<(nW + 255) / 256, 256>>>(Wq, Wk, Wv, Wo, Wqkvf, Wof);

    gemm_qkv16<<<dim3(NQKV / 256, MTOT / 64), 128, GEMMQ_SMEM>>>(
        Xh16, Xl16, Wqkvf, bq, bk, bv, Qh, Ql, Kf, Vf);

    attn_mma<<<dim3(TT / 64, BB * HH), 128, ATTN_SMEM>>>(
        Qh, Ql, Kf, Vf, Yf);

    gemm_o16<<<dim3(DD / 256, MTOT / 64), 128, GEMMO_SMEM>>>(
        Yf, Wof, bo, out, DD, DD);
}

// round 16
// speedup vs baseline: 5.9981x; 1.3144x over previous
#include <cuda_runtime.h>
#include <cuda_bf16.h>
#include <cuda_fp16.h>
#include <cstdint>

#define BB   2
#define TT   2048
#define DD   4096
#define HH   32
#define GG   8
#define DH   128
#define KVD  (GG*DH)     /* 1024 */
#define NQKV (DD+2*KVD)  /* 6144 */
#define MTOT (BB*TT)     /* 4096 */

// fp16 operands
__device__ __half g_X_f[(size_t)MTOT * DD];
__device__ __half g_Wqkv_f[(size_t)NQKV * DD];
__device__ __half g_Q_h16[(size_t)MTOT * DD], g_Q_l16[(size_t)MTOT * DD];
__device__ __half g_K_f[(size_t)MTOT * KVD];
__device__ __half g_V_f[(size_t)MTOT * KVD];
__device__ __half g_Wo_f[(size_t)DD * DD];
__device__ __half g_Y_f[(size_t)MTOT * DD];

// ---------------------------------------------------------------------------
__device__ __forceinline__ uint32_t smem_u32(const void* p) {
    uint32_t a;
    asm("{ .reg .u64 t; cvta.to.shared.u64 t, %1; cvt.u32.u64 %0, t; }"
        : "=r"(a) : "l"(p));
    return a;
}
__device__ __forceinline__ void ldsm4(uint32_t& r0, uint32_t& r1, uint32_t& r2,
                                      uint32_t& r3, uint32_t addr) {
    asm volatile("ldmatrix.sync.aligned.m8n8.x4.shared.b16 {%0,%1,%2,%3}, [%4];"
                 : "=r"(r0), "=r"(r1), "=r"(r2), "=r"(r3) : "r"(addr));
}
__device__ __forceinline__ void ldsm4t(uint32_t& r0, uint32_t& r1, uint32_t& r2,
                                       uint32_t& r3, uint32_t addr) {
    asm volatile("ldmatrix.sync.aligned.m8n8.x4.trans.shared.b16 {%0,%1,%2,%3}, [%4];"
                 : "=r"(r0), "=r"(r1), "=r"(r2), "=r"(r3) : "r"(addr));
}
__device__ __forceinline__ void mma16816h(float* c, const uint32_t* a,
                                          uint32_t b0, uint32_t b1) {
    asm volatile(
        "mma.sync.aligned.m16n8k16.row.col.f32.f16.f16.f32 "
        "{%0,%1,%2,%3}, {%4,%5,%6,%7}, {%8,%9}, {%0,%1,%2,%3};"
        : "+f"(c[0]), "+f"(c[1]), "+f"(c[2]), "+f"(c[3])
        : "r"(a[0]), "r"(a[1]), "r"(a[2]), "r"(a[3]), "r"(b0), "r"(b1));
}
__device__ __forceinline__ void cpasync16(uint32_t dst, const void* src) {
    asm volatile("cp.async.cg.shared.global [%0], [%1], 16;"
                 :: "r"(dst), "l"(src) : "memory");
}
#define CP_COMMIT() asm volatile("cp.async.commit_group;" ::: "memory")
#define CP_WAIT1()  asm volatile("cp.async.wait_group 1;" ::: "memory")
#define CP_WAIT0()  asm volatile("cp.async.wait_group 0;" ::: "memory")

__device__ __forceinline__ float ex2f(float x) {
    float y;
    asm("ex2.approx.ftz.f32 %0, %1;" : "=f"(y) : "f"(x));
    return y;
}
__device__ __forceinline__ void split_pack_h(float a, float b,
                                             uint32_t& h, uint32_t& l) {
    __half2 hb = __floats2half2_rn(a, b);
    float2 bk = __half22float2(hb);
    __half2 lb = __floats2half2_rn(a - bk.x, b - bk.y);
    h = *reinterpret_cast<uint32_t*>(&hb);
    l = *reinterpret_cast<uint32_t*>(&lb);
}

// ---------------------------------------------------------------------------
// all fp32->fp16 conversions (X + 4 weights) in one launch
__global__ void conv_f16_all(const float* __restrict__ x,
                             const float* __restrict__ wq,
                             const float* __restrict__ wk,
                             const float* __restrict__ wv,
                             const float* __restrict__ wo,
                             __half* __restrict__ xf,
                             __half* __restrict__ qkv, __half* __restrict__ o)
{
    const int nXD = MTOT * DD / 4, nDD = DD * DD / 4, nKD = KVD * DD / 4;
    int i = blockIdx.x * blockDim.x + threadIdx.x;
    const float* src; __half* dst; int j = i;
    if (j < nXD)                { src = x;  dst = xf; }
    else if ((j -= nXD) < nDD)  { src = wq; dst = qkv; }
    else if ((j -= nDD) < nKD)  { src = wk; dst = qkv + (size_t)DD * DD; }
    else if ((j -= nKD) < nKD)  { src = wv; dst = qkv + (size_t)(DD + KVD) * DD; }
    else if ((j -= nKD) < nDD)  { src = wo; dst = o; }
    else return;
    float4 v = ((const float4*)src)[j];
    __half2 a = __floats2half2_rn(v.x, v.y);
    __half2 b = __floats2half2_rn(v.z, v.w);
    ((uint32_t*)dst)[2 * j]     = *reinterpret_cast<uint32_t*>(&a);
    ((uint32_t*)dst)[2 * j + 1] = *reinterpret_cast<uint32_t*>(&b);
}

// ---------------------------------------------------------------------------
// Single-product fp16 GEMM core: CTA 128 thr (4 warps), CTA tile 64x256,
// warp tile 64x64, K-chunk 32, 3-stage cp.async, 1 sync/chunk, 2 CTAs/SM.
// ---------------------------------------------------------------------------
#define GK      32
#define A16SUB  (64 * 80)               /* 5120 B  */
#define B16SUB  (256 * 80)              /* 20480 B */
#define STAGE_O (A16SUB + B16SUB)       /* 25600 B */
#define GEMMO_SMEM (3 * STAGE_O)        /* 76800 B */

__device__ __forceinline__ void load_stage_o(
    uint32_t sb, int tid, const __half* a, const __half* b, int K, int k0)
{
    #pragma unroll
    for (int t = 0; t < 10; t++) {
        const int id = t * 128 + tid;          // 0..1279
        if (id < 256) {
            const int r = id >> 2, cb = (id & 3) << 4;
            cpasync16(sb + r * 80 + cb, a + (size_t)r * K + k0 + (cb >> 1));
        } else {
            const int x = id - 256;
            const int r = x >> 2, cb = (x & 3) << 4;
            cpasync16(sb + A16SUB + r * 80 + cb,
                      b + (size_t)r * K + k0 + (cb >> 1));
        }
    }
}

__device__ __forceinline__ void o_chunk(
    float acc[4][8][4], uint32_t sb, int wn, int lane)
{
    const int a_row = lane & 15;
    const int a_kb  = (lane >> 4) << 4;
    const int b_row = (lane & 7) + ((lane >> 4) << 3);
    const int b_kb  = ((lane >> 3) & 1) << 4;
    #pragma unroll
    for (int ks = 0; ks < 2; ks++) {
        uint32_t ah[4][4], bh[4][4];
        #pragma unroll
        for (int mt = 0; mt < 4; mt++) {
            uint32_t ra = sb + (mt * 16 + a_row) * 80 + ks * 32 + a_kb;
            ldsm4(ah[mt][0], ah[mt][1], ah[mt][2], ah[mt][3], ra);
        }
        #pragma unroll
        for (int bt = 0; bt < 4; bt++) {
            uint32_t rb = sb + A16SUB
                        + (wn * 64 + bt * 16 + b_row) * 80
                        + ks * 32 + b_kb;
            ldsm4(bh[bt][0], bh[bt][1], bh[bt][2], bh[bt][3], rb);
        }
        #pragma unroll
        for (int bt = 0; bt < 4; bt++)
            #pragma unroll
            for (int mt = 0; mt < 4; mt++) {
                mma16816h(acc[mt][bt * 2],     ah[mt], bh[bt][0], bh[bt][1]);
                mma16816h(acc[mt][bt * 2 + 1], ah[mt], bh[bt][2], bh[bt][3]);
            }
    }
}

__device__ __forceinline__ void o_mainloop(
    float acc[4][8][4], uint32_t smem_base, int tid, int wn, int lane,
    const __half* pa, const __half* pb, int K)
{
    const int nchunks = K / GK;
    load_stage_o(smem_base,           tid, pa, pb, K, 0);   CP_COMMIT();
    load_stage_o(smem_base + STAGE_O, tid, pa, pb, K, GK);  CP_COMMIT();

    uint32_t buf = 0;
    for (int chunk = 0; chunk < nchunks; chunk++) {
        if (chunk + 1 < nchunks) { CP_WAIT1(); } else { CP_WAIT0(); }
        __syncthreads();
        if (chunk + 2 < nchunks) {
            uint32_t nb = buf + 2 * STAGE_O;
            if (nb >= 3 * STAGE_O) nb -= 3 * STAGE_O;
            load_stage_o(smem_base + nb, tid, pa, pb, K, (chunk + 2) * GK);
            CP_COMMIT();
        }
        o_chunk(acc, smem_base + buf, wn, lane);
        buf += STAGE_O;
        if (buf == 3 * STAGE_O) buf = 0;
    }
}

// ---------------------------------------------------------------------------
// QKV projection (single product): Q -> fp16 hi/lo; K,V -> single fp16
// ---------------------------------------------------------------------------
__global__ __launch_bounds__(128, 2) void gemm_qkv16(
    const __half* __restrict__ A, const __half* __restrict__ B,
    const float* __restrict__ bq, const float* __restrict__ bk,
    const float* __restrict__ bv,
    __half* __restrict__ Qh, __half* __restrict__ Ql,
    __half* __restrict__ Kf, __half* __restrict__ Vf)
{
    extern __shared__ char sm_[];
    const uint32_t smem_base = smem_u32(sm_);
    const int tid  = threadIdx.x;
    const int wn   = tid >> 5;
    const int lane = tid & 31;
    const int brow = blockIdx.y << 6;
    const int bcol = blockIdx.x << 8;
    const int K    = DD;

    __half *Ch, *Cl; const float* bias; int outN, obase;
    if (bcol < DD)            { Ch = Qh; Cl = Ql;      bias = bq; outN = DD;  obase = bcol; }
    else if (bcol < DD + KVD) { Ch = Kf; Cl = nullptr; bias = bk; outN = KVD; obase = bcol - DD; }
    else                      { Ch = Vf; Cl = nullptr; bias = bv; outN = KVD; obase = bcol - DD - KVD; }

    const __half* pa = A + (size_t)brow * K;
    const __half* pb = B + (size_t)bcol * K;

    float acc[4][8][4];
    #pragma unroll
    for (int i = 0; i < 4; i++)
        #pragma unroll
        for (int j = 0; j < 8; j++)
            #pragma unroll
            for (int k = 0; k < 4; k++) acc[i][j][k] = 0.f;

    o_mainloop(acc, smem_base, tid, wn, lane, pa, pb, K);

    const int crow = lane >> 2;
    const int ccol = (lane & 3) << 1;
    #pragma unroll
    for (int nt = 0; nt < 8; nt++) {
        const int col = obase + wn * 64 + nt * 8 + ccol;
        float b0 = __ldg(&bias[col]), b1 = __ldg(&bias[col + 1]);
        #pragma unroll
        for (int mt = 0; mt < 4; mt++) {
            size_t row0 = (size_t)(brow + mt * 16 + crow);
            float x0 = acc[mt][nt][0] + b0, x1 = acc[mt][nt][1] + b1;
            float x2 = acc[mt][nt][2] + b0, x3 = acc[mt][nt][3] + b1;
            if (Cl) {
                uint32_t h0, l0, h1, l1;
                split_pack_h(x0, x1, h0, l0);
                split_pack_h(x2, x3, h1, l1);
                *(uint32_t*)&Ch[row0 * outN + col]       = h0;
                *(uint32_t*)&Cl[row0 * outN + col]       = l0;
                *(uint32_t*)&Ch[(row0 + 8) * outN + col] = h1;
                *(uint32_t*)&Cl[(row0 + 8) * outN + col] = l1;
            } else {
                __half2 v0 = __floats2half2_rn(x0, x1);
                __half2 v1 = __floats2half2_rn(x2, x3);
                *(uint32_t*)&Ch[row0 * outN + col]       = *reinterpret_cast<uint32_t*>(&v0);
                *(uint32_t*)&Ch[(row0 + 8) * outN + col] = *reinterpret_cast<uint32_t*>(&v1);
            }
        }
    }
}

// ---------------------------------------------------------------------------
// O projection (single product) -> fp32 out
// ---------------------------------------------------------------------------
__global__ __launch_bounds__(128, 2) void gemm_o16(
    const __half* __restrict__ A, const __half* __restrict__ B,
    const float* __restrict__ bias, float* __restrict__ Cf, int N, int K)
{
    extern __shared__ char sm_[];
    const uint32_t smem_base = smem_u32(sm_);
    const int tid  = threadIdx.x;
    const int wn   = tid >> 5;
    const int lane = tid & 31;
    const int brow = blockIdx.y << 6;
    const int bcol = blockIdx.x << 8;

    const __half* pa = A + (size_t)brow * K;
    const __half* pb = B + (size_t)bcol * K;

    float acc[4][8][4];
    #pragma unroll
    for (int i = 0; i < 4; i++)
        #pragma unroll
        for (int j = 0; j < 8; j++)
            #pragma unroll
            for (int k = 0; k < 4; k++) acc[i][j][k] = 0.f;

    o_mainloop(acc, smem_base, tid, wn, lane, pa, pb, K);

    const int crow = lane >> 2;
    const int ccol = (lane & 3) << 1;
    #pragma unroll
    for (int nt = 0; nt < 8; nt++) {
        const int col = bcol + wn * 64 + nt * 8 + ccol;
        float b0 = __ldg(&bias[col]), b1 = __ldg(&bias[col + 1]);
        #pragma unroll
        for (int mt = 0; mt < 4; mt++) {
            size_t row0 = (size_t)(brow + mt * 16 + crow);
            float2 v0 = { acc[mt][nt][0] + b0, acc[mt][nt][1] + b1 };
            float2 v1 = { acc[mt][nt][2] + b0, acc[mt][nt][3] + b1 };
            *(float2*)&Cf[row0 * N + col]       = v0;
            *(float2*)&Cf[(row0 + 8) * N + col] = v1;
        }
    }
}

// ---------------------------------------------------------------------------
// fp16 causal GQA flash attention (unchanged from R15).
// Q hi/lo (2-product QK); P single; Y single fp16 out.
// ---------------------------------------------------------------------------
#define ATSTR 272
#define AT64  (64 * ATSTR)
#define AQ_B  AT64
#define AKV_B (2 * AT64)
#define ATTN_SMEM (2 * AQ_B + 2 * AKV_B)

__device__ __forceinline__ void attn_load_kv(
    uint32_t base, int tid,
    const __half* __restrict__ Kf, const __half* __restrict__ Vf,
    size_t grow0, int gcol)
{
    const __half* srcs[2] = { Kf, Vf };
    #pragma unroll
    for (int t = 0; t < 2; t++) {
        const __half* s = srcs[t] + grow0 * KVD + gcol;
        #pragma unroll
        for (int i = 0; i < 8; i++) {
            int ch = tid + i * 128;
            int r = ch >> 4, c = ch & 15;
            cpasync16(base + t * AT64 + r * ATSTR + c * 16,
                      s + (size_t)r * KVD + c * 8);
        }
    }
    CP_COMMIT();
}

__global__ __launch_bounds__(128, 2) void attn_mma(
    const __half* __restrict__ Qh_, const __half* __restrict__ Ql_,
    const __half* __restrict__ Kf_, const __half* __restrict__ Vf_,
    __half* __restrict__ Yf_)
{
    extern __shared__ char sm_[];
    const uint32_t sb = smem_u32(sm_);
    const int tid  = threadIdx.x;
    const int lane = tid & 31;
    const int w    = tid >> 5;
    const int qt   = (int)gridDim.x - 1 - (int)blockIdx.x;
    const int bh   = blockIdx.y;
    const int b    = bh >> 5, h = bh & 31, g = h >> 2;
    const int ktmax = qt;
    const size_t qrow0 = (size_t)b * TT + (size_t)qt * 64;
    const size_t krow0 = (size_t)b * TT;
    const int gcol = g * DH;

    {
        const __half* q0 = Qh_ + qrow0 * DD + h * DH;
        const __half* q1 = Ql_ + qrow0 * DD + h * DH;
        #pragma unroll
        for (int i = 0; i < 8; i++) {
            int ch = tid + i * 128;
            int r = ch >> 4, c = ch & 15;
            cpasync16(sb + r * ATSTR + c * 16,        q0 + (size_t)r * DD + c * 8);
            cpasync16(sb + AQ_B + r * ATSTR + c * 16, q1 + (size_t)r * DD + c * 8);
        }
        CP_COMMIT();
    }
    attn_load_kv(sb + 2 * AQ_B, tid, Kf_, Vf_, krow0, gcol);
    if (ktmax >= 1)
        attn_load_kv(sb + 2 * AQ_B + AKV_B, tid, Kf_, Vf_, krow0 + 64, gcol);
    else
        CP_COMMIT();

    float o[16][4];
    #pragma unroll
    for (int i = 0; i < 16; i++)
        #pragma unroll
        for (int j = 0; j < 4; j++) o[i][j] = 0.f;
    float m_lo = -1e30f, m_hi = -1e30f, l_lo = 0.f, l_hi = 0.f;

    const int wrow = qt * 64 + w * 16;
    const int rl   = lane >> 2;
    const float SC = 0.088388347648318447f * 1.4426950408889634f;

    for (int kt = 0; kt <= ktmax; kt++) {
        if (kt < ktmax) { CP_WAIT1(); } else { CP_WAIT0(); }
        __syncthreads();
        const uint32_t kb = sb + 2 * AQ_B + (kt & 1) * AKV_B;

        {
            float s[8][4];
            #pragma unroll
            for (int j = 0; j < 8; j++)
                #pragma unroll
                for (int e = 0; e < 4; e++) s[j][e] = 0.f;

            #pragma unroll
            for (int ks = 0; ks < 8; ks++) {
                uint32_t qh[4], ql[4];
                uint32_t ra = sb + (w * 16 + (lane & 15)) * ATSTR
                            + ks * 32 + ((lane >> 4) << 4);
                ldsm4(qh[0], qh[1], qh[2], qh[3], ra);
                ldsm4(ql[0], ql[1], ql[2], ql[3], ra + AQ_B);
                uint32_t kf[4][4];
                #pragma unroll
                for (int np = 0; np < 4; np++) {
                    uint32_t rb = kb
                        + (np * 16 + (lane & 7) + ((lane >> 4) << 3)) * ATSTR
                        + ks * 32 + (((lane >> 3) & 1) << 4);
                    ldsm4(kf[np][0], kf[np][1], kf[np][2], kf[np][3], rb);
                }
                #pragma unroll
                for (int np = 0; np < 4; np++) {
                    mma16816h(s[2 * np],     qh, kf[np][0], kf[np][1]);
                    mma16816h(s[2 * np + 1], qh, kf[np][2], kf[np][3]);
                }
                #pragma unroll
                for (int np = 0; np < 4; np++) {
                    mma16816h(s[2 * np],     ql, kf[np][0], kf[np][1]);
                    mma16816h(s[2 * np + 1], ql, kf[np][2], kf[np][3]);
                }
            }

            #pragma unroll
            for (int j = 0; j < 8; j++)
                #pragma unroll
                for (int e = 0; e < 4; e++) s[j][e] *= SC;
            if (kt * 64 + 63 > wrow) {
                const int row_lo = wrow + rl, row_hi = row_lo + 8;
                #pragma unroll
                for (int j = 0; j < 8; j++) {
                    int c0 = kt * 64 + j * 8 + ((lane & 3) << 1);
                    if (c0 > row_lo)     s[j][0] = -1e30f;
                    if (c0 + 1 > row_lo) s[j][1] = -1e30f;
                    if (c0 > row_hi)     s[j][2] = -1e30f;
                    if (c0 + 1 > row_hi) s[j][3] = -1e30f;
                }
            }

            float mx0 = -1e30f, mx1 = -1e30f;
            #pragma unroll
            for (int j = 0; j < 8; j++) {
                mx0 = fmaxf(mx0, fmaxf(s[j][0], s[j][1]));
                mx1 = fmaxf(mx1, fmaxf(s[j][2], s[j][3]));
            }
            mx0 = fmaxf(mx0, __shfl_xor_sync(0xffffffffu, mx0, 1));
            mx0 = fmaxf(mx0, __shfl_xor_sync(0xffffffffu, mx0, 2));
            mx1 = fmaxf(mx1, __shfl_xor_sync(0xffffffffu, mx1, 1));
            mx1 = fmaxf(mx1, __shfl_xor_sync(0xffffffffu, mx1, 2));
            float mn0 = fmaxf(m_lo, mx0), mn1 = fmaxf(m_hi, mx1);
            float c0 = ex2f(m_lo - mn0), c1 = ex2f(m_hi - mn1);
            float su0 = 0.f, su1 = 0.f;
            #pragma unroll
            for (int j = 0; j < 8; j++) {
                s[j][0] = ex2f(s[j][0] - mn0);
                s[j][1] = ex2f(s[j][1] - mn0);
                s[j][2] = ex2f(s[j][2] - mn1);
                s[j][3] = ex2f(s[j][3] - mn1);
                su0 += s[j][0] + s[j][1];
                su1 += s[j][2] + s[j][3];
            }
            su0 += __shfl_xor_sync(0xffffffffu, su0, 1);
            su0 += __shfl_xor_sync(0xffffffffu, su0, 2);
            su1 += __shfl_xor_sync(0xffffffffu, su1, 1);
            su1 += __shfl_xor_sync(0xffffffffu, su1, 2);
            l_lo = l_lo * c0 + su0;  l_hi = l_hi * c1 + su1;
            m_lo = mn0;              m_hi = mn1;
            #pragma unroll
            for (int nt = 0; nt < 16; nt++) {
                o[nt][0] *= c0; o[nt][1] *= c0;
                o[nt][2] *= c1; o[nt][3] *= c1;
            }

            #pragma unroll
            for (int ks = 0; ks < 4; ks++) {
                uint32_t ph[4];
                __half2 p0 = __floats2half2_rn(s[2 * ks][0],     s[2 * ks][1]);
                __half2 p1 = __floats2half2_rn(s[2 * ks][2],     s[2 * ks][3]);
                __half2 p2 = __floats2half2_rn(s[2 * ks + 1][0], s[2 * ks + 1][1]);
                __half2 p3 = __floats2half2_rn(s[2 * ks + 1][2], s[2 * ks + 1][3]);
                ph[0] = *reinterpret_cast<uint32_t*>(&p0);
                ph[1] = *reinterpret_cast<uint32_t*>(&p1);
                ph[2] = *reinterpret_cast<uint32_t*>(&p2);
                ph[3] = *reinterpret_cast<uint32_t*>(&p3);
                #pragma unroll
                for (int npp = 0; npp < 4; npp++) {
                    uint32_t vh0[4], vh1[4];
                    uint32_t rv = kb + AT64
                        + (ks * 16 + (lane & 15)) * ATSTR
                        + npp * 64 + ((lane >> 4) << 4);
                    ldsm4t(vh0[0], vh0[1], vh0[2], vh0[3], rv);
                    ldsm4t(vh1[0], vh1[1], vh1[2], vh1[3], rv + 32);
                    mma16816h(o[4 * npp],     ph, vh0[0], vh0[1]);
                    mma16816h(o[4 * npp + 1], ph, vh0[2], vh0[3]);
                    mma16816h(o[4 * npp + 2], ph, vh1[0], vh1[1]);
                    mma16816h(o[4 * npp + 3], ph, vh1[2], vh1[3]);
                }
            }
        }
        __syncthreads();
        if (kt + 2 <= ktmax)
            attn_load_kv(sb + 2 * AQ_B + (kt & 1) * AKV_B, tid,
                         Kf_, Vf_, krow0 + (size_t)(kt + 2) * 64, gcol);
    }

    const float i0 = 1.f / l_lo, i1 = 1.f / l_hi;
    const size_t row_lo = qrow0 + w * 16 + rl;
    const size_t row_hi = row_lo + 8;
    const int colb = h * DH + ((lane & 3) << 1);
    #pragma unroll
    for (int nt = 0; nt < 16; nt++) {
        int col = colb + nt * 8;
        __half2 y0 = __floats2half2_rn(o[nt][0] * i0, o[nt][1] * i0);
        __half2 y1 = __floats2half2_rn(o[nt][2] * i1, o[nt][3] * i1);
        *(uint32_t*)&Yf_[row_lo * DD + col] = *reinterpret_cast<uint32_t*>(&y0);
        *(uint32_t*)&Yf_[row_hi * DD + col] = *reinterpret_cast<uint32_t*>(&y1);
    }
}

// ---------------------------------------------------------------------------
extern "C" void kernel_launch(void* const* d_in, const int* in_sizes, int n_in,
                              void* d_out, int out_size)
{
    (void)in_sizes; (void)n_in; (void)out_size;
    const float* X  = (const float*)d_in[0];
    const float* Wq = (const float*)d_in[1];
    const float* bq = (const float*)d_in[2];
    const float* Wk = (const float*)d_in[3];
    const float* bk = (const float*)d_in[4];
    const float* Wv = (const float*)d_in[5];
    const float* bv = (const float*)d_in[6];
    const float* Wo = (const float*)d_in[7];
    const float* bo = (const float*)d_in[8];
    float* out = (float*)d_out;

    __half *Xf, *Wqkvf, *Wof, *Yf, *Qh, *Ql, *Kf, *Vf;
    cudaGetSymbolAddress((void**)&Xf, g_X_f);
    cudaGetSymbolAddress((void**)&Wqkvf, g_Wqkv_f);
    cudaGetSymbolAddress((void**)&Qh, g_Q_h16);   cudaGetSymbolAddress((void**)&Ql, g_Q_l16);
    cudaGetSymbolAddress((void**)&Kf, g_K_f);     cudaGetSymbolAddress((void**)&Vf, g_V_f);
    cudaGetSymbolAddress((void**)&Wof, g_Wo_f);
    cudaGetSymbolAddress((void**)&Yf, g_Y_f);

    cudaFuncSetAttribute(gemm_qkv16,
                         cudaFuncAttributeMaxDynamicSharedMemorySize, GEMMO_SMEM);
    cudaFuncSetAttribute(gemm_o16,
                         cudaFuncAttributeMaxDynamicSharedMemorySize, GEMMO_SMEM);
    cudaFuncSetAttribute(attn_mma,
                         cudaFuncAttributeMaxDynamicSharedMemorySize, ATTN_SMEM);

    const int nAll = (MTOT * DD + 2 * DD * DD + 2 * KVD * DD) / 4;
    conv_f16_all<<<(nAll + 255) / 256, 256>>>(X, Wq, Wk, Wv, Wo, Xf, Wqkvf, Wof);

    // QKV projection (single product)
    gemm_qkv16<<<dim3(NQKV / 256, MTOT / 64), 128, GEMMO_SMEM>>>(
        Xf, Wqkvf, bq, bk, bv, Qh, Ql, Kf, Vf);

    // attention (Q 2-product, P single)
    attn_mma<<<dim3(TT / 64, BB * HH), 128, ATTN_SMEM>>>(
        Qh, Ql, Kf, Vf, Yf);

    // O projection (single product)
    gemm_o16<<<dim3(DD / 256, MTOT / 64), 128, GEMMO_SMEM>>>(
        Yf, Wof, bo, out, DD, DD);
}

// round 17
// speedup vs baseline: 6.4694x; 1.0786x over previous
#include <cuda_runtime.h>
#include <cuda_bf16.h>
#include <cuda_fp16.h>
#include <cstdint>

#define BB   2
#define TT   2048
#define DD   4096
#define HH   32
#define GG   8
#define DH   128
#define KVD  (GG*DH)     /* 1024 */
#define NQKV (DD+2*KVD)  /* 6144 */
#define MTOT (BB*TT)     /* 4096 */

// fp16 operands (all single-precision-fp16 now)
__device__ __half g_X_f[(size_t)MTOT * DD];
__device__ __half g_Wqkv_f[(size_t)NQKV * DD];
__device__ __half g_Q_f[(size_t)MTOT * DD];
__device__ __half g_K_f[(size_t)MTOT * KVD];
__device__ __half g_V_f[(size_t)MTOT * KVD];
__device__ __half g_Wo_f[(size_t)DD * DD];
__device__ __half g_Y_f[(size_t)MTOT * DD];

// ---------------------------------------------------------------------------
__device__ __forceinline__ uint32_t smem_u32(const void* p) {
    uint32_t a;
    asm("{ .reg .u64 t; cvta.to.shared.u64 t, %1; cvt.u32.u64 %0, t; }"
        : "=r"(a) : "l"(p));
    return a;
}
__device__ __forceinline__ void ldsm4(uint32_t& r0, uint32_t& r1, uint32_t& r2,
                                      uint32_t& r3, uint32_t addr) {
    asm volatile("ldmatrix.sync.aligned.m8n8.x4.shared.b16 {%0,%1,%2,%3}, [%4];"
                 : "=r"(r0), "=r"(r1), "=r"(r2), "=r"(r3) : "r"(addr));
}
__device__ __forceinline__ void ldsm4t(uint32_t& r0, uint32_t& r1, uint32_t& r2,
                                       uint32_t& r3, uint32_t addr) {
    asm volatile("ldmatrix.sync.aligned.m8n8.x4.trans.shared.b16 {%0,%1,%2,%3}, [%4];"
                 : "=r"(r0), "=r"(r1), "=r"(r2), "=r"(r3) : "r"(addr));
}
__device__ __forceinline__ void mma16816h(float* c, const uint32_t* a,
                                          uint32_t b0, uint32_t b1) {
    asm volatile(
        "mma.sync.aligned.m16n8k16.row.col.f32.f16.f16.f32 "
        "{%0,%1,%2,%3}, {%4,%5,%6,%7}, {%8,%9}, {%0,%1,%2,%3};"
        : "+f"(c[0]), "+f"(c[1]), "+f"(c[2]), "+f"(c[3])
        : "r"(a[0]), "r"(a[1]), "r"(a[2]), "r"(a[3]), "r"(b0), "r"(b1));
}
__device__ __forceinline__ void cpasync16(uint32_t dst, const void* src) {
    asm volatile("cp.async.cg.shared.global [%0], [%1], 16;"
                 :: "r"(dst), "l"(src) : "memory");
}
#define CP_COMMIT() asm volatile("cp.async.commit_group;" ::: "memory")
#define CP_WAIT1()  asm volatile("cp.async.wait_group 1;" ::: "memory")
#define CP_WAIT0()  asm volatile("cp.async.wait_group 0;" ::: "memory")

__device__ __forceinline__ float ex2f(float x) {
    float y;
    asm("ex2.approx.ftz.f32 %0, %1;" : "=f"(y) : "f"(x));
    return y;
}

// ---------------------------------------------------------------------------
// all fp32->fp16 conversions (X + 4 weights) in one launch
__global__ void conv_f16_all(const float* __restrict__ x,
                             const float* __restrict__ wq,
                             const float* __restrict__ wk,
                             const float* __restrict__ wv,
                             const float* __restrict__ wo,
                             __half* __restrict__ xf,
                             __half* __restrict__ qkv, __half* __restrict__ o)
{
    const int nXD = MTOT * DD / 4, nDD = DD * DD / 4, nKD = KVD * DD / 4;
    int i = blockIdx.x * blockDim.x + threadIdx.x;
    const float* src; __half* dst; int j = i;
    if (j < nXD)                { src = x;  dst = xf; }
    else if ((j -= nXD) < nDD)  { src = wq; dst = qkv; }
    else if ((j -= nDD) < nKD)  { src = wk; dst = qkv + (size_t)DD * DD; }
    else if ((j -= nKD) < nKD)  { src = wv; dst = qkv + (size_t)(DD + KVD) * DD; }
    else if ((j -= nKD) < nDD)  { src = wo; dst = o; }
    else return;
    float4 v = ((const float4*)src)[j];
    __half2 a = __floats2half2_rn(v.x, v.y);
    __half2 b = __floats2half2_rn(v.z, v.w);
    ((uint32_t*)dst)[2 * j]     = *reinterpret_cast<uint32_t*>(&a);
    ((uint32_t*)dst)[2 * j + 1] = *reinterpret_cast<uint32_t*>(&b);
}

// ---------------------------------------------------------------------------
// Single-product fp16 GEMM core: CTA 128 thr (4 warps), CTA tile 64x256,
// warp tile 64x64, K-chunk 32, 3-stage cp.async, 1 sync/chunk, 2 CTAs/SM.
// ---------------------------------------------------------------------------
#define GK      32
#define A16SUB  (64 * 80)               /* 5120 B  */
#define B16SUB  (256 * 80)              /* 20480 B */
#define STAGE_O (A16SUB + B16SUB)       /* 25600 B */
#define GEMMO_SMEM (3 * STAGE_O)        /* 76800 B */

__device__ __forceinline__ void load_stage_o(
    uint32_t sb, int tid, const __half* a, const __half* b, int K, int k0)
{
    #pragma unroll
    for (int t = 0; t < 10; t++) {
        const int id = t * 128 + tid;          // 0..1279
        if (id < 256) {
            const int r = id >> 2, cb = (id & 3) << 4;
            cpasync16(sb + r * 80 + cb, a + (size_t)r * K + k0 + (cb >> 1));
        } else {
            const int x = id - 256;
            const int r = x >> 2, cb = (x & 3) << 4;
            cpasync16(sb + A16SUB + r * 80 + cb,
                      b + (size_t)r * K + k0 + (cb >> 1));
        }
    }
}

__device__ __forceinline__ void o_chunk(
    float acc[4][8][4], uint32_t sb, int wn, int lane)
{
    const int a_row = lane & 15;
    const int a_kb  = (lane >> 4) << 4;
    const int b_row = (lane & 7) + ((lane >> 4) << 3);
    const int b_kb  = ((lane >> 3) & 1) << 4;
    #pragma unroll
    for (int ks = 0; ks < 2; ks++) {
        uint32_t ah[4][4], bh[4][4];
        #pragma unroll
        for (int mt = 0; mt < 4; mt++) {
            uint32_t ra = sb + (mt * 16 + a_row) * 80 + ks * 32 + a_kb;
            ldsm4(ah[mt][0], ah[mt][1], ah[mt][2], ah[mt][3], ra);
        }
        #pragma unroll
        for (int bt = 0; bt < 4; bt++) {
            uint32_t rb = sb + A16SUB
                        + (wn * 64 + bt * 16 + b_row) * 80
                        + ks * 32 + b_kb;
            ldsm4(bh[bt][0], bh[bt][1], bh[bt][2], bh[bt][3], rb);
        }
        #pragma unroll
        for (int bt = 0; bt < 4; bt++)
            #pragma unroll
            for (int mt = 0; mt < 4; mt++) {
                mma16816h(acc[mt][bt * 2],     ah[mt], bh[bt][0], bh[bt][1]);
                mma16816h(acc[mt][bt * 2 + 1], ah[mt], bh[bt][2], bh[bt][3]);
            }
    }
}

__device__ __forceinline__ void o_mainloop(
    float acc[4][8][4], uint32_t smem_base, int tid, int wn, int lane,
    const __half* pa, const __half* pb, int K)
{
    const int nchunks = K / GK;
    load_stage_o(smem_base,           tid, pa, pb, K, 0);   CP_COMMIT();
    load_stage_o(smem_base + STAGE_O, tid, pa, pb, K, GK);  CP_COMMIT();

    uint32_t buf = 0;
    for (int chunk = 0; chunk < nchunks; chunk++) {
        if (chunk + 1 < nchunks) { CP_WAIT1(); } else { CP_WAIT0(); }
        __syncthreads();
        if (chunk + 2 < nchunks) {
            uint32_t nb = buf + 2 * STAGE_O;
            if (nb >= 3 * STAGE_O) nb -= 3 * STAGE_O;
            load_stage_o(smem_base + nb, tid, pa, pb, K, (chunk + 2) * GK);
            CP_COMMIT();
        }
        o_chunk(acc, smem_base + buf, wn, lane);
        buf += STAGE_O;
        if (buf == 3 * STAGE_O) buf = 0;
    }
}

// ---------------------------------------------------------------------------
// QKV projection (single product) -> single fp16 Q, K, V
// ---------------------------------------------------------------------------
__global__ __launch_bounds__(128, 2) void gemm_qkv16(
    const __half* __restrict__ A, const __half* __restrict__ B,
    const float* __restrict__ bq, const float* __restrict__ bk,
    const float* __restrict__ bv,
    __half* __restrict__ Qf, __half* __restrict__ Kf, __half* __restrict__ Vf)
{
    extern __shared__ char sm_[];
    const uint32_t smem_base = smem_u32(sm_);
    const int tid  = threadIdx.x;
    const int wn   = tid >> 5;
    const int lane = tid & 31;
    const int brow = blockIdx.y << 6;
    const int bcol = blockIdx.x << 8;
    const int K    = DD;

    __half* Ch; const float* bias; int outN, obase;
    if (bcol < DD)            { Ch = Qf; bias = bq; outN = DD;  obase = bcol; }
    else if (bcol < DD + KVD) { Ch = Kf; bias = bk; outN = KVD; obase = bcol - DD; }
    else                      { Ch = Vf; bias = bv; outN = KVD; obase = bcol - DD - KVD; }

    const __half* pa = A + (size_t)brow * K;
    const __half* pb = B + (size_t)bcol * K;

    float acc[4][8][4];
    #pragma unroll
    for (int i = 0; i < 4; i++)
        #pragma unroll
        for (int j = 0; j < 8; j++)
            #pragma unroll
            for (int k = 0; k < 4; k++) acc[i][j][k] = 0.f;

    o_mainloop(acc, smem_base, tid, wn, lane, pa, pb, K);

    const int crow = lane >> 2;
    const int ccol = (lane & 3) << 1;
    #pragma unroll
    for (int nt = 0; nt < 8; nt++) {
        const int col = obase + wn * 64 + nt * 8 + ccol;
        float b0 = __ldg(&bias[col]), b1 = __ldg(&bias[col + 1]);
        #pragma unroll
        for (int mt = 0; mt < 4; mt++) {
            size_t row0 = (size_t)(brow + mt * 16 + crow);
            __half2 v0 = __floats2half2_rn(acc[mt][nt][0] + b0, acc[mt][nt][1] + b1);
            __half2 v1 = __floats2half2_rn(acc[mt][nt][2] + b0, acc[mt][nt][3] + b1);
            *(uint32_t*)&Ch[row0 * outN + col]       = *reinterpret_cast<uint32_t*>(&v0);
            *(uint32_t*)&Ch[(row0 + 8) * outN + col] = *reinterpret_cast<uint32_t*>(&v1);
        }
    }
}

// ---------------------------------------------------------------------------
// O projection (single product) -> fp32 out
// ---------------------------------------------------------------------------
__global__ __launch_bounds__(128, 2) void gemm_o16(
    const __half* __restrict__ A, const __half* __restrict__ B,
    const float* __restrict__ bias, float* __restrict__ Cf, int N, int K)
{
    extern __shared__ char sm_[];
    const uint32_t smem_base = smem_u32(sm_);
    const int tid  = threadIdx.x;
    const int wn   = tid >> 5;
    const int lane = tid & 31;
    const int brow = blockIdx.y << 6;
    const int bcol = blockIdx.x << 8;

    const __half* pa = A + (size_t)brow * K;
    const __half* pb = B + (size_t)bcol * K;

    float acc[4][8][4];
    #pragma unroll
    for (int i = 0; i < 4; i++)
        #pragma unroll
        for (int j = 0; j < 8; j++)
            #pragma unroll
            for (int k = 0; k < 4; k++) acc[i][j][k] = 0.f;

    o_mainloop(acc, smem_base, tid, wn, lane, pa, pb, K);

    const int crow = lane >> 2;
    const int ccol = (lane & 3) << 1;
    #pragma unroll
    for (int nt = 0; nt < 8; nt++) {
        const int col = bcol + wn * 64 + nt * 8 + ccol;
        float b0 = __ldg(&bias[col]), b1 = __ldg(&bias[col + 1]);
        #pragma unroll
        for (int mt = 0; mt < 4; mt++) {
            size_t row0 = (size_t)(brow + mt * 16 + crow);
            float2 v0 = { acc[mt][nt][0] + b0, acc[mt][nt][1] + b1 };
            float2 v1 = { acc[mt][nt][2] + b0, acc[mt][nt][3] + b1 };
            *(float2*)&Cf[row0 * N + col]       = v0;
            *(float2*)&Cf[(row0 + 8) * N + col] = v1;
        }
    }
}

// ---------------------------------------------------------------------------
// fp16 causal GQA flash attention — all single-product.
// CTA 128 thr, q-tile 64, 2 CTAs/SM. SMEM = Q(17408) + 2x(K|V)(34816) = 87040.
// ---------------------------------------------------------------------------
#define ATSTR 272
#define AT64  (64 * ATSTR)
#define AQ_B  AT64
#define AKV_B (2 * AT64)
#define ATTN_SMEM (AQ_B + 2 * AKV_B)    /* 87040 */

__device__ __forceinline__ void attn_load_kv(
    uint32_t base, int tid,
    const __half* __restrict__ Kf, const __half* __restrict__ Vf,
    size_t grow0, int gcol)
{
    const __half* srcs[2] = { Kf, Vf };
    #pragma unroll
    for (int t = 0; t < 2; t++) {
        const __half* s = srcs[t] + grow0 * KVD + gcol;
        #pragma unroll
        for (int i = 0; i < 8; i++) {
            int ch = tid + i * 128;
            int r = ch >> 4, c = ch & 15;
            cpasync16(base + t * AT64 + r * ATSTR + c * 16,
                      s + (size_t)r * KVD + c * 8);
        }
    }
    CP_COMMIT();
}

__global__ __launch_bounds__(128, 2) void attn_mma(
    const __half* __restrict__ Qf_,
    const __half* __restrict__ Kf_, const __half* __restrict__ Vf_,
    __half* __restrict__ Yf_)
{
    extern __shared__ char sm_[];
    const uint32_t sb = smem_u32(sm_);
    const int tid  = threadIdx.x;
    const int lane = tid & 31;
    const int w    = tid >> 5;
    const int qt   = (int)gridDim.x - 1 - (int)blockIdx.x;
    const int bh   = blockIdx.y;
    const int b    = bh >> 5, h = bh & 31, g = h >> 2;
    const int ktmax = qt;
    const size_t qrow0 = (size_t)b * TT + (size_t)qt * 64;
    const size_t krow0 = (size_t)b * TT;
    const int gcol = g * DH;

    {
        const __half* q0 = Qf_ + qrow0 * DD + h * DH;
        #pragma unroll
        for (int i = 0; i < 8; i++) {
            int ch = tid + i * 128;
            int r = ch >> 4, c = ch & 15;
            cpasync16(sb + r * ATSTR + c * 16, q0 + (size_t)r * DD + c * 8);
        }
        CP_COMMIT();
    }
    attn_load_kv(sb + AQ_B, tid, Kf_, Vf_, krow0, gcol);
    if (ktmax >= 1)
        attn_load_kv(sb + AQ_B + AKV_B, tid, Kf_, Vf_, krow0 + 64, gcol);
    else
        CP_COMMIT();

    float o[16][4];
    #pragma unroll
    for (int i = 0; i < 16; i++)
        #pragma unroll
        for (int j = 0; j < 4; j++) o[i][j] = 0.f;
    float m_lo = -1e30f, m_hi = -1e30f, l_lo = 0.f, l_hi = 0.f;

    const int wrow = qt * 64 + w * 16;
    const int rl   = lane >> 2;
    const float SC = 0.088388347648318447f * 1.4426950408889634f;

    for (int kt = 0; kt <= ktmax; kt++) {
        if (kt < ktmax) { CP_WAIT1(); } else { CP_WAIT0(); }
        __syncthreads();
        const uint32_t kb = sb + AQ_B + (kt & 1) * AKV_B;

        {
            float s[8][4];
            #pragma unroll
            for (int j = 0; j < 8; j++)
                #pragma unroll
                for (int e = 0; e < 4; e++) s[j][e] = 0.f;

            // ---- S = Q K^T (single product) ----
            #pragma unroll
            for (int ks = 0; ks < 8; ks++) {
                uint32_t qh[4];
                uint32_t ra = sb + (w * 16 + (lane & 15)) * ATSTR
                            + ks * 32 + ((lane >> 4) << 4);
                ldsm4(qh[0], qh[1], qh[2], qh[3], ra);
                uint32_t kf[4][4];
                #pragma unroll
                for (int np = 0; np < 4; np++) {
                    uint32_t rb = kb
                        + (np * 16 + (lane & 7) + ((lane >> 4) << 3)) * ATSTR
                        + ks * 32 + (((lane >> 3) & 1) << 4);
                    ldsm4(kf[np][0], kf[np][1], kf[np][2], kf[np][3], rb);
                }
                #pragma unroll
                for (int np = 0; np < 4; np++) {
                    mma16816h(s[2 * np],     qh, kf[np][0], kf[np][1]);
                    mma16816h(s[2 * np + 1], qh, kf[np][2], kf[np][3]);
                }
            }

            #pragma unroll
            for (int j = 0; j < 8; j++)
                #pragma unroll
                for (int e = 0; e < 4; e++) s[j][e] *= SC;
            if (kt * 64 + 63 > wrow) {
                const int row_lo = wrow + rl, row_hi = row_lo + 8;
                #pragma unroll
                for (int j = 0; j < 8; j++) {
                    int c0 = kt * 64 + j * 8 + ((lane & 3) << 1);
                    if (c0 > row_lo)     s[j][0] = -1e30f;
                    if (c0 + 1 > row_lo) s[j][1] = -1e30f;
                    if (c0 > row_hi)     s[j][2] = -1e30f;
                    if (c0 + 1 > row_hi) s[j][3] = -1e30f;
                }
            }

            float mx0 = -1e30f, mx1 = -1e30f;
            #pragma unroll
            for (int j = 0; j < 8; j++) {
                mx0 = fmaxf(mx0, fmaxf(s[j][0], s[j][1]));
                mx1 = fmaxf(mx1, fmaxf(s[j][2], s[j][3]));
            }
            mx0 = fmaxf(mx0, __shfl_xor_sync(0xffffffffu, mx0, 1));
            mx0 = fmaxf(mx0, __shfl_xor_sync(0xffffffffu, mx0, 2));
            mx1 = fmaxf(mx1, __shfl_xor_sync(0xffffffffu, mx1, 1));
            mx1 = fmaxf(mx1, __shfl_xor_sync(0xffffffffu, mx1, 2));
            float mn0 = fmaxf(m_lo, mx0), mn1 = fmaxf(m_hi, mx1);
            float c0 = ex2f(m_lo - mn0), c1 = ex2f(m_hi - mn1);
            float su0 = 0.f, su1 = 0.f;
            #pragma unroll
            for (int j = 0; j < 8; j++) {
                s[j][0] = ex2f(s[j][0] - mn0);
                s[j][1] = ex2f(s[j][1] - mn0);
                s[j][2] = ex2f(s[j][2] - mn1);
                s[j][3] = ex2f(s[j][3] - mn1);
                su0 += s[j][0] + s[j][1];
                su1 += s[j][2] + s[j][3];
            }
            su0 += __shfl_xor_sync(0xffffffffu, su0, 1);
            su0 += __shfl_xor_sync(0xffffffffu, su0, 2);
            su1 += __shfl_xor_sync(0xffffffffu, su1, 1);
            su1 += __shfl_xor_sync(0xffffffffu, su1, 2);
            l_lo = l_lo * c0 + su0;  l_hi = l_hi * c1 + su1;
            m_lo = mn0;              m_hi = mn1;
            #pragma unroll
            for (int nt = 0; nt < 16; nt++) {
                o[nt][0] *= c0; o[nt][1] *= c0;
                o[nt][2] *= c1; o[nt][3] *= c1;
            }

            // ---- O += P V (single product) ----
            #pragma unroll
            for (int ks = 0; ks < 4; ks++) {
                uint32_t ph[4];
                __half2 p0 = __floats2half2_rn(s[2 * ks][0],     s[2 * ks][1]);
                __half2 p1 = __floats2half2_rn(s[2 * ks][2],     s[2 * ks][3]);
                __half2 p2 = __floats2half2_rn(s[2 * ks + 1][0], s[2 * ks + 1][1]);
                __half2 p3 = __floats2half2_rn(s[2 * ks + 1][2], s[2 * ks + 1][3]);
                ph[0] = *reinterpret_cast<uint32_t*>(&p0);
                ph[1] = *reinterpret_cast<uint32_t*>(&p1);
                ph[2] = *reinterpret_cast<uint32_t*>(&p2);
                ph[3] = *reinterpret_cast<uint32_t*>(&p3);
                #pragma unroll
                for (int npp = 0; npp < 4; npp++) {
                    uint32_t vh0[4], vh1[4];
                    uint32_t rv = kb + AT64
                        + (ks * 16 + (lane & 15)) * ATSTR
                        + npp * 64 + ((lane >> 4) << 4);
                    ldsm4t(vh0[0], vh0[1], vh0[2], vh0[3], rv);
                    ldsm4t(vh1[0], vh1[1], vh1[2], vh1[3], rv + 32);
                    mma16816h(o[4 * npp],     ph, vh0[0], vh0[1]);
                    mma16816h(o[4 * npp + 1], ph, vh0[2], vh0[3]);
                    mma16816h(o[4 * npp + 2], ph, vh1[0], vh1[1]);
                    mma16816h(o[4 * npp + 3], ph, vh1[2], vh1[3]);
                }
            }
        }
        __syncthreads();
        if (kt + 2 <= ktmax)
            attn_load_kv(sb + AQ_B + (kt & 1) * AKV_B, tid,
                         Kf_, Vf_, krow0 + (size_t)(kt + 2) * 64, gcol);
    }

    const float i0 = 1.f / l_lo, i1 = 1.f / l_hi;
    const size_t row_lo = qrow0 + w * 16 + rl;
    const size_t row_hi = row_lo + 8;
    const int colb = h * DH + ((lane & 3) << 1);
    #pragma unroll
    for (int nt = 0; nt < 16; nt++) {
        int col = colb + nt * 8;
        __half2 y0 = __floats2half2_rn(o[nt][0] * i0, o[nt][1] * i0);
        __half2 y1 = __floats2half2_rn(o[nt][2] * i1, o[nt][3] * i1);
        *(uint32_t*)&Yf_[row_lo * DD + col] = *reinterpret_cast<uint32_t*>(&y0);
        *(uint32_t*)&Yf_[row_hi * DD + col] = *reinterpret_cast<uint32_t*>(&y1);
    }
}

// ---------------------------------------------------------------------------
extern "C" void kernel_launch(void* const* d_in, const int* in_sizes, int n_in,
                              void* d_out, int out_size)
{
    (void)in_sizes; (void)n_in; (void)out_size;
    const float* X  = (const float*)d_in[0];
    const float* Wq = (const float*)d_in[1];
    const float* bq = (const float*)d_in[2];
    const float* Wk = (const float*)d_in[3];
    const float* bk = (const float*)d_in[4];
    const float* Wv = (const float*)d_in[5];
    const float* bv = (const float*)d_in[6];
    const float* Wo = (const float*)d_in[7];
    const float* bo = (const float*)d_in[8];
    float* out = (float*)d_out;

    __half *Xf, *Wqkvf, *Wof, *Yf, *Qf, *Kf, *Vf;
    cudaGetSymbolAddress((void**)&Xf, g_X_f);
    cudaGetSymbolAddress((void**)&Wqkvf, g_Wqkv_f);
    cudaGetSymbolAddress((void**)&Qf, g_Q_f);
    cudaGetSymbolAddress((void**)&Kf, g_K_f);
    cudaGetSymbolAddress((void**)&Vf, g_V_f);
    cudaGetSymbolAddress((void**)&Wof, g_Wo_f);
    cudaGetSymbolAddress((void**)&Yf, g_Y_f);

    cudaFuncSetAttribute(gemm_qkv16,
                         cudaFuncAttributeMaxDynamicSharedMemorySize, GEMMO_SMEM);
    cudaFuncSetAttribute(gemm_o16,
                         cudaFuncAttributeMaxDynamicSharedMemorySize, GEMMO_SMEM);
    cudaFuncSetAttribute(attn_mma,
                         cudaFuncAttributeMaxDynamicSharedMemorySize, ATTN_SMEM);

    const int nAll = (MTOT * DD + 2 * DD * DD + 2 * KVD * DD) / 4;
    conv_f16_all<<<(nAll + 255) / 256, 256>>>(X, Wq, Wk, Wv, Wo, Xf, Wqkvf, Wof);

    // QKV projection (single product)
    gemm_qkv16<<<dim3(NQKV / 256, MTOT / 64), 128, GEMMO_SMEM>>>(
        Xf, Wqkvf, bq, bk, bv, Qf, Kf, Vf);

    // attention (all single product)
    attn_mma<<<dim3(TT / 64, BB * HH), 128, ATTN_SMEM>>>(Qf, Kf, Vf, Yf);

    // O projection (single product)
    gemm_o16<<<dim3(DD / 256, MTOT / 64), 128, GEMMO_SMEM>>>(
        Yf, Wof, bo, out, DD, DD);
}